// round 2
// baseline (speedup 1.0000x reference)
#include <cuda_runtime.h>
#include <math.h>

#define E_DIM   2048
#define H_HEADS 16
#define D_HEAD  128
#define N_BATCH 4
#define S_LEN   2048
#define T_LEN   2048
#define M_TOK   (N_BATCH * S_LEN)   // 8192 tokens

// ---------------- scratch (device globals: allocation-free rule) -------------
__device__ float g_q[16777216];     // (N*S, E) projected Q
__device__ float g_k[16777216];     // (N*T, E) projected K
__device__ float g_v[16777216];     // (N*T, E) projected V
__device__ float g_ctx[16777216];   // (N*S, E) attention output (pre out-proj)
__device__ int   g_mask_allones;

// ---------------- SGEMM: C = A @ B^T + bias ---------------------------------
// A: (M,K) row-major, B: (N,K) row-major (nn.Linear weight), C: (M,N)
// 128x128 block tile, BK=8, 256 threads, 8x8 per-thread microtile.
__global__ __launch_bounds__(256) void sgemm_bias_kernel(
    const float* __restrict__ A, const float* __restrict__ B,
    const float* __restrict__ bias, float* __restrict__ C,
    int M, int N, int K)
{
    __shared__ float As[8][128];
    __shared__ float Bs[8][128];

    const int tid  = threadIdx.x;
    const int tx   = tid & 15;       // 16 col-groups
    const int ty   = tid >> 4;       // 16 row-groups
    const int lrow = tid >> 1;       // 0..127 (load row)
    const int lcol = (tid & 1) * 4;  // 0 or 4 (load k-offset, float4)

    const float* Ab = A + (size_t)(blockIdx.y * 128 + lrow) * K + lcol;
    const float* Bb = B + (size_t)(blockIdx.x * 128 + lrow) * K + lcol;

    float acc[8][8];
#pragma unroll
    for (int i = 0; i < 8; i++)
#pragma unroll
        for (int j = 0; j < 8; j++) acc[i][j] = 0.f;

    for (int k0 = 0; k0 < K; k0 += 8) {
        float4 av = *(const float4*)(Ab + k0);
        float4 bv = *(const float4*)(Bb + k0);
        __syncthreads();
        As[lcol + 0][lrow] = av.x; As[lcol + 1][lrow] = av.y;
        As[lcol + 2][lrow] = av.z; As[lcol + 3][lrow] = av.w;
        Bs[lcol + 0][lrow] = bv.x; Bs[lcol + 1][lrow] = bv.y;
        Bs[lcol + 2][lrow] = bv.z; Bs[lcol + 3][lrow] = bv.w;
        __syncthreads();

#pragma unroll
        for (int kk = 0; kk < 8; kk++) {
            float4 a0 = *(const float4*)&As[kk][ty * 8];
            float4 a1 = *(const float4*)&As[kk][ty * 8 + 4];
            float4 b0 = *(const float4*)&Bs[kk][tx * 8];
            float4 b1 = *(const float4*)&Bs[kk][tx * 8 + 4];
            float a[8] = {a0.x, a0.y, a0.z, a0.w, a1.x, a1.y, a1.z, a1.w};
            float b[8] = {b0.x, b0.y, b0.z, b0.w, b1.x, b1.y, b1.z, b1.w};
#pragma unroll
            for (int i = 0; i < 8; i++)
#pragma unroll
                for (int j = 0; j < 8; j++)
                    acc[i][j] += a[i] * b[j];
        }
    }

    const int row0 = blockIdx.y * 128 + ty * 8;
    const int col0 = blockIdx.x * 128 + tx * 8;
#pragma unroll
    for (int i = 0; i < 8; i++) {
#pragma unroll
        for (int j = 0; j < 8; j += 4) {
            float4 o;
            o.x = acc[i][j + 0] + bias[col0 + j + 0];
            o.y = acc[i][j + 1] + bias[col0 + j + 1];
            o.z = acc[i][j + 2] + bias[col0 + j + 2];
            o.w = acc[i][j + 3] + bias[col0 + j + 3];
            *(float4*)&C[(size_t)(row0 + i) * N + col0 + j] = o;
        }
    }
}

// ---------------- mask reduction --------------------------------------------
__global__ void mask_init_kernel() { g_mask_allones = 1; }

__global__ void mask_check_kernel(const int* __restrict__ mask, int n)
{
    int idx    = blockIdx.x * blockDim.x + threadIdx.x;
    int stride = gridDim.x * blockDim.x;
    int bad    = 0;
    for (int i = idx; i < n; i += stride) bad |= (mask[i] == 0);
    if (bad) atomicAnd(&g_mask_allones, 0);
}

// ---------------- flash attention (fp32, online softmax) --------------------
// grid: (S/64, N*H), 256 threads. BM=BN=64, d=128.
// Thread (tx,ty) = (tid&15, tid>>4): S-tile 4x4, O-tile 4 rows x 8 cols.
__global__ __launch_bounds__(256) void flash_attn_kernel(const int* __restrict__ mask)
{
    extern __shared__ float smem[];
    float* sQ = smem;                 // 64 x 132
    float* sK = smem + 64 * 132;      // 64 x 132
    float* sV = smem + 2 * 64 * 132;  // 64 x 132
    float* sP = smem + 3 * 64 * 132;  // 64 x 68

    const int tid = threadIdx.x;
    const int tx  = tid & 15;
    const int ty  = tid >> 4;
    const int q0  = blockIdx.x * 64;
    const int nh  = blockIdx.y;
    const int n   = nh / H_HEADS;
    const int h   = nh % H_HEADS;
    const bool allones = (g_mask_allones != 0);
    const float scale  = rsqrtf((float)D_HEAD);

    // load Q tile, pre-scaled by 1/sqrt(d)
    const float* qptr = g_q + (size_t)(n * S_LEN + q0) * E_DIM + h * D_HEAD;
#pragma unroll
    for (int it = 0; it < 8; it++) {
        int idx = tid + it * 256;
        int r = idx >> 5, c4 = (idx & 31) * 4;
        float4 v = *(const float4*)(qptr + (size_t)r * E_DIM + c4);
        float* dst = &sQ[r * 132 + c4];
        dst[0] = v.x * scale; dst[1] = v.y * scale;
        dst[2] = v.z * scale; dst[3] = v.w * scale;
    }

    float o[4][8];
    float m[4], l[4];
#pragma unroll
    for (int i = 0; i < 4; i++) {
        m[i] = -INFINITY; l[i] = 0.f;
#pragma unroll
        for (int j = 0; j < 8; j++) o[i][j] = 0.f;
    }

    const float* kbase = g_k + (size_t)(n * T_LEN) * E_DIM + h * D_HEAD;
    const float* vbase = g_v + (size_t)(n * T_LEN) * E_DIM + h * D_HEAD;

    for (int t0 = 0; t0 < T_LEN; t0 += 64) {
        __syncthreads();  // prev iter PV done (and Q-store visible on iter 0)
#pragma unroll
        for (int it = 0; it < 8; it++) {
            int idx = tid + it * 256;
            int r = idx >> 5, c4 = (idx & 31) * 4;
            float4 kv = *(const float4*)(kbase + (size_t)(t0 + r) * E_DIM + c4);
            float4 vv = *(const float4*)(vbase + (size_t)(t0 + r) * E_DIM + c4);
            *(float4*)&sK[r * 132 + c4] = kv;
            *(float4*)&sV[r * 132 + c4] = vv;
        }
        __syncthreads();

        // S = Qs @ Ks^T  (4x4 per thread)
        float s[4][4];
#pragma unroll
        for (int i = 0; i < 4; i++)
#pragma unroll
            for (int j = 0; j < 4; j++) s[i][j] = 0.f;

#pragma unroll
        for (int dk = 0; dk < 128; dk += 4) {
            float4 a[4], b[4];
#pragma unroll
            for (int i = 0; i < 4; i++)
                a[i] = *(const float4*)&sQ[(ty * 4 + i) * 132 + dk];
#pragma unroll
            for (int j = 0; j < 4; j++)
                b[j] = *(const float4*)&sK[(tx * 4 + j) * 132 + dk];
#pragma unroll
            for (int i = 0; i < 4; i++)
#pragma unroll
                for (int j = 0; j < 4; j++)
                    s[i][j] += a[i].x * b[j].x + a[i].y * b[j].y +
                               a[i].z * b[j].z + a[i].w * b[j].w;
        }

        // generic mask path (skipped on the bench: mask is all ones)
        if (!allones) {
#pragma unroll
            for (int j = 0; j < 4; j++) {
                int t = t0 + tx * 4 + j;
                const int* mp = mask + (size_t)t * S_LEN + q0;
#pragma unroll
                for (int i = 0; i < 4; i++)
                    if (mp[ty * 4 + i] == 0) s[i][j] = -INFINITY;
            }
        }

        // online softmax update (row = query; reduce over 16 tx threads)
        float pfrag[4][4];
#pragma unroll
        for (int i = 0; i < 4; i++) {
            float mx = fmaxf(fmaxf(s[i][0], s[i][1]), fmaxf(s[i][2], s[i][3]));
#pragma unroll
            for (int off = 8; off >= 1; off >>= 1)
                mx = fmaxf(mx, __shfl_xor_sync(0xffffffffu, mx, off));
            float mn = fmaxf(m[i], mx);
            float sc = (m[i] == mn) ? 1.f : __expf(m[i] - mn);
            m[i] = mn;
            float rs = 0.f;
#pragma unroll
            for (int j = 0; j < 4; j++) {
                float p = __expf(s[i][j] - mn);
                pfrag[i][j] = p;
                rs += p;
            }
#pragma unroll
            for (int off = 8; off >= 1; off >>= 1)
                rs += __shfl_xor_sync(0xffffffffu, rs, off);
            l[i] = l[i] * sc + rs;
#pragma unroll
            for (int j = 0; j < 8; j++) o[i][j] *= sc;
        }

        // stage P through smem for the PV GEMM
#pragma unroll
        for (int i = 0; i < 4; i++)
#pragma unroll
            for (int j = 0; j < 4; j++)
                sP[(ty * 4 + i) * 68 + tx * 4 + j] = pfrag[i][j];
        __syncthreads();

        // O += P @ V
#pragma unroll 4
        for (int t = 0; t < 64; t++) {
            float4 v0 = *(const float4*)&sV[t * 132 + tx * 8];
            float4 v1 = *(const float4*)&sV[t * 132 + tx * 8 + 4];
#pragma unroll
            for (int i = 0; i < 4; i++) {
                float p = sP[(ty * 4 + i) * 68 + t];
                o[i][0] += p * v0.x; o[i][1] += p * v0.y;
                o[i][2] += p * v0.z; o[i][3] += p * v0.w;
                o[i][4] += p * v1.x; o[i][5] += p * v1.y;
                o[i][6] += p * v1.z; o[i][7] += p * v1.w;
            }
        }
    }

    // normalize and store context
    float* cbase = g_ctx + (size_t)(n * S_LEN + q0) * E_DIM + h * D_HEAD;
#pragma unroll
    for (int i = 0; i < 4; i++) {
        float inv = 1.f / l[i];
        float4 w0, w1;
        w0.x = o[i][0] * inv; w0.y = o[i][1] * inv;
        w0.z = o[i][2] * inv; w0.w = o[i][3] * inv;
        w1.x = o[i][4] * inv; w1.y = o[i][5] * inv;
        w1.z = o[i][6] * inv; w1.w = o[i][7] * inv;
        *(float4*)&cbase[(size_t)(ty * 4 + i) * E_DIM + tx * 8]     = w0;
        *(float4*)&cbase[(size_t)(ty * 4 + i) * E_DIM + tx * 8 + 4] = w1;
    }
}

// ---------------- launch -----------------------------------------------------
extern "C" void kernel_launch(void* const* d_in, const int* in_sizes, int n_in,
                              void* d_out, int out_size)
{
    const float* query = (const float*)d_in[0];
    const float* key   = (const float*)d_in[1];
    const float* value = (const float*)d_in[2];
    const int*   mask  = (const int*)  d_in[3];
    const float* Wq    = (const float*)d_in[4];
    const float* bq    = (const float*)d_in[5];
    const float* Wk    = (const float*)d_in[6];
    const float* bk    = (const float*)d_in[7];
    const float* Wv    = (const float*)d_in[8];
    const float* bv    = (const float*)d_in[9];
    const float* Wp    = (const float*)d_in[10];
    const float* bp    = (const float*)d_in[11];
    float* out = (float*)d_out;

    float *qs, *ks, *vs, *cs;
    cudaGetSymbolAddress((void**)&qs, g_q);
    cudaGetSymbolAddress((void**)&ks, g_k);
    cudaGetSymbolAddress((void**)&vs, g_v);
    cudaGetSymbolAddress((void**)&cs, g_ctx);

    dim3 gblock(256);
    dim3 ggrid(E_DIM / 128, M_TOK / 128);  // (16, 64)

    sgemm_bias_kernel<<<ggrid, gblock>>>(query, Wq, bq, qs, M_TOK, E_DIM, E_DIM);
    sgemm_bias_kernel<<<ggrid, gblock>>>(key,   Wk, bk, ks, M_TOK, E_DIM, E_DIM);
    sgemm_bias_kernel<<<ggrid, gblock>>>(value, Wv, bv, vs, M_TOK, E_DIM, E_DIM);

    mask_init_kernel<<<1, 1>>>();
    mask_check_kernel<<<1024, 256>>>(mask, T_LEN * S_LEN);

    size_t smem_bytes = (size_t)(3 * 64 * 132 + 64 * 68) * sizeof(float);  // 118784
    cudaFuncSetAttribute(flash_attn_kernel,
                         cudaFuncAttributeMaxDynamicSharedMemorySize,
                         (int)smem_bytes);
    flash_attn_kernel<<<dim3(S_LEN / 64, N_BATCH * H_HEADS), 256, smem_bytes>>>(mask);

    sgemm_bias_kernel<<<ggrid, gblock>>>(cs, Wp, bp, out, M_TOK, E_DIM, E_DIM);
}

// round 6
// speedup vs baseline: 1.3259x; 1.3259x over previous
#include <cuda_runtime.h>
#include <cuda_bf16.h>
#include <math.h>
#include <cstdint>

#define E_DIM   2048
#define H_HEADS 16
#define D_HEAD  128
#define N_BATCH 4
#define S_LEN   2048
#define T_LEN   2048
#define M_TOK   (N_BATCH * S_LEN)   // 8192
#define K2      4096                // split storage: [hi | lo]

// ---------------- scratch (device globals: allocation-free rule) -------------
__device__ float g_q[16777216];
__device__ float g_k[16777216];
__device__ float g_v[16777216];
__device__ float g_ctx[16777216];
__device__ __nv_bfloat16 g_abig[8192 * 4096];  // activation [hi|lo]
__device__ __nv_bfloat16 g_bbig[2048 * 4096];  // weight [hi|lo]
__device__ int   g_mask_allones;

extern __shared__ char dynsmem[];

// ======================= PTX helpers (family-wide only) ======================
__device__ __forceinline__ uint32_t smem_u32(const void* p) {
    uint32_t a;
    asm("{ .reg .u64 t; cvta.to.shared.u64 t, %1; cvt.u32.u64 %0, t; }"
        : "=r"(a) : "l"(p));
    return a;
}
#define CP_ASYNC16(dst, src) asm volatile("cp.async.cg.shared.global [%0], [%1], 16;" :: "r"(dst), "l"(src))
#define CP_COMMIT()          asm volatile("cp.async.commit_group;" ::: "memory")
#define CP_WAIT2()           asm volatile("cp.async.wait_group 2;" ::: "memory")

__device__ __forceinline__ void ldsm_x4(uint32_t& r0, uint32_t& r1,
                                        uint32_t& r2, uint32_t& r3, uint32_t a) {
    asm volatile("ldmatrix.sync.aligned.m8n8.x4.shared.b16 {%0,%1,%2,%3}, [%4];"
                 : "=r"(r0), "=r"(r1), "=r"(r2), "=r"(r3) : "r"(a));
}
__device__ __forceinline__ void mma16816(float* d, const uint32_t* a, const uint32_t* b) {
    asm volatile(
        "mma.sync.aligned.m16n8k16.row.col.f32.bf16.bf16.f32 "
        "{%0,%1,%2,%3}, {%4,%5,%6,%7}, {%8,%9}, {%0,%1,%2,%3};"
        : "+f"(d[0]), "+f"(d[1]), "+f"(d[2]), "+f"(d[3])
        : "r"(a[0]), "r"(a[1]), "r"(a[2]), "r"(a[3]), "r"(b[0]), "r"(b[1]));
}

// ======================= split fp32 -> (hi|lo) bf16 ==========================
__global__ __launch_bounds__(256) void split_bf16_kernel(
    const float* __restrict__ src, __nv_bfloat16* __restrict__ dst, int n4)
{
    int idx = blockIdx.x * blockDim.x + threadIdx.x;
    if (idx >= n4) return;
    int r  = idx >> 9;
    int c4 = (idx & 511) * 4;
    float4 v = ((const float4*)src)[idx];
    __nv_bfloat16 h0 = __float2bfloat16(v.x), h1 = __float2bfloat16(v.y);
    __nv_bfloat16 h2 = __float2bfloat16(v.z), h3 = __float2bfloat16(v.w);
    __nv_bfloat16 l0 = __float2bfloat16(v.x - __bfloat162float(h0));
    __nv_bfloat16 l1 = __float2bfloat16(v.y - __bfloat162float(h1));
    __nv_bfloat16 l2 = __float2bfloat16(v.z - __bfloat162float(h2));
    __nv_bfloat16 l3 = __float2bfloat16(v.w - __bfloat162float(h3));
    __nv_bfloat162* dh = (__nv_bfloat162*)(dst + (size_t)r * K2 + c4);
    __nv_bfloat162* dl = (__nv_bfloat162*)(dst + (size_t)r * K2 + 2048 + c4);
    dh[0] = __nv_bfloat162(h0, h1); dh[1] = __nv_bfloat162(h2, h3);
    dl[0] = __nv_bfloat162(l0, l1); dl[1] = __nv_bfloat162(l2, l3);
}

// ======================= mma.sync bf16 GEMM ==================================
// C = A@B^T + bias via compensated bf16: AhBh + AhBl + AlBh (3 K-segments).
// A,B stored [hi|lo] (K2=4096). Tile 128x128, 8 warps (32x64 each), BK=32,
// 4-stage cp.async. smem rows padded to 80B -> conflict-free ldmatrix.
#define GSEGS 3
#define GNT   192                    // 3 segs * 64 BK-iters
#define STG_HALF (128 * 80)          // 10240 B per operand per stage
#define STG_B    (2 * STG_HALF)      // 20480
#define GEMM_SMEM (4 * STG_B)        // 81920

__global__ __launch_bounds__(256, 1) void gemm_mma_kernel(
    const __nv_bfloat16* __restrict__ A,
    const __nv_bfloat16* __restrict__ B,
    const float* __restrict__ bias,
    float* __restrict__ C)
{
    const uint32_t sbase = smem_u32(dynsmem);
    const int tid  = threadIdx.x;
    const int lane = tid & 31;
    const int wid  = tid >> 5;
    const int wm   = wid & 3;        // m sub-block (32 rows)
    const int wn   = wid >> 2;       // n sub-block (64 cols)
    const int row0 = blockIdx.y * 128;
    const int col0 = blockIdx.x * 128;

    const char* Ab = (const char*)(A + (size_t)row0 * K2);  // row = 8192 B
    const char* Bb = (const char*)(B + (size_t)col0 * K2);

    float acc[2][8][4];
#pragma unroll
    for (int mt = 0; mt < 2; mt++)
#pragma unroll
        for (int nt = 0; nt < 8; nt++)
#pragma unroll
            for (int e = 0; e < 4; e++) acc[mt][nt][e] = 0.f;

    auto load_stage = [&](int j, int stg) {
        const int seg = j >> 6, ks = j & 63;
        const size_t ka = ((seg == 2) ? 2048 : 0) + ks * 32;  // bf16 elems
        const size_t kb = ((seg == 1) ? 2048 : 0) + ks * 32;
        const uint32_t sA = sbase + stg * STG_B;
        const uint32_t sB = sA + STG_HALF;
#pragma unroll
        for (int it = 0; it < 2; it++) {
            int ch = tid + it * 256;          // 512 chunks of 16B
            int r = ch >> 2, cc = ch & 3;
            CP_ASYNC16(sA + r * 80 + cc * 16, Ab + (size_t)r * 8192 + ka * 2 + cc * 16);
        }
#pragma unroll
        for (int it = 0; it < 2; it++) {
            int ch = tid + it * 256;
            int r = ch >> 2, cc = ch & 3;
            CP_ASYNC16(sB + r * 80 + cc * 16, Bb + (size_t)r * 8192 + kb * 2 + cc * 16);
        }
    };

    load_stage(0, 0); CP_COMMIT();
    load_stage(1, 1); CP_COMMIT();
    load_stage(2, 2); CP_COMMIT();

    // ldmatrix lane addressing (stage-invariant parts)
    const int a_row  = wm * 32 + (lane & 15);        // + mt*16
    const int a_kc   = (lane >> 4) * 16;             // byte offset of k-half
    const int b_rowb = wn * 64 + (lane & 7) + ((lane >> 3) & 2) * 4;  // + p4*16
    const int b_kc   = ((lane >> 3) & 1) * 16;

    for (int i = 0; i < GNT; i++) {
        CP_WAIT2();
        __syncthreads();

        const int j = i + 3;
        if (j < GNT) { load_stage(j, j & 3); CP_COMMIT(); }

        const uint32_t sA = sbase + (i & 3) * STG_B;
        const uint32_t sB = sA + STG_HALF;
#pragma unroll
        for (int s = 0; s < 2; s++) {          // two k16 steps per BK=32
            uint32_t a[2][4], b[4][4];
#pragma unroll
            for (int mt = 0; mt < 2; mt++)
                ldsm_x4(a[mt][0], a[mt][1], a[mt][2], a[mt][3],
                        sA + (a_row + mt * 16) * 80 + s * 32 + a_kc);
#pragma unroll
            for (int p4 = 0; p4 < 4; p4++)
                ldsm_x4(b[p4][0], b[p4][1], b[p4][2], b[p4][3],
                        sB + (b_rowb + p4 * 16) * 80 + s * 32 + b_kc);
#pragma unroll
            for (int mt = 0; mt < 2; mt++)
#pragma unroll
                for (int nt = 0; nt < 8; nt++)
                    mma16816(acc[mt][nt], a[mt], &b[nt >> 1][(nt & 1) * 2]);
        }
    }

    // epilogue: c-frag rows g=(lane>>2), g+8; cols 2*(lane&3)+{0,1}
#pragma unroll
    for (int mt = 0; mt < 2; mt++) {
        const int rg = row0 + wm * 32 + mt * 16 + (lane >> 2);
#pragma unroll
        for (int nt = 0; nt < 8; nt++) {
            const int col = col0 + wn * 64 + nt * 8 + (lane & 3) * 2;
            const float b0 = bias[col], b1 = bias[col + 1];
            float2 v0 = {acc[mt][nt][0] + b0, acc[mt][nt][1] + b1};
            float2 v1 = {acc[mt][nt][2] + b0, acc[mt][nt][3] + b1};
            *(float2*)&C[(size_t)rg * E_DIM + col]       = v0;
            *(float2*)&C[(size_t)(rg + 8) * E_DIM + col] = v1;
        }
    }
}

// ---------------- mask reduction --------------------------------------------
__global__ void mask_init_kernel() { g_mask_allones = 1; }

__global__ void mask_check_kernel(const int* __restrict__ mask, int n)
{
    int idx    = blockIdx.x * blockDim.x + threadIdx.x;
    int stride = gridDim.x * blockDim.x;
    int bad    = 0;
    for (int i = idx; i < n; i += stride) bad |= (mask[i] == 0);
    if (bad) atomicAnd(&g_mask_allones, 0);
}

// ---------------- flash attention (fp32, online softmax) — known good -------
__global__ __launch_bounds__(256) void flash_attn_kernel(const int* __restrict__ mask)
{
    float* smem = (float*)dynsmem;
    float* sQ = smem;
    float* sK = smem + 64 * 132;
    float* sV = smem + 2 * 64 * 132;
    float* sP = smem + 3 * 64 * 132;

    const int tid = threadIdx.x;
    const int tx  = tid & 15;
    const int ty  = tid >> 4;
    const int q0  = blockIdx.x * 64;
    const int nh  = blockIdx.y;
    const int n   = nh / H_HEADS;
    const int h   = nh % H_HEADS;
    const bool allones = (g_mask_allones != 0);
    const float scale  = rsqrtf((float)D_HEAD);

    const float* qptr = g_q + (size_t)(n * S_LEN + q0) * E_DIM + h * D_HEAD;
#pragma unroll
    for (int it = 0; it < 8; it++) {
        int idx = tid + it * 256;
        int r = idx >> 5, c4 = (idx & 31) * 4;
        float4 v = *(const float4*)(qptr + (size_t)r * E_DIM + c4);
        float* dst = &sQ[r * 132 + c4];
        dst[0] = v.x * scale; dst[1] = v.y * scale;
        dst[2] = v.z * scale; dst[3] = v.w * scale;
    }

    float o[4][8];
    float m[4], l[4];
#pragma unroll
    for (int i = 0; i < 4; i++) {
        m[i] = -INFINITY; l[i] = 0.f;
#pragma unroll
        for (int j = 0; j < 8; j++) o[i][j] = 0.f;
    }

    const float* kbase = g_k + (size_t)(n * T_LEN) * E_DIM + h * D_HEAD;
    const float* vbase = g_v + (size_t)(n * T_LEN) * E_DIM + h * D_HEAD;

    for (int t0 = 0; t0 < T_LEN; t0 += 64) {
        __syncthreads();
#pragma unroll
        for (int it = 0; it < 8; it++) {
            int idx = tid + it * 256;
            int r = idx >> 5, c4 = (idx & 31) * 4;
            float4 kv = *(const float4*)(kbase + (size_t)(t0 + r) * E_DIM + c4);
            float4 vv = *(const float4*)(vbase + (size_t)(t0 + r) * E_DIM + c4);
            *(float4*)&sK[r * 132 + c4] = kv;
            *(float4*)&sV[r * 132 + c4] = vv;
        }
        __syncthreads();

        float s[4][4];
#pragma unroll
        for (int i = 0; i < 4; i++)
#pragma unroll
            for (int j = 0; j < 4; j++) s[i][j] = 0.f;

#pragma unroll
        for (int dk = 0; dk < 128; dk += 4) {
            float4 a[4], b[4];
#pragma unroll
            for (int i = 0; i < 4; i++)
                a[i] = *(const float4*)&sQ[(ty * 4 + i) * 132 + dk];
#pragma unroll
            for (int j = 0; j < 4; j++)
                b[j] = *(const float4*)&sK[(tx * 4 + j) * 132 + dk];
#pragma unroll
            for (int i = 0; i < 4; i++)
#pragma unroll
                for (int j = 0; j < 4; j++)
                    s[i][j] += a[i].x * b[j].x + a[i].y * b[j].y +
                               a[i].z * b[j].z + a[i].w * b[j].w;
        }

        if (!allones) {
#pragma unroll
            for (int j = 0; j < 4; j++) {
                int t = t0 + tx * 4 + j;
                const int* mp = mask + (size_t)t * S_LEN + q0;
#pragma unroll
                for (int i = 0; i < 4; i++)
                    if (mp[ty * 4 + i] == 0) s[i][j] = -INFINITY;
            }
        }

        float pfrag[4][4];
#pragma unroll
        for (int i = 0; i < 4; i++) {
            float mx = fmaxf(fmaxf(s[i][0], s[i][1]), fmaxf(s[i][2], s[i][3]));
#pragma unroll
            for (int off = 8; off >= 1; off >>= 1)
                mx = fmaxf(mx, __shfl_xor_sync(0xffffffffu, mx, off));
            float mn = fmaxf(m[i], mx);
            float sc = (m[i] == mn) ? 1.f : __expf(m[i] - mn);
            m[i] = mn;
            float rs = 0.f;
#pragma unroll
            for (int j = 0; j < 4; j++) {
                float p = __expf(s[i][j] - mn);
                pfrag[i][j] = p;
                rs += p;
            }
#pragma unroll
            for (int off = 8; off >= 1; off >>= 1)
                rs += __shfl_xor_sync(0xffffffffu, rs, off);
            l[i] = l[i] * sc + rs;
#pragma unroll
            for (int j = 0; j < 8; j++) o[i][j] *= sc;
        }

#pragma unroll
        for (int i = 0; i < 4; i++)
#pragma unroll
            for (int j = 0; j < 4; j++)
                sP[(ty * 4 + i) * 68 + tx * 4 + j] = pfrag[i][j];
        __syncthreads();

#pragma unroll 4
        for (int t = 0; t < 64; t++) {
            float4 v0 = *(const float4*)&sV[t * 132 + tx * 8];
            float4 v1 = *(const float4*)&sV[t * 132 + tx * 8 + 4];
#pragma unroll
            for (int i = 0; i < 4; i++) {
                float p = sP[(ty * 4 + i) * 68 + t];
                o[i][0] += p * v0.x; o[i][1] += p * v0.y;
                o[i][2] += p * v0.z; o[i][3] += p * v0.w;
                o[i][4] += p * v1.x; o[i][5] += p * v1.y;
                o[i][6] += p * v1.z; o[i][7] += p * v1.w;
            }
        }
    }

    float* cbase = g_ctx + (size_t)(n * S_LEN + q0) * E_DIM + h * D_HEAD;
#pragma unroll
    for (int i = 0; i < 4; i++) {
        float inv = 1.f / l[i];
        float4 w0, w1;
        w0.x = o[i][0] * inv; w0.y = o[i][1] * inv;
        w0.z = o[i][2] * inv; w0.w = o[i][3] * inv;
        w1.x = o[i][4] * inv; w1.y = o[i][5] * inv;
        w1.z = o[i][6] * inv; w1.w = o[i][7] * inv;
        *(float4*)&cbase[(size_t)(ty * 4 + i) * E_DIM + tx * 8]     = w0;
        *(float4*)&cbase[(size_t)(ty * 4 + i) * E_DIM + tx * 8 + 4] = w1;
    }
}

// ---------------- launch -----------------------------------------------------
extern "C" void kernel_launch(void* const* d_in, const int* in_sizes, int n_in,
                              void* d_out, int out_size)
{
    const float* query = (const float*)d_in[0];
    const float* key   = (const float*)d_in[1];
    const float* value = (const float*)d_in[2];
    const int*   mask  = (const int*)  d_in[3];
    const float* Wq    = (const float*)d_in[4];
    const float* bq    = (const float*)d_in[5];
    const float* Wk    = (const float*)d_in[6];
    const float* bk    = (const float*)d_in[7];
    const float* Wv    = (const float*)d_in[8];
    const float* bv    = (const float*)d_in[9];
    const float* Wp    = (const float*)d_in[10];
    const float* bp    = (const float*)d_in[11];
    float* out = (float*)d_out;

    float *qs, *ks, *vs, *cs;
    __nv_bfloat16 *ab, *bb;
    cudaGetSymbolAddress((void**)&qs, g_q);
    cudaGetSymbolAddress((void**)&ks, g_k);
    cudaGetSymbolAddress((void**)&vs, g_v);
    cudaGetSymbolAddress((void**)&cs, g_ctx);
    cudaGetSymbolAddress((void**)&ab, g_abig);
    cudaGetSymbolAddress((void**)&bb, g_bbig);

    cudaFuncSetAttribute(gemm_mma_kernel,
                         cudaFuncAttributeMaxDynamicSharedMemorySize, GEMM_SMEM);

    const int nA4 = M_TOK * 512;
    const int nB4 = E_DIM * 512;
    dim3 ggrid(E_DIM / 128, M_TOK / 128);   // (16, 64)

    split_bf16_kernel<<<nA4 / 256, 256>>>(query, ab, nA4);
    split_bf16_kernel<<<nB4 / 256, 256>>>(Wq, bb, nB4);
    gemm_mma_kernel<<<ggrid, 256, GEMM_SMEM>>>(ab, bb, bq, qs);

    split_bf16_kernel<<<nA4 / 256, 256>>>(key, ab, nA4);
    split_bf16_kernel<<<nB4 / 256, 256>>>(Wk, bb, nB4);
    gemm_mma_kernel<<<ggrid, 256, GEMM_SMEM>>>(ab, bb, bk, ks);

    split_bf16_kernel<<<nA4 / 256, 256>>>(value, ab, nA4);
    split_bf16_kernel<<<nB4 / 256, 256>>>(Wv, bb, nB4);
    gemm_mma_kernel<<<ggrid, 256, GEMM_SMEM>>>(ab, bb, bv, vs);

    mask_init_kernel<<<1, 1>>>();
    mask_check_kernel<<<1024, 256>>>(mask, T_LEN * S_LEN);
    size_t smem_bytes = (size_t)(3 * 64 * 132 + 64 * 68) * sizeof(float);
    cudaFuncSetAttribute(flash_attn_kernel,
                         cudaFuncAttributeMaxDynamicSharedMemorySize,
                         (int)smem_bytes);
    flash_attn_kernel<<<dim3(S_LEN / 64, N_BATCH * H_HEADS), 256, smem_bytes>>>(mask);

    split_bf16_kernel<<<nA4 / 256, 256>>>(cs, ab, nA4);
    split_bf16_kernel<<<nB4 / 256, 256>>>(Wp, bb, nB4);
    gemm_mma_kernel<<<ggrid, 256, GEMM_SMEM>>>(ab, bb, bp, out);
}

// round 7
// speedup vs baseline: 5.2977x; 3.9955x over previous
#include <cuda_runtime.h>
#include <math.h>
#include <cstdint>

#define E_DIM   2048
#define H_HEADS 16
#define D_HEAD  128
#define N_BATCH 4
#define S_LEN   2048
#define T_LEN   2048
#define M_TOK   (N_BATCH * S_LEN)   // 8192

// ---------------- scratch (device globals) -----------------------------------
__device__ float g_q[16777216];     // projected Q (tf32-rounded)
__device__ float g_k[16777216];
__device__ float g_v[16777216];
__device__ float g_ctx[16777216];   // attention out (tf32-rounded)
__device__ float g_ra[16777216];    // rounded activation (64MB)
__device__ float g_rw[4194304];     // rounded weight (16MB)
__device__ int   g_mask_allones;

extern __shared__ char dynsmem[];

// ======================= helpers =============================================
__device__ __forceinline__ uint32_t smem_u32(const void* p) {
    uint32_t a;
    asm("{ .reg .u64 t; cvta.to.shared.u64 t, %1; cvt.u32.u64 %0, t; }"
        : "=r"(a) : "l"(p));
    return a;
}
__device__ __forceinline__ float tf32r(float x) {
    uint32_t u;
    asm("cvt.rna.tf32.f32 %0, %1;" : "=r"(u) : "f"(x));
    return __uint_as_float(u);
}
#define CP_ASYNC16(dst, src) asm volatile("cp.async.cg.shared.global [%0], [%1], 16;" :: "r"(dst), "l"(src))
#define CP_COMMIT()          asm volatile("cp.async.commit_group;" ::: "memory")
#define CP_WAIT0()           asm volatile("cp.async.wait_group 0;" ::: "memory")
#define CP_WAIT1()           asm volatile("cp.async.wait_group 1;" ::: "memory")

__device__ __forceinline__ void ldsm_x4(uint32_t& r0, uint32_t& r1,
                                        uint32_t& r2, uint32_t& r3, uint32_t a) {
    asm volatile("ldmatrix.sync.aligned.m8n8.x4.shared.b16 {%0,%1,%2,%3}, [%4];"
                 : "=r"(r0), "=r"(r1), "=r"(r2), "=r"(r3) : "r"(a));
}
__device__ __forceinline__ void mma_tf32(float* d, const uint32_t* a, const uint32_t* b) {
    asm volatile(
        "mma.sync.aligned.m16n8k8.row.col.f32.tf32.tf32.f32 "
        "{%0,%1,%2,%3}, {%4,%5,%6,%7}, {%8,%9}, {%0,%1,%2,%3};"
        : "+f"(d[0]), "+f"(d[1]), "+f"(d[2]), "+f"(d[3])
        : "r"(a[0]), "r"(a[1]), "r"(a[2]), "r"(a[3]), "r"(b[0]), "r"(b[1]));
}
// swizzle: 16B-granule group g XOR low bits of row (keeps g's high bits)
#define SW4(g, row) (((g) & 24) | (((g) & 7) ^ ((row) & 7)))

// ======================= round fp32 -> tf32(RN) ==============================
__global__ __launch_bounds__(256) void round_tf32_kernel(
    const float* __restrict__ src, float* __restrict__ dst, int n4)
{
    int idx = blockIdx.x * blockDim.x + threadIdx.x;
    if (idx >= n4) return;
    float4 v = ((const float4*)src)[idx];
    v.x = tf32r(v.x); v.y = tf32r(v.y); v.z = tf32r(v.z); v.w = tf32r(v.w);
    ((float4*)dst)[idx] = v;
}

// ======================= tf32 GEMM: C = A@B^T + bias =========================
// Tile 128x128, 8 warps (4m x 2n, warp 32x64), BK=32, 3-stage cp.async.
#define GNT 64                       // 2048 / 32
#define GOP_B (128 * 32 * 4)         // 16384 B per operand per stage
#define GSTG_B (2 * GOP_B)           // 32768
#define GEMM_SMEM (3 * GSTG_B)       // 98304 -> 2 CTA/SM

__global__ __launch_bounds__(256, 2) void gemm_tf32_kernel(
    const float* __restrict__ A, const float* __restrict__ B,
    const float* __restrict__ bias, float* __restrict__ C, int do_round)
{
    const uint32_t sb = smem_u32(dynsmem);
    const int tid  = threadIdx.x;
    const int lane = tid & 31;
    const int wid  = tid >> 5;
    const int wm   = wid & 3;
    const int wn   = wid >> 2;
    const int row0 = blockIdx.y * 128;
    const int col0 = blockIdx.x * 128;

    const char* Ab = (const char*)(A + (size_t)row0 * E_DIM);  // row = 8192 B
    const char* Bb = (const char*)(B + (size_t)col0 * E_DIM);

    float acc[2][8][4];
#pragma unroll
    for (int mf = 0; mf < 2; mf++)
#pragma unroll
        for (int nf = 0; nf < 8; nf++)
#pragma unroll
            for (int e = 0; e < 4; e++) acc[mf][nf][e] = 0.f;

    auto load_stage = [&](int kt, int stg) {
        const uint32_t sA = sb + stg * GSTG_B;
        const uint32_t sB = sA + GOP_B;
        const size_t koff = (size_t)kt * 128;   // bytes in row
#pragma unroll
        for (int it = 0; it < 4; it++) {
            int ch = tid + it * 256;            // 1024 chunks
            int r = ch >> 3, g = ch & 7;
            CP_ASYNC16(sA + r * 128 + SW4(g, r) * 16,
                       Ab + (size_t)r * 8192 + koff + g * 16);
        }
#pragma unroll
        for (int it = 0; it < 4; it++) {
            int ch = tid + it * 256;
            int r = ch >> 3, g = ch & 7;
            CP_ASYNC16(sB + r * 128 + SW4(g, r) * 16,
                       Bb + (size_t)r * 8192 + koff + g * 16);
        }
    };

    load_stage(0, 0); CP_COMMIT();
    load_stage(1, 1); CP_COMMIT();

    // ldmatrix lane geometry
    const int a_ro = (lane & 7) + ((lane >> 3) & 1) * 8;   // A/B matrix row offset
    const int a_kh = (lane >> 4) & 1;                      // A k4 half
    const int b_ro = (lane & 7) + ((lane >> 4) & 1) * 8;
    const int b_kh = (lane >> 3) & 1;

    for (int i = 0; i < GNT; i++) {
        CP_WAIT1();
        __syncthreads();
        const int j = i + 2;
        if (j < GNT) load_stage(j, j % 3);
        CP_COMMIT();

        const uint32_t sA = sb + (i % 3) * GSTG_B;
        const uint32_t sB = sA + GOP_B;
#pragma unroll
        for (int s = 0; s < 4; s++) {           // 4 k8-steps per BK=32
            uint32_t a[2][4], b[8][2];
#pragma unroll
            for (int mf = 0; mf < 2; mf++) {
                int r = wm * 32 + mf * 16 + a_ro;
                ldsm_x4(a[mf][0], a[mf][1], a[mf][2], a[mf][3],
                        sA + r * 128 + SW4(2 * s + a_kh, r) * 16);
            }
#pragma unroll
            for (int pj = 0; pj < 4; pj++) {
                int r = wn * 64 + pj * 16 + b_ro;
                uint32_t r0, r1, r2, r3;
                ldsm_x4(r0, r1, r2, r3,
                        sB + r * 128 + SW4(2 * s + b_kh, r) * 16);
                b[2 * pj][0] = r0;     b[2 * pj][1] = r1;
                b[2 * pj + 1][0] = r2; b[2 * pj + 1][1] = r3;
            }
#pragma unroll
            for (int mf = 0; mf < 2; mf++)
#pragma unroll
                for (int nf = 0; nf < 8; nf++)
                    mma_tf32(acc[mf][nf], a[mf], b[nf]);
        }
    }

    // epilogue
#pragma unroll
    for (int mf = 0; mf < 2; mf++) {
        const int rg = row0 + wm * 32 + mf * 16 + (lane >> 2);
#pragma unroll
        for (int nf = 0; nf < 8; nf++) {
            const int col = col0 + wn * 64 + nf * 8 + (lane & 3) * 2;
            const float b0 = bias[col], b1 = bias[col + 1];
            float2 v0 = {acc[mf][nf][0] + b0, acc[mf][nf][1] + b1};
            float2 v1 = {acc[mf][nf][2] + b0, acc[mf][nf][3] + b1};
            if (do_round) {
                v0.x = tf32r(v0.x); v0.y = tf32r(v0.y);
                v1.x = tf32r(v1.x); v1.y = tf32r(v1.y);
            }
            *(float2*)&C[(size_t)rg * E_DIM + col]       = v0;
            *(float2*)&C[(size_t)(rg + 8) * E_DIM + col] = v1;
        }
    }
}

// ---------------- mask reduction --------------------------------------------
__global__ void mask_init_kernel() { g_mask_allones = 1; }
__global__ void mask_check_kernel(const int* __restrict__ mask, int n)
{
    int idx = blockIdx.x * blockDim.x + threadIdx.x;
    int stride = gridDim.x * blockDim.x;
    int bad = 0;
    for (int i = idx; i < n; i += stride) bad |= (mask[i] == 0);
    if (bad) atomicAnd(&g_mask_allones, 0);
}

// ======================= tf32 flash attention ================================
// BM=64 q, BN=64 keys, d=128. 8 warps: 2m x 4n.
// smem (floats): Q 8192 | K0 8192 | K1 8192 | V0 8192 | V1 8192 | P 4096 | red 512
#define AT_OQ  0
#define AT_OK  8192
#define AT_OV  24576
#define AT_OP  40960
#define AT_ORM 45056
#define AT_ORS 45312
#define ATT_SMEM (45568 * 4)         // 182272 B

__global__ __launch_bounds__(256, 1) void attn_tf32_kernel(const int* __restrict__ mask)
{
    const uint32_t sb = smem_u32(dynsmem);
    const int tid  = threadIdx.x;
    const int lane = tid & 31;
    const int wid  = tid >> 5;
    const int wm   = wid & 1;        // q 32-row half
    const int wn   = wid >> 1;       // 0..3
    const int q0   = blockIdx.x * 64;
    const int nh   = blockIdx.y;
    const int bn   = nh / H_HEADS;
    const int h    = nh % H_HEADS;
    const bool allones = (g_mask_allones != 0);
    const float sc = rsqrtf((float)D_HEAD);

    const char* qg = (const char*)(g_q + (size_t)(bn * S_LEN + q0) * E_DIM + h * D_HEAD);
    const char* kg = (const char*)(g_k + (size_t)(bn * T_LEN) * E_DIM + h * D_HEAD);
    const char* vg = (const char*)(g_v + (size_t)(bn * T_LEN) * E_DIM + h * D_HEAD);

    // ldmatrix lane geometry (shared with GEMM conventions)
    const int a_ro = (lane & 7) + ((lane >> 3) & 1) * 8;
    const int a_kh = (lane >> 4) & 1;
    const int b_ro = (lane & 7) + ((lane >> 4) & 1) * 8;
    const int b_kh = (lane >> 3) & 1;

    auto load_qkv = [&](const char* src, uint32_t base) {  // 64x128 fp32, swizzled
#pragma unroll
        for (int it = 0; it < 8; it++) {
            int ch = tid + it * 256;            // 2048 chunks
            int r = ch >> 5, g = ch & 31;
            CP_ASYNC16(base + r * 512 + SW4(g, r) * 16,
                       src + (size_t)r * 8192 + g * 16);
        }
    };

    // prologue: Q + K/V block 0
    load_qkv(qg, sb + AT_OQ * 4);
    load_qkv(kg, sb + AT_OK * 4);
    load_qkv(vg, sb + AT_OV * 4);
    CP_COMMIT();

    float o[2][4][4];
    float m[2][2], lsum[2][2];
#pragma unroll
    for (int mf = 0; mf < 2; mf++) {
#pragma unroll
        for (int r = 0; r < 2; r++) { m[mf][r] = -INFINITY; lsum[mf][r] = 0.f; }
#pragma unroll
        for (int nf = 0; nf < 4; nf++)
#pragma unroll
            for (int e = 0; e < 4; e++) o[mf][nf][e] = 0.f;
    }

    const int nb = T_LEN / 64;
    for (int j = 0; j < nb; j++) {
        const int b = j & 1;
        CP_WAIT0();
        __syncthreads();   // KV(j) visible to all; prev compute done
        if (j + 1 < nb) {
            load_qkv(kg + (size_t)(j + 1) * 64 * 8192, sb + (AT_OK + (1 - b) * 8192) * 4);
            load_qkv(vg + (size_t)(j + 1) * 64 * 8192, sb + (AT_OV + (1 - b) * 8192) * 4);
            CP_COMMIT();
        }
        const uint32_t sQ = sb + AT_OQ * 4;
        const uint32_t sK = sb + (AT_OK + b * 8192) * 4;
        const uint32_t sV = sb + (AT_OV + b * 8192) * 4;
        const uint32_t sP = sb + AT_OP * 4;

        // ---- S = Q K^T (warp: 32q x 16keys), d=128 -> 16 k8-steps
        float s[2][2][4];
#pragma unroll
        for (int mf = 0; mf < 2; mf++)
#pragma unroll
            for (int nf = 0; nf < 2; nf++)
#pragma unroll
                for (int e = 0; e < 4; e++) s[mf][nf][e] = 0.f;

#pragma unroll
        for (int ks = 0; ks < 16; ks++) {
            uint32_t a[2][4], bfr[2][2];
#pragma unroll
            for (int mf = 0; mf < 2; mf++) {
                int r = wm * 32 + mf * 16 + a_ro;
                ldsm_x4(a[mf][0], a[mf][1], a[mf][2], a[mf][3],
                        sQ + r * 512 + SW4(2 * ks + a_kh, r) * 16);
            }
            {
                int r = wn * 16 + b_ro;
                uint32_t r0, r1, r2, r3;
                ldsm_x4(r0, r1, r2, r3,
                        sK + r * 512 + SW4(2 * ks + b_kh, r) * 16);
                bfr[0][0] = r0; bfr[0][1] = r1; bfr[1][0] = r2; bfr[1][1] = r3;
            }
#pragma unroll
            for (int mf = 0; mf < 2; mf++)
#pragma unroll
                for (int nf = 0; nf < 2; nf++)
                    mma_tf32(s[mf][nf], a[mf], bfr[nf]);
        }

        // scale
#pragma unroll
        for (int mf = 0; mf < 2; mf++)
#pragma unroll
            for (int nf = 0; nf < 2; nf++)
#pragma unroll
                for (int e = 0; e < 4; e++) s[mf][nf][e] *= sc;

        // generic mask path (bench: all ones -> skipped)
        if (!allones) {
#pragma unroll
            for (int mf = 0; mf < 2; mf++)
#pragma unroll
                for (int nf = 0; nf < 2; nf++)
#pragma unroll
                    for (int e = 0; e < 4; e++) {
                        int r = wm * 32 + mf * 16 + (lane >> 2) + (e >> 1) * 8;
                        int c = wn * 16 + nf * 8 + (lane & 3) * 2 + (e & 1);
                        if (mask[(size_t)(j * 64 + c) * S_LEN + q0 + r] == 0)
                            s[mf][nf][e] = -INFINITY;
                    }
        }

        // ---- online softmax
        float* redM = (float*)(sb + AT_ORM * 4 - sb + (size_t)0, (float*)dynsmem + AT_ORM);
        float* redS = (float*)dynsmem + AT_ORS;
        // partial row max (rows: R0 = base+lane>>2, R1 = +8)
#pragma unroll
        for (int mf = 0; mf < 2; mf++) {
            float mx0 = fmaxf(fmaxf(s[mf][0][0], s[mf][0][1]),
                              fmaxf(s[mf][1][0], s[mf][1][1]));
            float mx1 = fmaxf(fmaxf(s[mf][0][2], s[mf][0][3]),
                              fmaxf(s[mf][1][2], s[mf][1][3]));
            mx0 = fmaxf(mx0, __shfl_xor_sync(0xffffffffu, mx0, 1));
            mx0 = fmaxf(mx0, __shfl_xor_sync(0xffffffffu, mx0, 2));
            mx1 = fmaxf(mx1, __shfl_xor_sync(0xffffffffu, mx1, 1));
            mx1 = fmaxf(mx1, __shfl_xor_sync(0xffffffffu, mx1, 2));
            if ((lane & 3) == 0) {
                redM[wn * 64 + wm * 32 + mf * 16 + (lane >> 2)]     = mx0;
                redM[wn * 64 + wm * 32 + mf * 16 + (lane >> 2) + 8] = mx1;
            }
        }
        __syncthreads();

        float alpha[2][2], psum[2][2];
#pragma unroll
        for (int mf = 0; mf < 2; mf++)
#pragma unroll
            for (int r = 0; r < 2; r++) {
                int row = wm * 32 + mf * 16 + (lane >> 2) + r * 8;
                float bm = fmaxf(fmaxf(redM[row], redM[64 + row]),
                                 fmaxf(redM[128 + row], redM[192 + row]));
                float mn = fmaxf(m[mf][r], bm);
                alpha[mf][r] = (m[mf][r] == mn) ? 1.f : __expf(m[mf][r] - mn);
                m[mf][r] = mn;
            }
        // p = exp(s - m); partial row sums; store P (tf32-rounded)
#pragma unroll
        for (int mf = 0; mf < 2; mf++) {
            float s00 = __expf(s[mf][0][0] - m[mf][0]);
            float s01 = __expf(s[mf][0][1] - m[mf][0]);
            float s10 = __expf(s[mf][1][0] - m[mf][0]);
            float s11 = __expf(s[mf][1][1] - m[mf][0]);
            float t00 = __expf(s[mf][0][2] - m[mf][1]);
            float t01 = __expf(s[mf][0][3] - m[mf][1]);
            float t10 = __expf(s[mf][1][2] - m[mf][1]);
            float t11 = __expf(s[mf][1][3] - m[mf][1]);
            float ps0 = s00 + s01 + s10 + s11;
            float ps1 = t00 + t01 + t10 + t11;
            ps0 += __shfl_xor_sync(0xffffffffu, ps0, 1);
            ps0 += __shfl_xor_sync(0xffffffffu, ps0, 2);
            ps1 += __shfl_xor_sync(0xffffffffu, ps1, 1);
            ps1 += __shfl_xor_sync(0xffffffffu, ps1, 2);
            psum[mf][0] = ps0; psum[mf][1] = ps1;
            if ((lane & 3) == 0) {
                redS[wn * 64 + wm * 32 + mf * 16 + (lane >> 2)]     = ps0;
                redS[wn * 64 + wm * 32 + mf * 16 + (lane >> 2) + 8] = ps1;
            }
            // store P: rows R0/R1, cols wn*16 + nf*8 + 2(lane&3)
            int R0 = wm * 32 + mf * 16 + (lane >> 2);
            int R1 = R0 + 8;
#pragma unroll
            for (int nf = 0; nf < 2; nf++) {
                int c  = wn * 16 + nf * 8 + (lane & 3) * 2;
                int g  = c >> 2;
                float2 v0 = {tf32r(nf ? s10 : s00), tf32r(nf ? s11 : s01)};
                float2 v1 = {tf32r(nf ? t10 : t00), tf32r(nf ? t11 : t01)};
                *(float2*)(dynsmem + (size_t)sP - sb + R0 * 256 + SW4(g, R0) * 16 + (c & 3) * 4) = v0;
                *(float2*)(dynsmem + (size_t)sP - sb + R1 * 256 + SW4(g, R1) * 16 + (c & 3) * 4) = v1;
            }
            // rescale o rows
#pragma unroll
            for (int nf = 0; nf < 4; nf++) {
                o[mf][nf][0] *= alpha[mf][0]; o[mf][nf][1] *= alpha[mf][0];
                o[mf][nf][2] *= alpha[mf][1]; o[mf][nf][3] *= alpha[mf][1];
            }
        }
        __syncthreads();

#pragma unroll
        for (int mf = 0; mf < 2; mf++)
#pragma unroll
            for (int r = 0; r < 2; r++) {
                int row = wm * 32 + mf * 16 + (lane >> 2) + r * 8;
                float tot = redS[row] + redS[64 + row] + redS[128 + row] + redS[192 + row];
                lsum[mf][r] = lsum[mf][r] * alpha[mf][r] + tot;
            }

        // ---- O += P V  (warp: 32q x 32d), k=64 keys -> 8 k8-steps
#pragma unroll
        for (int ks = 0; ks < 8; ks++) {
            uint32_t ap[2][4];
#pragma unroll
            for (int mf = 0; mf < 2; mf++) {
                int r = wm * 32 + mf * 16 + a_ro;
                ldsm_x4(ap[mf][0], ap[mf][1], ap[mf][2], ap[mf][3],
                        sP + r * 256 + SW4(2 * ks + a_kh, r) * 16);
            }
#pragma unroll
            for (int nf = 0; nf < 4; nf++) {
                int d = wn * 32 + nf * 8 + (lane >> 2);
                int t0l = ks * 8 + (lane & 3);
                uint32_t bv[2];
                bv[0] = *(const uint32_t*)(dynsmem + (size_t)sV - sb + t0l * 512 + SW4(d >> 2, t0l) * 16 + (d & 3) * 4);
                int t1l = t0l + 4;
                bv[1] = *(const uint32_t*)(dynsmem + (size_t)sV - sb + t1l * 512 + SW4(d >> 2, t1l) * 16 + (d & 3) * 4);
#pragma unroll
                for (int mf = 0; mf < 2; mf++)
                    mma_tf32(o[mf][nf], ap[mf], bv);
            }
        }
        __syncthreads();   // protect buf b before next iter's cp.async
    }

    // epilogue
    float* cb = g_ctx + (size_t)(bn * S_LEN + q0) * E_DIM + h * D_HEAD;
#pragma unroll
    for (int mf = 0; mf < 2; mf++) {
        int R0 = wm * 32 + mf * 16 + (lane >> 2);
        float i0 = 1.f / lsum[mf][0], i1 = 1.f / lsum[mf][1];
#pragma unroll
        for (int nf = 0; nf < 4; nf++) {
            int c = wn * 32 + nf * 8 + (lane & 3) * 2;
            float2 v0 = {tf32r(o[mf][nf][0] * i0), tf32r(o[mf][nf][1] * i0)};
            float2 v1 = {tf32r(o[mf][nf][2] * i1), tf32r(o[mf][nf][3] * i1)};
            *(float2*)&cb[(size_t)R0 * E_DIM + c]       = v0;
            *(float2*)&cb[(size_t)(R0 + 8) * E_DIM + c] = v1;
        }
    }
}

// ---------------- launch -----------------------------------------------------
extern "C" void kernel_launch(void* const* d_in, const int* in_sizes, int n_in,
                              void* d_out, int out_size)
{
    const float* query = (const float*)d_in[0];
    const float* key   = (const float*)d_in[1];
    const float* value = (const float*)d_in[2];
    const int*   mask  = (const int*)  d_in[3];
    const float* Wq    = (const float*)d_in[4];
    const float* bq    = (const float*)d_in[5];
    const float* Wk    = (const float*)d_in[6];
    const float* bk    = (const float*)d_in[7];
    const float* Wv    = (const float*)d_in[8];
    const float* bv    = (const float*)d_in[9];
    const float* Wp    = (const float*)d_in[10];
    const float* bp    = (const float*)d_in[11];
    float* out = (float*)d_out;

    float *qs, *ks, *vs, *cs, *ra, *rw;
    cudaGetSymbolAddress((void**)&qs, g_q);
    cudaGetSymbolAddress((void**)&ks, g_k);
    cudaGetSymbolAddress((void**)&vs, g_v);
    cudaGetSymbolAddress((void**)&cs, g_ctx);
    cudaGetSymbolAddress((void**)&ra, g_ra);
    cudaGetSymbolAddress((void**)&rw, g_rw);

    cudaFuncSetAttribute(gemm_tf32_kernel,
                         cudaFuncAttributeMaxDynamicSharedMemorySize, GEMM_SMEM);
    cudaFuncSetAttribute(attn_tf32_kernel,
                         cudaFuncAttributeMaxDynamicSharedMemorySize, ATT_SMEM);

    const int nA4 = M_TOK * 512;   // float4s, activation
    const int nW4 = E_DIM * 512;   // float4s, weight
    dim3 ggrid(E_DIM / 128, M_TOK / 128);

    round_tf32_kernel<<<nA4 / 256, 256>>>(query, ra, nA4);
    round_tf32_kernel<<<nW4 / 256, 256>>>(Wq, rw, nW4);
    gemm_tf32_kernel<<<ggrid, 256, GEMM_SMEM>>>(ra, rw, bq, qs, 1);

    round_tf32_kernel<<<nA4 / 256, 256>>>(key, ra, nA4);
    round_tf32_kernel<<<nW4 / 256, 256>>>(Wk, rw, nW4);
    gemm_tf32_kernel<<<ggrid, 256, GEMM_SMEM>>>(ra, rw, bk, ks, 1);

    round_tf32_kernel<<<nA4 / 256, 256>>>(value, ra, nA4);
    round_tf32_kernel<<<nW4 / 256, 256>>>(Wv, rw, nW4);
    gemm_tf32_kernel<<<ggrid, 256, GEMM_SMEM>>>(ra, rw, bv, vs, 1);

    mask_init_kernel<<<1, 1>>>();
    mask_check_kernel<<<1024, 256>>>(mask, T_LEN * S_LEN);

    attn_tf32_kernel<<<dim3(S_LEN / 64, N_BATCH * H_HEADS), 256, ATT_SMEM>>>(mask);

    round_tf32_kernel<<<nW4 / 256, 256>>>(Wp, rw, nW4);
    gemm_tf32_kernel<<<ggrid, 256, GEMM_SMEM>>>(cs, rw, bp, out, 0);
}

// round 8
// speedup vs baseline: 5.3854x; 1.0166x over previous
#include <cuda_runtime.h>
#include <math.h>
#include <cstdint>

#define E_DIM   2048
#define H_HEADS 16
#define D_HEAD  128
#define N_BATCH 4
#define S_LEN   2048
#define T_LEN   2048
#define M_TOK   (N_BATCH * S_LEN)

// ---------------- scratch ----------------------------------------------------
__device__ float g_q[16777216];
__device__ float g_k[16777216];
__device__ float g_v[16777216];
__device__ float g_ctx[16777216];
__device__ float g_ra[16777216];
__device__ float g_rw[4194304];
__device__ int   g_mask_allones;

extern __shared__ char dynsmem[];

// ======================= helpers =============================================
__device__ __forceinline__ uint32_t smem_u32(const void* p) {
    uint32_t a;
    asm("{ .reg .u64 t; cvta.to.shared.u64 t, %1; cvt.u32.u64 %0, t; }"
        : "=r"(a) : "l"(p));
    return a;
}
__device__ __forceinline__ float tf32r(float x) {
    uint32_t u;
    asm("cvt.rna.tf32.f32 %0, %1;" : "=r"(u) : "f"(x));
    return __uint_as_float(u);
}
#define CP_ASYNC16(dst, src) asm volatile("cp.async.cg.shared.global [%0], [%1], 16;" :: "r"(dst), "l"(src))
#define CP_COMMIT()          asm volatile("cp.async.commit_group;" ::: "memory")
#define CP_WAIT0()           asm volatile("cp.async.wait_group 0;" ::: "memory")
#define CP_WAIT1()           asm volatile("cp.async.wait_group 1;" ::: "memory")

__device__ __forceinline__ void ldsm_x4(uint32_t& r0, uint32_t& r1,
                                        uint32_t& r2, uint32_t& r3, uint32_t a) {
    asm volatile("ldmatrix.sync.aligned.m8n8.x4.shared.b16 {%0,%1,%2,%3}, [%4];"
                 : "=r"(r0), "=r"(r1), "=r"(r2), "=r"(r3) : "r"(a));
}
__device__ __forceinline__ void mma_tf32(float* d, const uint32_t* a, const uint32_t* b) {
    asm volatile(
        "mma.sync.aligned.m16n8k8.row.col.f32.tf32.tf32.f32 "
        "{%0,%1,%2,%3}, {%4,%5,%6,%7}, {%8,%9}, {%0,%1,%2,%3};"
        : "+f"(d[0]), "+f"(d[1]), "+f"(d[2]), "+f"(d[3])
        : "r"(a[0]), "r"(a[1]), "r"(a[2]), "r"(a[3]), "r"(b[0]), "r"(b[1]));
}
#define SW4(g, row) (((g) & 24) | (((g) & 7) ^ ((row) & 7)))

// ======================= round fp32 -> tf32(RN) ==============================
__global__ __launch_bounds__(256) void round_tf32_kernel(
    const float* __restrict__ src, float* __restrict__ dst, int n4)
{
    int idx = blockIdx.x * blockDim.x + threadIdx.x;
    if (idx >= n4) return;
    float4 v = ((const float4*)src)[idx];
    v.x = tf32r(v.x); v.y = tf32r(v.y); v.z = tf32r(v.z); v.w = tf32r(v.w);
    ((float4*)dst)[idx] = v;
}

// ======================= tf32 GEMM: C = A@B^T + bias =========================
// Tile 128x256, 8 warps (2m x 4n, warp 64x64), BK=32, 3-stage cp.async.
#define GNT 64
#define GA_B (128 * 32 * 4)          // 16384
#define GB_B (256 * 32 * 4)          // 32768
#define GSTG_B (GA_B + GB_B)         // 49152
#define GEMM_SMEM (3 * GSTG_B)       // 147456

__global__ __launch_bounds__(256, 1) void gemm_tf32_kernel(
    const float* __restrict__ A, const float* __restrict__ B,
    const float* __restrict__ bias, float* __restrict__ C, int do_round)
{
    const uint32_t sb = smem_u32(dynsmem);
    const int tid  = threadIdx.x;
    const int lane = tid & 31;
    const int wid  = tid >> 5;
    const int wm   = wid & 1;        // 64-row half
    const int wn   = wid >> 1;       // 64-col quarter
    const int row0 = blockIdx.y * 128;
    const int col0 = blockIdx.x * 256;

    const char* Ab = (const char*)(A + (size_t)row0 * E_DIM);
    const char* Bb = (const char*)(B + (size_t)col0 * E_DIM);

    float acc[4][8][4];
#pragma unroll
    for (int mf = 0; mf < 4; mf++)
#pragma unroll
        for (int nf = 0; nf < 8; nf++)
#pragma unroll
            for (int e = 0; e < 4; e++) acc[mf][nf][e] = 0.f;

    auto load_stage = [&](int kt, int stg) {
        const uint32_t sA = sb + stg * GSTG_B;
        const uint32_t sB = sA + GA_B;
        const size_t koff = (size_t)kt * 128;
#pragma unroll
        for (int it = 0; it < 4; it++) {          // A: 1024 chunks
            int ch = tid + it * 256;
            int r = ch >> 3, g = ch & 7;
            CP_ASYNC16(sA + r * 128 + SW4(g, r) * 16,
                       Ab + (size_t)r * 8192 + koff + g * 16);
        }
#pragma unroll
        for (int it = 0; it < 8; it++) {          // B: 2048 chunks
            int ch = tid + it * 256;
            int r = ch >> 3, g = ch & 7;
            CP_ASYNC16(sB + r * 128 + SW4(g, r) * 16,
                       Bb + (size_t)r * 8192 + koff + g * 16);
        }
    };

    load_stage(0, 0); CP_COMMIT();
    load_stage(1, 1); CP_COMMIT();

    const int a_ro = (lane & 7) + ((lane >> 3) & 1) * 8;
    const int a_kh = (lane >> 4) & 1;
    const int b_ro = (lane & 7) + ((lane >> 4) & 1) * 8;
    const int b_kh = (lane >> 3) & 1;

    for (int i = 0; i < GNT; i++) {
        CP_WAIT1();
        __syncthreads();
        const int j = i + 2;
        if (j < GNT) load_stage(j, j % 3);
        CP_COMMIT();

        const uint32_t sA = sb + (i % 3) * GSTG_B;
        const uint32_t sB = sA + GA_B;
#pragma unroll
        for (int s = 0; s < 4; s++) {
            uint32_t a[4][4], b[8][2];
#pragma unroll
            for (int mf = 0; mf < 4; mf++) {
                int r = wm * 64 + mf * 16 + a_ro;
                ldsm_x4(a[mf][0], a[mf][1], a[mf][2], a[mf][3],
                        sA + r * 128 + SW4(2 * s + a_kh, r) * 16);
            }
#pragma unroll
            for (int pj = 0; pj < 4; pj++) {
                int r = wn * 64 + pj * 16 + b_ro;
                uint32_t r0, r1, r2, r3;
                ldsm_x4(r0, r1, r2, r3, sB + r * 128 + SW4(2 * s + b_kh, r) * 16);
                b[2 * pj][0] = r0;     b[2 * pj][1] = r1;
                b[2 * pj + 1][0] = r2; b[2 * pj + 1][1] = r3;
            }
#pragma unroll
            for (int mf = 0; mf < 4; mf++)
#pragma unroll
                for (int nf = 0; nf < 8; nf++)
                    mma_tf32(acc[mf][nf], a[mf], b[nf]);
        }
    }

#pragma unroll
    for (int mf = 0; mf < 4; mf++) {
        const int rg = row0 + wm * 64 + mf * 16 + (lane >> 2);
#pragma unroll
        for (int nf = 0; nf < 8; nf++) {
            const int col = col0 + wn * 64 + nf * 8 + (lane & 3) * 2;
            const float b0 = bias[col], b1 = bias[col + 1];
            float2 v0 = {acc[mf][nf][0] + b0, acc[mf][nf][1] + b1};
            float2 v1 = {acc[mf][nf][2] + b0, acc[mf][nf][3] + b1};
            if (do_round) {
                v0.x = tf32r(v0.x); v0.y = tf32r(v0.y);
                v1.x = tf32r(v1.x); v1.y = tf32r(v1.y);
            }
            *(float2*)&C[(size_t)rg * E_DIM + col]       = v0;
            *(float2*)&C[(size_t)(rg + 8) * E_DIM + col] = v1;
        }
    }
}

// ---------------- mask reduction --------------------------------------------
__global__ void mask_init_kernel() { g_mask_allones = 1; }
__global__ void mask_check_kernel(const int* __restrict__ mask, int n)
{
    int idx = blockIdx.x * blockDim.x + threadIdx.x;
    int stride = gridDim.x * blockDim.x;
    int bad = 0;
    for (int i = idx; i < n; i += stride) bad |= (mask[i] == 0);
    if (bad) atomicAnd(&g_mask_allones, 0);
}

// ======================= tf32 flash attention (BM=128) =======================
// 128 q, 64 keys/iter, d=128. 8 warps: S 4m x 2n (warp 32x32); PV 4m x 2d.
// smem floats: Q 16384 | K 2x8192 | V 2x8192 | P 8192 | redM 256 | redS 256
#define AT_OQ  0
#define AT_OK  16384
#define AT_OV  32768
#define AT_OP  49152
#define AT_ORM 57344
#define AT_ORS 57600
#define ATT_SMEM (57856 * 4)         // 231424 B

__global__ __launch_bounds__(256, 1) void attn_tf32_kernel(const int* __restrict__ mask)
{
    char* smc = dynsmem;
    const uint32_t sb = smem_u32(dynsmem);
    const int tid  = threadIdx.x;
    const int lane = tid & 31;
    const int wid  = tid >> 5;
    const int wm   = wid & 3;        // q 32-row group
    const int wn   = wid >> 2;       // 0..1
    const int q0   = blockIdx.x * 128;
    const int nh   = blockIdx.y;
    const int bn   = nh / H_HEADS;
    const int h    = nh % H_HEADS;
    const bool allones = (g_mask_allones != 0);
    const float sc = rsqrtf((float)D_HEAD);

    const char* qg = (const char*)(g_q + (size_t)(bn * S_LEN + q0) * E_DIM + h * D_HEAD);
    const char* kg = (const char*)(g_k + (size_t)(bn * T_LEN) * E_DIM + h * D_HEAD);
    const char* vg = (const char*)(g_v + (size_t)(bn * T_LEN) * E_DIM + h * D_HEAD);

    const int a_ro = (lane & 7) + ((lane >> 3) & 1) * 8;
    const int a_kh = (lane >> 4) & 1;
    const int b_ro = (lane & 7) + ((lane >> 4) & 1) * 8;
    const int b_kh = (lane >> 3) & 1;

    auto load64 = [&](const char* src, uint32_t base) {   // 64x128 fp32
#pragma unroll
        for (int it = 0; it < 8; it++) {
            int ch = tid + it * 256;
            int r = ch >> 5, g = ch & 31;
            CP_ASYNC16(base + r * 512 + SW4(g, r) * 16, src + (size_t)r * 8192 + g * 16);
        }
    };
    // Q: 128x128 fp32 (4096 chunks)
#pragma unroll
    for (int it = 0; it < 16; it++) {
        int ch = tid + it * 256;
        int r = ch >> 5, g = ch & 31;
        CP_ASYNC16(sb + AT_OQ * 4 + r * 512 + SW4(g, r) * 16,
                   qg + (size_t)r * 8192 + g * 16);
    }
    load64(kg, sb + AT_OK * 4);
    load64(vg, sb + AT_OV * 4);
    CP_COMMIT();

    float o[2][8][4];
    float m[2][2], lsum[2][2];
#pragma unroll
    for (int mf = 0; mf < 2; mf++) {
#pragma unroll
        for (int r = 0; r < 2; r++) { m[mf][r] = -INFINITY; lsum[mf][r] = 0.f; }
#pragma unroll
        for (int nf = 0; nf < 8; nf++)
#pragma unroll
            for (int e = 0; e < 4; e++) o[mf][nf][e] = 0.f;
    }
    float* redM = (float*)smc + AT_ORM;
    float* redS = (float*)smc + AT_ORS;

    const int nb = T_LEN / 64;
    for (int j = 0; j < nb; j++) {
        const int b = j & 1;
        CP_WAIT0();
        __syncthreads();
        if (j + 1 < nb) {
            load64(kg + (size_t)(j + 1) * 64 * 8192, sb + (AT_OK + (1 - b) * 8192) * 4);
            load64(vg + (size_t)(j + 1) * 64 * 8192, sb + (AT_OV + (1 - b) * 8192) * 4);
            CP_COMMIT();
        }
        const uint32_t sQ = sb + AT_OQ * 4;
        const uint32_t sK = sb + (AT_OK + b * 8192) * 4;
        const uint32_t sP = sb + AT_OP * 4;

        // ---- S = Q K^T  (warp: 32q x 32keys), 16 k8-steps
        float s[2][4][4];
#pragma unroll
        for (int mf = 0; mf < 2; mf++)
#pragma unroll
            for (int nf = 0; nf < 4; nf++)
#pragma unroll
                for (int e = 0; e < 4; e++) s[mf][nf][e] = 0.f;

#pragma unroll
        for (int ks = 0; ks < 16; ks++) {
            uint32_t a[2][4], bfr[4][2];
#pragma unroll
            for (int mf = 0; mf < 2; mf++) {
                int r = wm * 32 + mf * 16 + a_ro;
                ldsm_x4(a[mf][0], a[mf][1], a[mf][2], a[mf][3],
                        sQ + r * 512 + SW4(2 * ks + a_kh, r) * 16);
            }
#pragma unroll
            for (int pj = 0; pj < 2; pj++) {
                int r = wn * 32 + pj * 16 + b_ro;
                uint32_t r0, r1, r2, r3;
                ldsm_x4(r0, r1, r2, r3, sK + r * 512 + SW4(2 * ks + b_kh, r) * 16);
                bfr[2 * pj][0] = r0;     bfr[2 * pj][1] = r1;
                bfr[2 * pj + 1][0] = r2; bfr[2 * pj + 1][1] = r3;
            }
#pragma unroll
            for (int mf = 0; mf < 2; mf++)
#pragma unroll
                for (int nf = 0; nf < 4; nf++)
                    mma_tf32(s[mf][nf], a[mf], bfr[nf]);
        }

#pragma unroll
        for (int mf = 0; mf < 2; mf++)
#pragma unroll
            for (int nf = 0; nf < 4; nf++)
#pragma unroll
                for (int e = 0; e < 4; e++) s[mf][nf][e] *= sc;

        if (!allones) {
#pragma unroll
            for (int mf = 0; mf < 2; mf++)
#pragma unroll
                for (int nf = 0; nf < 4; nf++)
#pragma unroll
                    for (int e = 0; e < 4; e++) {
                        int r = wm * 32 + mf * 16 + (lane >> 2) + (e >> 1) * 8;
                        int c = wn * 32 + nf * 8 + (lane & 3) * 2 + (e & 1);
                        if (mask[(size_t)(j * 64 + c) * S_LEN + q0 + r] == 0)
                            s[mf][nf][e] = -INFINITY;
                    }
        }

        // ---- partial row max over this warp's 32 keys
#pragma unroll
        for (int mf = 0; mf < 2; mf++) {
            float mx0 = fmaxf(fmaxf(s[mf][0][0], s[mf][0][1]),
                              fmaxf(s[mf][1][0], s[mf][1][1]));
            mx0 = fmaxf(mx0, fmaxf(fmaxf(s[mf][2][0], s[mf][2][1]),
                                   fmaxf(s[mf][3][0], s[mf][3][1])));
            float mx1 = fmaxf(fmaxf(s[mf][0][2], s[mf][0][3]),
                              fmaxf(s[mf][1][2], s[mf][1][3]));
            mx1 = fmaxf(mx1, fmaxf(fmaxf(s[mf][2][2], s[mf][2][3]),
                                   fmaxf(s[mf][3][2], s[mf][3][3])));
            mx0 = fmaxf(mx0, __shfl_xor_sync(0xffffffffu, mx0, 1));
            mx0 = fmaxf(mx0, __shfl_xor_sync(0xffffffffu, mx0, 2));
            mx1 = fmaxf(mx1, __shfl_xor_sync(0xffffffffu, mx1, 1));
            mx1 = fmaxf(mx1, __shfl_xor_sync(0xffffffffu, mx1, 2));
            if ((lane & 3) == 0) {
                int row = wm * 32 + mf * 16 + (lane >> 2);
                redM[wn * 128 + row]     = mx0;
                redM[wn * 128 + row + 8] = mx1;
            }
        }
        __syncthreads();

        float alpha[2][2];
#pragma unroll
        for (int mf = 0; mf < 2; mf++)
#pragma unroll
            for (int r = 0; r < 2; r++) {
                int row = wm * 32 + mf * 16 + (lane >> 2) + r * 8;
                float bm = fmaxf(redM[row], redM[128 + row]);
                float mn = fmaxf(m[mf][r], bm);
                alpha[mf][r] = (m[mf][r] == mn) ? 1.f : __expf(m[mf][r] - mn);
                m[mf][r] = mn;
            }

        // ---- p = exp(s-m); P store (tf32); partial sums
#pragma unroll
        for (int mf = 0; mf < 2; mf++) {
            int R0 = wm * 32 + mf * 16 + (lane >> 2);
            int R1 = R0 + 8;
            float ps0 = 0.f, ps1 = 0.f;
#pragma unroll
            for (int nf = 0; nf < 4; nf++) {
                float e0 = __expf(s[mf][nf][0] - m[mf][0]);
                float e1 = __expf(s[mf][nf][1] - m[mf][0]);
                float e2 = __expf(s[mf][nf][2] - m[mf][1]);
                float e3 = __expf(s[mf][nf][3] - m[mf][1]);
                ps0 += e0 + e1; ps1 += e2 + e3;
                int c = wn * 32 + nf * 8 + (lane & 3) * 2;
                int g = c >> 2;
                float2 v0 = {tf32r(e0), tf32r(e1)};
                float2 v1 = {tf32r(e2), tf32r(e3)};
                *(float2*)(smc + AT_OP * 4 + R0 * 256 + SW4(g, R0) * 16 + (c & 3) * 4) = v0;
                *(float2*)(smc + AT_OP * 4 + R1 * 256 + SW4(g, R1) * 16 + (c & 3) * 4) = v1;
            }
            ps0 += __shfl_xor_sync(0xffffffffu, ps0, 1);
            ps0 += __shfl_xor_sync(0xffffffffu, ps0, 2);
            ps1 += __shfl_xor_sync(0xffffffffu, ps1, 1);
            ps1 += __shfl_xor_sync(0xffffffffu, ps1, 2);
            if ((lane & 3) == 0) {
                redS[wn * 128 + R0] = ps0;
                redS[wn * 128 + R1] = ps1;
            }
            // rescale O
#pragma unroll
            for (int nf = 0; nf < 8; nf++) {
                o[mf][nf][0] *= alpha[mf][0]; o[mf][nf][1] *= alpha[mf][0];
                o[mf][nf][2] *= alpha[mf][1]; o[mf][nf][3] *= alpha[mf][1];
            }
        }
        __syncthreads();

#pragma unroll
        for (int mf = 0; mf < 2; mf++)
#pragma unroll
            for (int r = 0; r < 2; r++) {
                int row = wm * 32 + mf * 16 + (lane >> 2) + r * 8;
                lsum[mf][r] = lsum[mf][r] * alpha[mf][r] + redS[row] + redS[128 + row];
            }

        // ---- O += P V  (warp: 32q x 64d), 8 k8-steps
#pragma unroll
        for (int ks = 0; ks < 8; ks++) {
            uint32_t ap[2][4];
#pragma unroll
            for (int mf = 0; mf < 2; mf++) {
                int r = wm * 32 + mf * 16 + a_ro;
                ldsm_x4(ap[mf][0], ap[mf][1], ap[mf][2], ap[mf][3],
                        sP + r * 256 + SW4(2 * ks + a_kh, r) * 16);
            }
            int t0l = ks * 8 + (lane & 3);
            int t1l = t0l + 4;
#pragma unroll
            for (int nf = 0; nf < 8; nf++) {
                int d = wn * 64 + nf * 8 + (lane >> 2);
                uint32_t bv[2];
                bv[0] = *(const uint32_t*)(smc + (AT_OV + b * 8192) * 4 + t0l * 512 + SW4(d >> 2, t0l) * 16 + (d & 3) * 4);
                bv[1] = *(const uint32_t*)(smc + (AT_OV + b * 8192) * 4 + t1l * 512 + SW4(d >> 2, t1l) * 16 + (d & 3) * 4);
#pragma unroll
                for (int mf = 0; mf < 2; mf++)
                    mma_tf32(o[mf][nf], ap[mf], bv);
            }
        }
        __syncthreads();   // protect KV buffer b, P, red before next iter
    }

    float* cb = g_ctx + (size_t)(bn * S_LEN + q0) * E_DIM + h * D_HEAD;
#pragma unroll
    for (int mf = 0; mf < 2; mf++) {
        int R0 = wm * 32 + mf * 16 + (lane >> 2);
        float i0 = 1.f / lsum[mf][0], i1 = 1.f / lsum[mf][1];
#pragma unroll
        for (int nf = 0; nf < 8; nf++) {
            int c = wn * 64 + nf * 8 + (lane & 3) * 2;
            float2 v0 = {tf32r(o[mf][nf][0] * i0), tf32r(o[mf][nf][1] * i0)};
            float2 v1 = {tf32r(o[mf][nf][2] * i1), tf32r(o[mf][nf][3] * i1)};
            *(float2*)&cb[(size_t)R0 * E_DIM + c]       = v0;
            *(float2*)&cb[(size_t)(R0 + 8) * E_DIM + c] = v1;
        }
    }
}

// ---------------- launch -----------------------------------------------------
extern "C" void kernel_launch(void* const* d_in, const int* in_sizes, int n_in,
                              void* d_out, int out_size)
{
    const float* query = (const float*)d_in[0];
    const float* key   = (const float*)d_in[1];
    const float* value = (const float*)d_in[2];
    const int*   mask  = (const int*)  d_in[3];
    const float* Wq    = (const float*)d_in[4];
    const float* bq    = (const float*)d_in[5];
    const float* Wk    = (const float*)d_in[6];
    const float* bk    = (const float*)d_in[7];
    const float* Wv    = (const float*)d_in[8];
    const float* bv    = (const float*)d_in[9];
    const float* Wp    = (const float*)d_in[10];
    const float* bp    = (const float*)d_in[11];
    float* out = (float*)d_out;

    float *qs, *ks, *vs, *cs, *ra, *rw;
    cudaGetSymbolAddress((void**)&qs, g_q);
    cudaGetSymbolAddress((void**)&ks, g_k);
    cudaGetSymbolAddress((void**)&vs, g_v);
    cudaGetSymbolAddress((void**)&cs, g_ctx);
    cudaGetSymbolAddress((void**)&ra, g_ra);
    cudaGetSymbolAddress((void**)&rw, g_rw);

    cudaFuncSetAttribute(gemm_tf32_kernel,
                         cudaFuncAttributeMaxDynamicSharedMemorySize, GEMM_SMEM);
    cudaFuncSetAttribute(attn_tf32_kernel,
                         cudaFuncAttributeMaxDynamicSharedMemorySize, ATT_SMEM);

    const int nA4 = M_TOK * 512;
    const int nW4 = E_DIM * 512;
    dim3 ggrid(E_DIM / 256, M_TOK / 128);   // (8, 64)

    round_tf32_kernel<<<nA4 / 256, 256>>>(query, ra, nA4);
    round_tf32_kernel<<<nW4 / 256, 256>>>(Wq, rw, nW4);
    gemm_tf32_kernel<<<ggrid, 256, GEMM_SMEM>>>(ra, rw, bq, qs, 1);

    round_tf32_kernel<<<nA4 / 256, 256>>>(key, ra, nA4);
    round_tf32_kernel<<<nW4 / 256, 256>>>(Wk, rw, nW4);
    gemm_tf32_kernel<<<ggrid, 256, GEMM_SMEM>>>(ra, rw, bk, ks, 1);

    round_tf32_kernel<<<nA4 / 256, 256>>>(value, ra, nA4);
    round_tf32_kernel<<<nW4 / 256, 256>>>(Wv, rw, nW4);
    gemm_tf32_kernel<<<ggrid, 256, GEMM_SMEM>>>(ra, rw, bv, vs, 1);

    mask_init_kernel<<<1, 1>>>();
    mask_check_kernel<<<1024, 256>>>(mask, T_LEN * S_LEN);

    attn_tf32_kernel<<<dim3(S_LEN / 128, N_BATCH * H_HEADS), 256, ATT_SMEM>>>(mask);

    round_tf32_kernel<<<nW4 / 256, 256>>>(Wp, rw, nW4);
    gemm_tf32_kernel<<<ggrid, 256, GEMM_SMEM>>>(cs, rw, bp, out, 0);
}

// round 9
// speedup vs baseline: 9.9938x; 1.8557x over previous
#include <cuda_runtime.h>
#include <cuda_fp16.h>
#include <math.h>
#include <cstdint>

#define E_DIM   2048
#define H_HEADS 16
#define D_HEAD  128
#define N_BATCH 4
#define S_LEN   2048
#define T_LEN   2048
#define M_TOK   (N_BATCH * S_LEN)

// ---------------- scratch ----------------------------------------------------
__device__ __half g_q16[16777216];
__device__ __half g_k16[16777216];
__device__ __half g_v16[16777216];
__device__ __half g_ctx16[16777216];
__device__ __half g_ra16[16777216];   // converted activation
__device__ __half g_rw16[4194304];    // converted weight
__device__ int    g_mask_allones;

extern __shared__ char dynsmem[];

// ======================= helpers =============================================
__device__ __forceinline__ uint32_t smem_u32(const void* p) {
    uint32_t a;
    asm("{ .reg .u64 t; cvta.to.shared.u64 t, %1; cvt.u32.u64 %0, t; }"
        : "=r"(a) : "l"(p));
    return a;
}
#define CP_ASYNC16(dst, src) asm volatile("cp.async.cg.shared.global [%0], [%1], 16;" :: "r"(dst), "l"(src))
#define CP_COMMIT()          asm volatile("cp.async.commit_group;" ::: "memory")
#define CP_WAIT0()           asm volatile("cp.async.wait_group 0;" ::: "memory")
#define CP_WAIT1()           asm volatile("cp.async.wait_group 1;" ::: "memory")

__device__ __forceinline__ void ldsm_x4(uint32_t& r0, uint32_t& r1,
                                        uint32_t& r2, uint32_t& r3, uint32_t a) {
    asm volatile("ldmatrix.sync.aligned.m8n8.x4.shared.b16 {%0,%1,%2,%3}, [%4];"
                 : "=r"(r0), "=r"(r1), "=r"(r2), "=r"(r3) : "r"(a));
}
__device__ __forceinline__ void ldsm_x4_t(uint32_t& r0, uint32_t& r1,
                                          uint32_t& r2, uint32_t& r3, uint32_t a) {
    asm volatile("ldmatrix.sync.aligned.m8n8.x4.trans.shared.b16 {%0,%1,%2,%3}, [%4];"
                 : "=r"(r0), "=r"(r1), "=r"(r2), "=r"(r3) : "r"(a));
}
__device__ __forceinline__ void mma_f16(float* d, const uint32_t* a, const uint32_t* b) {
    asm volatile(
        "mma.sync.aligned.m16n8k16.row.col.f32.f16.f16.f32 "
        "{%0,%1,%2,%3}, {%4,%5,%6,%7}, {%8,%9}, {%0,%1,%2,%3};"
        : "+f"(d[0]), "+f"(d[1]), "+f"(d[2]), "+f"(d[3])
        : "r"(a[0]), "r"(a[1]), "r"(a[2]), "r"(a[3]), "r"(b[0]), "r"(b[1]));
}
#define SW4(g, row) (((g) & 24) | (((g) & 7) ^ ((row) & 7)))

// ======================= convert fp32 -> fp16(RN) ============================
__global__ __launch_bounds__(256) void cvt_f16_kernel(
    const float* __restrict__ src, __half* __restrict__ dst, int n4)
{
    int idx = blockIdx.x * blockDim.x + threadIdx.x;
    if (idx >= n4) return;
    float4 v = ((const float4*)src)[idx];
    __half2 h0 = __floats2half2_rn(v.x, v.y);
    __half2 h1 = __floats2half2_rn(v.z, v.w);
    ((__half2*)dst)[idx * 2]     = h0;
    ((__half2*)dst)[idx * 2 + 1] = h1;
}

// ======================= fp16 GEMM: C = A@B^T + bias =========================
// Tile 128x256, 8 warps (2m x 4n, warp 64x64), BK=64 fp16 (128B rows), 3 stages.
#define GNT 32                       // 2048/64
#define GA_B (128 * 128)             // 16384 B
#define GB_B (256 * 128)             // 32768 B
#define GSTG_B (GA_B + GB_B)         // 49152
#define GEMM_SMEM (3 * GSTG_B)       // 147456

__global__ __launch_bounds__(256, 1) void gemm_f16_kernel(
    const __half* __restrict__ A, const __half* __restrict__ B,
    const float* __restrict__ bias, __half* __restrict__ C16,
    float* __restrict__ C32)
{
    const uint32_t sb = smem_u32(dynsmem);
    const int tid  = threadIdx.x;
    const int lane = tid & 31;
    const int wid  = tid >> 5;
    const int wm   = wid & 1;
    const int wn   = wid >> 1;
    const int row0 = blockIdx.y * 128;
    const int col0 = blockIdx.x * 256;

    const char* Ab = (const char*)(A + (size_t)row0 * E_DIM);  // row = 4096 B
    const char* Bb = (const char*)(B + (size_t)col0 * E_DIM);

    float acc[4][8][4];
#pragma unroll
    for (int mf = 0; mf < 4; mf++)
#pragma unroll
        for (int nf = 0; nf < 8; nf++)
#pragma unroll
            for (int e = 0; e < 4; e++) acc[mf][nf][e] = 0.f;

    auto load_stage = [&](int kt, int stg) {
        const uint32_t sA = sb + stg * GSTG_B;
        const uint32_t sB = sA + GA_B;
        const size_t koff = (size_t)kt * 128;   // bytes (64 halves)
#pragma unroll
        for (int it = 0; it < 4; it++) {        // A: 1024 chunks
            int ch = tid + it * 256;
            int r = ch >> 3, g = ch & 7;
            CP_ASYNC16(sA + r * 128 + SW4(g, r) * 16,
                       Ab + (size_t)r * 4096 + koff + g * 16);
        }
#pragma unroll
        for (int it = 0; it < 8; it++) {        // B: 2048 chunks
            int ch = tid + it * 256;
            int r = ch >> 3, g = ch & 7;
            CP_ASYNC16(sB + r * 128 + SW4(g, r) * 16,
                       Bb + (size_t)r * 4096 + koff + g * 16);
        }
    };

    load_stage(0, 0); CP_COMMIT();
    load_stage(1, 1); CP_COMMIT();

    const int a_ro = (lane & 7) + ((lane >> 3) & 1) * 8;
    const int a_kh = (lane >> 4) & 1;
    const int b_ro = (lane & 7) + ((lane >> 4) & 1) * 8;
    const int b_kh = (lane >> 3) & 1;

    for (int i = 0; i < GNT; i++) {
        CP_WAIT1();
        __syncthreads();
        const int j = i + 2;
        if (j < GNT) load_stage(j, j % 3);
        CP_COMMIT();

        const uint32_t sA = sb + (i % 3) * GSTG_B;
        const uint32_t sB = sA + GA_B;
#pragma unroll
        for (int s = 0; s < 4; s++) {           // 4 k16 steps per BK=64
            uint32_t a[4][4], b[8][2];
#pragma unroll
            for (int mf = 0; mf < 4; mf++) {
                int r = wm * 64 + mf * 16 + a_ro;
                ldsm_x4(a[mf][0], a[mf][1], a[mf][2], a[mf][3],
                        sA + r * 128 + SW4(2 * s + a_kh, r) * 16);
            }
#pragma unroll
            for (int pj = 0; pj < 4; pj++) {
                int r = wn * 64 + pj * 16 + b_ro;
                uint32_t r0, r1, r2, r3;
                ldsm_x4(r0, r1, r2, r3, sB + r * 128 + SW4(2 * s + b_kh, r) * 16);
                b[2 * pj][0] = r0;     b[2 * pj][1] = r1;
                b[2 * pj + 1][0] = r2; b[2 * pj + 1][1] = r3;
            }
#pragma unroll
            for (int mf = 0; mf < 4; mf++)
#pragma unroll
                for (int nf = 0; nf < 8; nf++)
                    mma_f16(acc[mf][nf], a[mf], b[nf]);
        }
    }

#pragma unroll
    for (int mf = 0; mf < 4; mf++) {
        const int rg = row0 + wm * 64 + mf * 16 + (lane >> 2);
#pragma unroll
        for (int nf = 0; nf < 8; nf++) {
            const int col = col0 + wn * 64 + nf * 8 + (lane & 3) * 2;
            const float b0 = bias[col], b1 = bias[col + 1];
            float v00 = acc[mf][nf][0] + b0, v01 = acc[mf][nf][1] + b1;
            float v10 = acc[mf][nf][2] + b0, v11 = acc[mf][nf][3] + b1;
            if (C16) {
                *(__half2*)&C16[(size_t)rg * E_DIM + col]       = __floats2half2_rn(v00, v01);
                *(__half2*)&C16[(size_t)(rg + 8) * E_DIM + col] = __floats2half2_rn(v10, v11);
            } else {
                *(float2*)&C32[(size_t)rg * E_DIM + col]       = make_float2(v00, v01);
                *(float2*)&C32[(size_t)(rg + 8) * E_DIM + col] = make_float2(v10, v11);
            }
        }
    }
}

// ---------------- mask reduction --------------------------------------------
__global__ void mask_init_kernel() { g_mask_allones = 1; }
__global__ void mask_check_kernel(const int* __restrict__ mask, int n)
{
    int idx = blockIdx.x * blockDim.x + threadIdx.x;
    int stride = gridDim.x * blockDim.x;
    int bad = 0;
    for (int i = idx; i < n; i += stride) bad |= (mask[i] == 0);
    if (bad) atomicAnd(&g_mask_allones, 0);
}

// ======================= fp16 flash attention (BM=128) =======================
// 128 q, 64 keys/iter, d=128. 8 warps: 4m x 2n (warp S: 32q x 32k; PV: 32q x 64d)
// smem bytes: Q 32768 | K 2x16384 | V 2x16384 | P 16384 | redM 1024 | redS 1024
#define AQ  0
#define AK  32768
#define AV  65536
#define AP  98304
#define ARM 114688
#define ARS 115712
#define ATT_SMEM 116736

__global__ __launch_bounds__(256, 1) void attn_f16_kernel(const int* __restrict__ mask)
{
    char* smc = dynsmem;
    const uint32_t sb = smem_u32(dynsmem);
    const int tid  = threadIdx.x;
    const int lane = tid & 31;
    const int wid  = tid >> 5;
    const int wm   = wid & 3;
    const int wn   = wid >> 2;
    const int q0   = blockIdx.x * 128;
    const int nh   = blockIdx.y;
    const int bn   = nh / H_HEADS;
    const int h    = nh % H_HEADS;
    const bool allones = (g_mask_allones != 0);
    const float sc = rsqrtf((float)D_HEAD);

    const char* qg = (const char*)(g_q16 + (size_t)(bn * S_LEN + q0) * E_DIM + h * D_HEAD);
    const char* kg = (const char*)(g_k16 + (size_t)(bn * T_LEN) * E_DIM + h * D_HEAD);
    const char* vg = (const char*)(g_v16 + (size_t)(bn * T_LEN) * E_DIM + h * D_HEAD);

    const int a_ro = (lane & 7) + ((lane >> 3) & 1) * 8;
    const int a_kh = (lane >> 4) & 1;
    const int b_ro = (lane & 7) + ((lane >> 4) & 1) * 8;
    const int b_kh = (lane >> 3) & 1;

    auto load64 = [&](const char* src, uint32_t base) {   // 64x128 fp16 (256B rows)
#pragma unroll
        for (int it = 0; it < 4; it++) {
            int ch = tid + it * 256;
            int r = ch >> 4, g = ch & 15;
            CP_ASYNC16(base + r * 256 + SW4(g, r) * 16, src + (size_t)r * 4096 + g * 16);
        }
    };
    // Q: 128x128 fp16 (2048 chunks)
#pragma unroll
    for (int it = 0; it < 8; it++) {
        int ch = tid + it * 256;
        int r = ch >> 4, g = ch & 15;
        CP_ASYNC16(sb + AQ + r * 256 + SW4(g, r) * 16, qg + (size_t)r * 4096 + g * 16);
    }
    load64(kg, sb + AK);
    load64(vg, sb + AV);
    CP_COMMIT();

    float o[2][8][4];
    float m[2][2], lsum[2][2];
#pragma unroll
    for (int mf = 0; mf < 2; mf++) {
#pragma unroll
        for (int r = 0; r < 2; r++) { m[mf][r] = -INFINITY; lsum[mf][r] = 0.f; }
#pragma unroll
        for (int nf = 0; nf < 8; nf++)
#pragma unroll
            for (int e = 0; e < 4; e++) o[mf][nf][e] = 0.f;
    }
    float* redM = (float*)(smc + ARM);
    float* redS = (float*)(smc + ARS);

    const int nb = T_LEN / 64;
    for (int j = 0; j < nb; j++) {
        const int b = j & 1;
        CP_WAIT0();
        __syncthreads();
        if (j + 1 < nb) {
            load64(kg + (size_t)(j + 1) * 64 * 4096, sb + AK + (1 - b) * 16384);
            load64(vg + (size_t)(j + 1) * 64 * 4096, sb + AV + (1 - b) * 16384);
            CP_COMMIT();
        }
        const uint32_t sQ = sb + AQ;
        const uint32_t sK = sb + AK + b * 16384;
        const uint32_t sV = sb + AV + b * 16384;
        const uint32_t sP = sb + AP;

        // ---- S = Q K^T (warp: 32q x 32keys), 8 k16-steps over d=128
        float s[2][4][4];
#pragma unroll
        for (int mf = 0; mf < 2; mf++)
#pragma unroll
            for (int nf = 0; nf < 4; nf++)
#pragma unroll
                for (int e = 0; e < 4; e++) s[mf][nf][e] = 0.f;

#pragma unroll
        for (int ks = 0; ks < 8; ks++) {
            uint32_t a[2][4], bfr[4][2];
#pragma unroll
            for (int mf = 0; mf < 2; mf++) {
                int r = wm * 32 + mf * 16 + a_ro;
                ldsm_x4(a[mf][0], a[mf][1], a[mf][2], a[mf][3],
                        sQ + r * 256 + SW4(2 * ks + a_kh, r) * 16);
            }
#pragma unroll
            for (int pj = 0; pj < 2; pj++) {
                int r = wn * 32 + pj * 16 + b_ro;
                uint32_t r0, r1, r2, r3;
                ldsm_x4(r0, r1, r2, r3, sK + r * 256 + SW4(2 * ks + b_kh, r) * 16);
                bfr[2 * pj][0] = r0;     bfr[2 * pj][1] = r1;
                bfr[2 * pj + 1][0] = r2; bfr[2 * pj + 1][1] = r3;
            }
#pragma unroll
            for (int mf = 0; mf < 2; mf++)
#pragma unroll
                for (int nf = 0; nf < 4; nf++)
                    mma_f16(s[mf][nf], a[mf], bfr[nf]);
        }

#pragma unroll
        for (int mf = 0; mf < 2; mf++)
#pragma unroll
            for (int nf = 0; nf < 4; nf++)
#pragma unroll
                for (int e = 0; e < 4; e++) s[mf][nf][e] *= sc;

        if (!allones) {
#pragma unroll
            for (int mf = 0; mf < 2; mf++)
#pragma unroll
                for (int nf = 0; nf < 4; nf++)
#pragma unroll
                    for (int e = 0; e < 4; e++) {
                        int r = wm * 32 + mf * 16 + (lane >> 2) + (e >> 1) * 8;
                        int c = wn * 32 + nf * 8 + (lane & 3) * 2 + (e & 1);
                        if (mask[(size_t)(j * 64 + c) * S_LEN + q0 + r] == 0)
                            s[mf][nf][e] = -INFINITY;
                    }
        }

        // ---- partial row max
#pragma unroll
        for (int mf = 0; mf < 2; mf++) {
            float mx0 = fmaxf(fmaxf(s[mf][0][0], s[mf][0][1]),
                              fmaxf(s[mf][1][0], s[mf][1][1]));
            mx0 = fmaxf(mx0, fmaxf(fmaxf(s[mf][2][0], s[mf][2][1]),
                                   fmaxf(s[mf][3][0], s[mf][3][1])));
            float mx1 = fmaxf(fmaxf(s[mf][0][2], s[mf][0][3]),
                              fmaxf(s[mf][1][2], s[mf][1][3]));
            mx1 = fmaxf(mx1, fmaxf(fmaxf(s[mf][2][2], s[mf][2][3]),
                                   fmaxf(s[mf][3][2], s[mf][3][3])));
            mx0 = fmaxf(mx0, __shfl_xor_sync(0xffffffffu, mx0, 1));
            mx0 = fmaxf(mx0, __shfl_xor_sync(0xffffffffu, mx0, 2));
            mx1 = fmaxf(mx1, __shfl_xor_sync(0xffffffffu, mx1, 1));
            mx1 = fmaxf(mx1, __shfl_xor_sync(0xffffffffu, mx1, 2));
            if ((lane & 3) == 0) {
                int row = wm * 32 + mf * 16 + (lane >> 2);
                redM[wn * 128 + row]     = mx0;
                redM[wn * 128 + row + 8] = mx1;
            }
        }
        __syncthreads();

        float alpha[2][2];
#pragma unroll
        for (int mf = 0; mf < 2; mf++)
#pragma unroll
            for (int r = 0; r < 2; r++) {
                int row = wm * 32 + mf * 16 + (lane >> 2) + r * 8;
                float bm = fmaxf(redM[row], redM[128 + row]);
                float mn = fmaxf(m[mf][r], bm);
                alpha[mf][r] = (m[mf][r] == mn) ? 1.f : __expf(m[mf][r] - mn);
                m[mf][r] = mn;
            }

        // ---- p = exp(s-m); store P as fp16; partial sums
#pragma unroll
        for (int mf = 0; mf < 2; mf++) {
            int R0 = wm * 32 + mf * 16 + (lane >> 2);
            int R1 = R0 + 8;
            float ps0 = 0.f, ps1 = 0.f;
#pragma unroll
            for (int nf = 0; nf < 4; nf++) {
                float e0 = __expf(s[mf][nf][0] - m[mf][0]);
                float e1 = __expf(s[mf][nf][1] - m[mf][0]);
                float e2 = __expf(s[mf][nf][2] - m[mf][1]);
                float e3 = __expf(s[mf][nf][3] - m[mf][1]);
                ps0 += e0 + e1; ps1 += e2 + e3;
                int c = wn * 32 + nf * 8 + (lane & 3) * 2;
                int g = c >> 3;                     // 16B granule (8 halves)
                int off = (2 * c) & 15;
                *(__half2*)(smc + AP + R0 * 128 + SW4(g, R0) * 16 + off) = __floats2half2_rn(e0, e1);
                *(__half2*)(smc + AP + R1 * 128 + SW4(g, R1) * 16 + off) = __floats2half2_rn(e2, e3);
            }
            ps0 += __shfl_xor_sync(0xffffffffu, ps0, 1);
            ps0 += __shfl_xor_sync(0xffffffffu, ps0, 2);
            ps1 += __shfl_xor_sync(0xffffffffu, ps1, 1);
            ps1 += __shfl_xor_sync(0xffffffffu, ps1, 2);
            if ((lane & 3) == 0) {
                redS[wn * 128 + R0] = ps0;
                redS[wn * 128 + R1] = ps1;
            }
#pragma unroll
            for (int nf = 0; nf < 8; nf++) {
                o[mf][nf][0] *= alpha[mf][0]; o[mf][nf][1] *= alpha[mf][0];
                o[mf][nf][2] *= alpha[mf][1]; o[mf][nf][3] *= alpha[mf][1];
            }
        }
        __syncthreads();

#pragma unroll
        for (int mf = 0; mf < 2; mf++)
#pragma unroll
            for (int r = 0; r < 2; r++) {
                int row = wm * 32 + mf * 16 + (lane >> 2) + r * 8;
                lsum[mf][r] = lsum[mf][r] * alpha[mf][r] + redS[row] + redS[128 + row];
            }

        // ---- O += P V (warp: 32q x 64d), 4 k16-steps; V via ldmatrix.trans
#pragma unroll
        for (int ks = 0; ks < 4; ks++) {
            uint32_t ap[2][4];
#pragma unroll
            for (int mf = 0; mf < 2; mf++) {
                int r = wm * 32 + mf * 16 + a_ro;
                ldsm_x4(ap[mf][0], ap[mf][1], ap[mf][2], ap[mf][3],
                        sP + r * 128 + SW4(2 * ks + a_kh, r) * 16);
            }
            uint32_t bv[8][2];
#pragma unroll
            for (int pv = 0; pv < 4; pv++) {
                // trans-ldsm: rows = keys ks*16 + (lane&15); granule = d-col group
                int r = ks * 16 + (lane & 15);
                int g = wn * 8 + pv * 2 + ((lane >> 4) & 1);
                uint32_t r0, r1, r2, r3;
                ldsm_x4_t(r0, r1, r2, r3, sV + r * 256 + SW4(g, r) * 16);
                bv[2 * pv][0] = r0;     bv[2 * pv][1] = r1;
                bv[2 * pv + 1][0] = r2; bv[2 * pv + 1][1] = r3;
            }
#pragma unroll
            for (int mf = 0; mf < 2; mf++)
#pragma unroll
                for (int nf = 0; nf < 8; nf++)
                    mma_f16(o[mf][nf], ap[mf], bv[nf]);
        }
        __syncthreads();
    }

    __half* cb = g_ctx16 + (size_t)(bn * S_LEN + q0) * E_DIM + h * D_HEAD;
#pragma unroll
    for (int mf = 0; mf < 2; mf++) {
        int R0 = wm * 32 + mf * 16 + (lane >> 2);
        float i0 = 1.f / lsum[mf][0], i1 = 1.f / lsum[mf][1];
#pragma unroll
        for (int nf = 0; nf < 8; nf++) {
            int c = wn * 64 + nf * 8 + (lane & 3) * 2;
            *(__half2*)&cb[(size_t)R0 * E_DIM + c] =
                __floats2half2_rn(o[mf][nf][0] * i0, o[mf][nf][1] * i0);
            *(__half2*)&cb[(size_t)(R0 + 8) * E_DIM + c] =
                __floats2half2_rn(o[mf][nf][2] * i1, o[mf][nf][3] * i1);
        }
    }
}

// ---------------- launch -----------------------------------------------------
extern "C" void kernel_launch(void* const* d_in, const int* in_sizes, int n_in,
                              void* d_out, int out_size)
{
    const float* query = (const float*)d_in[0];
    const float* key   = (const float*)d_in[1];
    const float* value = (const float*)d_in[2];
    const int*   mask  = (const int*)  d_in[3];
    const float* Wq    = (const float*)d_in[4];
    const float* bq    = (const float*)d_in[5];
    const float* Wk    = (const float*)d_in[6];
    const float* bk    = (const float*)d_in[7];
    const float* Wv    = (const float*)d_in[8];
    const float* bv    = (const float*)d_in[9];
    const float* Wp    = (const float*)d_in[10];
    const float* bp    = (const float*)d_in[11];
    float* out = (float*)d_out;

    __half *qs, *ks, *vs, *cs, *ra, *rw;
    cudaGetSymbolAddress((void**)&qs, g_q16);
    cudaGetSymbolAddress((void**)&ks, g_k16);
    cudaGetSymbolAddress((void**)&vs, g_v16);
    cudaGetSymbolAddress((void**)&cs, g_ctx16);
    cudaGetSymbolAddress((void**)&ra, g_ra16);
    cudaGetSymbolAddress((void**)&rw, g_rw16);

    cudaFuncSetAttribute(gemm_f16_kernel,
                         cudaFuncAttributeMaxDynamicSharedMemorySize, GEMM_SMEM);
    cudaFuncSetAttribute(attn_f16_kernel,
                         cudaFuncAttributeMaxDynamicSharedMemorySize, ATT_SMEM);

    const int nA4 = M_TOK * 512;
    const int nW4 = E_DIM * 512;
    dim3 ggrid(E_DIM / 256, M_TOK / 128);   // (8, 64)

    cvt_f16_kernel<<<nA4 / 256, 256>>>(query, ra, nA4);
    cvt_f16_kernel<<<nW4 / 256, 256>>>(Wq, rw, nW4);
    gemm_f16_kernel<<<ggrid, 256, GEMM_SMEM>>>(ra, rw, bq, qs, nullptr);

    cvt_f16_kernel<<<nA4 / 256, 256>>>(key, ra, nA4);
    cvt_f16_kernel<<<nW4 / 256, 256>>>(Wk, rw, nW4);
    gemm_f16_kernel<<<ggrid, 256, GEMM_SMEM>>>(ra, rw, bk, ks, nullptr);

    cvt_f16_kernel<<<nA4 / 256, 256>>>(value, ra, nA4);
    cvt_f16_kernel<<<nW4 / 256, 256>>>(Wv, rw, nW4);
    gemm_f16_kernel<<<ggrid, 256, GEMM_SMEM>>>(ra, rw, bv, vs, nullptr);

    mask_init_kernel<<<1, 1>>>();
    mask_check_kernel<<<1024, 256>>>(mask, T_LEN * S_LEN);

    attn_f16_kernel<<<dim3(S_LEN / 128, N_BATCH * H_HEADS), 256, ATT_SMEM>>>(mask);

    cvt_f16_kernel<<<nW4 / 256, 256>>>(Wp, rw, nW4);
    gemm_f16_kernel<<<ggrid, 256, GEMM_SMEM>>>(cs, rw, bp, nullptr, out);
}

// round 10
// speedup vs baseline: 10.6091x; 1.0616x over previous
#include <cuda_runtime.h>
#include <cuda_fp16.h>
#include <math.h>
#include <cstdint>

#define E_DIM   2048
#define H_HEADS 16
#define D_HEAD  128
#define N_BATCH 4
#define S_LEN   2048
#define T_LEN   2048
#define M_TOK   (N_BATCH * S_LEN)

// ---------------- scratch ----------------------------------------------------
__device__ __half g_q16[16777216];
__device__ __half g_k16[16777216];
__device__ __half g_v16[16777216];
__device__ __half g_ctx16[16777216];
__device__ __half g_ra16[50331648];   // 3 activation buffers (q|k|v inputs)
__device__ __half g_rw16[16777216];   // 4 weight buffers
__device__ int    g_mask_allones;

extern __shared__ char dynsmem[];

// ======================= helpers =============================================
__device__ __forceinline__ uint32_t smem_u32(const void* p) {
    uint32_t a;
    asm("{ .reg .u64 t; cvta.to.shared.u64 t, %1; cvt.u32.u64 %0, t; }"
        : "=r"(a) : "l"(p));
    return a;
}
__device__ __forceinline__ uint32_t packh2(float a, float b) {
    __half2 h = __floats2half2_rn(a, b);
    return *reinterpret_cast<uint32_t*>(&h);
}
#define CP_ASYNC16(dst, src) asm volatile("cp.async.cg.shared.global [%0], [%1], 16;" :: "r"(dst), "l"(src))
#define CP_COMMIT()          asm volatile("cp.async.commit_group;" ::: "memory")
#define CP_WAIT0()           asm volatile("cp.async.wait_group 0;" ::: "memory")
#define CP_WAIT1()           asm volatile("cp.async.wait_group 1;" ::: "memory")

__device__ __forceinline__ void ldsm_x4(uint32_t& r0, uint32_t& r1,
                                        uint32_t& r2, uint32_t& r3, uint32_t a) {
    asm volatile("ldmatrix.sync.aligned.m8n8.x4.shared.b16 {%0,%1,%2,%3}, [%4];"
                 : "=r"(r0), "=r"(r1), "=r"(r2), "=r"(r3) : "r"(a));
}
__device__ __forceinline__ void ldsm_x4_t(uint32_t& r0, uint32_t& r1,
                                          uint32_t& r2, uint32_t& r3, uint32_t a) {
    asm volatile("ldmatrix.sync.aligned.m8n8.x4.trans.shared.b16 {%0,%1,%2,%3}, [%4];"
                 : "=r"(r0), "=r"(r1), "=r"(r2), "=r"(r3) : "r"(a));
}
__device__ __forceinline__ void mma_f16(float* d, const uint32_t* a, const uint32_t* b) {
    asm volatile(
        "mma.sync.aligned.m16n8k16.row.col.f32.f16.f16.f32 "
        "{%0,%1,%2,%3}, {%4,%5,%6,%7}, {%8,%9}, {%0,%1,%2,%3};"
        : "+f"(d[0]), "+f"(d[1]), "+f"(d[2]), "+f"(d[3])
        : "r"(a[0]), "r"(a[1]), "r"(a[2]), "r"(a[3]), "r"(b[0]), "r"(b[1]));
}
#define SW4(g, row) (((g) & 24) | (((g) & 7) ^ ((row) & 7)))

// ======================= convert fp32 -> fp16(RN) ============================
__global__ __launch_bounds__(256) void cvt_f16_kernel(
    const float* __restrict__ src, __half* __restrict__ dst, int n4)
{
    int idx = blockIdx.x * blockDim.x + threadIdx.x;
    if (idx >= n4) return;
    float4 v = ((const float4*)src)[idx];
    ((__half2*)dst)[idx * 2]     = __floats2half2_rn(v.x, v.y);
    ((__half2*)dst)[idx * 2 + 1] = __floats2half2_rn(v.z, v.w);
}

// ======================= fp16 GEMM: C = A@B^T + bias (proven R9) =============
#define GNT 32
#define GA_B (128 * 128)
#define GB_B (256 * 128)
#define GSTG_B (GA_B + GB_B)
#define GEMM_SMEM (3 * GSTG_B)       // 147456

__global__ __launch_bounds__(256, 1) void gemm_f16_kernel(
    const __half* __restrict__ A, const __half* __restrict__ B,
    const float* __restrict__ bias, __half* __restrict__ C16,
    float* __restrict__ C32)
{
    const uint32_t sb = smem_u32(dynsmem);
    const int tid  = threadIdx.x;
    const int lane = tid & 31;
    const int wid  = tid >> 5;
    const int wm   = wid & 1;
    const int wn   = wid >> 1;
    const int row0 = blockIdx.y * 128;
    const int col0 = blockIdx.x * 256;

    const char* Ab = (const char*)(A + (size_t)row0 * E_DIM);
    const char* Bb = (const char*)(B + (size_t)col0 * E_DIM);

    float acc[4][8][4];
#pragma unroll
    for (int mf = 0; mf < 4; mf++)
#pragma unroll
        for (int nf = 0; nf < 8; nf++)
#pragma unroll
            for (int e = 0; e < 4; e++) acc[mf][nf][e] = 0.f;

    auto load_stage = [&](int kt, int stg) {
        const uint32_t sA = sb + stg * GSTG_B;
        const uint32_t sB = sA + GA_B;
        const size_t koff = (size_t)kt * 128;
#pragma unroll
        for (int it = 0; it < 4; it++) {
            int ch = tid + it * 256;
            int r = ch >> 3, g = ch & 7;
            CP_ASYNC16(sA + r * 128 + SW4(g, r) * 16,
                       Ab + (size_t)r * 4096 + koff + g * 16);
        }
#pragma unroll
        for (int it = 0; it < 8; it++) {
            int ch = tid + it * 256;
            int r = ch >> 3, g = ch & 7;
            CP_ASYNC16(sB + r * 128 + SW4(g, r) * 16,
                       Bb + (size_t)r * 4096 + koff + g * 16);
        }
    };

    load_stage(0, 0); CP_COMMIT();
    load_stage(1, 1); CP_COMMIT();

    const int a_ro = (lane & 7) + ((lane >> 3) & 1) * 8;
    const int a_kh = (lane >> 4) & 1;
    const int b_ro = (lane & 7) + ((lane >> 4) & 1) * 8;
    const int b_kh = (lane >> 3) & 1;

    for (int i = 0; i < GNT; i++) {
        CP_WAIT1();
        __syncthreads();
        const int j = i + 2;
        if (j < GNT) load_stage(j, j % 3);
        CP_COMMIT();

        const uint32_t sA = sb + (i % 3) * GSTG_B;
        const uint32_t sB = sA + GA_B;
#pragma unroll
        for (int s = 0; s < 4; s++) {
            uint32_t a[4][4], b[8][2];
#pragma unroll
            for (int mf = 0; mf < 4; mf++) {
                int r = wm * 64 + mf * 16 + a_ro;
                ldsm_x4(a[mf][0], a[mf][1], a[mf][2], a[mf][3],
                        sA + r * 128 + SW4(2 * s + a_kh, r) * 16);
            }
#pragma unroll
            for (int pj = 0; pj < 4; pj++) {
                int r = wn * 64 + pj * 16 + b_ro;
                uint32_t r0, r1, r2, r3;
                ldsm_x4(r0, r1, r2, r3, sB + r * 128 + SW4(2 * s + b_kh, r) * 16);
                b[2 * pj][0] = r0;     b[2 * pj][1] = r1;
                b[2 * pj + 1][0] = r2; b[2 * pj + 1][1] = r3;
            }
#pragma unroll
            for (int mf = 0; mf < 4; mf++)
#pragma unroll
                for (int nf = 0; nf < 8; nf++)
                    mma_f16(acc[mf][nf], a[mf], b[nf]);
        }
    }

#pragma unroll
    for (int mf = 0; mf < 4; mf++) {
        const int rg = row0 + wm * 64 + mf * 16 + (lane >> 2);
#pragma unroll
        for (int nf = 0; nf < 8; nf++) {
            const int col = col0 + wn * 64 + nf * 8 + (lane & 3) * 2;
            const float b0 = bias[col], b1 = bias[col + 1];
            float v00 = acc[mf][nf][0] + b0, v01 = acc[mf][nf][1] + b1;
            float v10 = acc[mf][nf][2] + b0, v11 = acc[mf][nf][3] + b1;
            if (C16) {
                *(__half2*)&C16[(size_t)rg * E_DIM + col]       = __floats2half2_rn(v00, v01);
                *(__half2*)&C16[(size_t)(rg + 8) * E_DIM + col] = __floats2half2_rn(v10, v11);
            } else {
                *(float2*)&C32[(size_t)rg * E_DIM + col]       = make_float2(v00, v01);
                *(float2*)&C32[(size_t)(rg + 8) * E_DIM + col] = make_float2(v10, v11);
            }
        }
    }
}

// ---------------- mask reduction --------------------------------------------
__global__ void mask_init_kernel() { g_mask_allones = 1; }
__global__ void mask_check_kernel(const int* __restrict__ mask, int n)
{
    int idx = blockIdx.x * blockDim.x + threadIdx.x;
    int stride = gridDim.x * blockDim.x;
    int bad = 0;
    for (int i = idx; i < n; i += stride) bad |= (mask[i] == 0);
    if (bad) atomicAnd(&g_mask_allones, 0);
}

// ======================= FA2 fp16 flash attention ============================
// BM=128 q (8 warps x 16 rows), BN=64 keys/iter, d=128.
// Each warp owns all 64 keys: P stays in registers; softmax fully in-warp.
// smem: Q 32768 | K 2x16384 | V 2x16384  = 98304 B
#define AQ  0
#define AK  32768
#define AV  65536
#define ATT_SMEM 98304

__global__ __launch_bounds__(256, 1) void attn_f16_kernel(const int* __restrict__ mask)
{
    const uint32_t sb = smem_u32(dynsmem);
    const int tid  = threadIdx.x;
    const int lane = tid & 31;
    const int wid  = tid >> 5;
    const int R    = wid * 16;           // warp's q-row base within tile
    const int q0   = blockIdx.x * 128;
    const int nh   = blockIdx.y;
    const int bn   = nh / H_HEADS;
    const int h    = nh % H_HEADS;
    const bool allones = (g_mask_allones != 0);
    const float sc = rsqrtf((float)D_HEAD);

    const char* qg = (const char*)(g_q16 + (size_t)(bn * S_LEN + q0) * E_DIM + h * D_HEAD);
    const char* kg = (const char*)(g_k16 + (size_t)(bn * T_LEN) * E_DIM + h * D_HEAD);
    const char* vg = (const char*)(g_v16 + (size_t)(bn * T_LEN) * E_DIM + h * D_HEAD);

    const int a_ro = (lane & 7) + ((lane >> 3) & 1) * 8;
    const int a_kh = (lane >> 4) & 1;
    const int b_ro = (lane & 7) + ((lane >> 4) & 1) * 8;
    const int b_kh = (lane >> 3) & 1;

    auto load64 = [&](const char* src, uint32_t base) {   // 64x128 fp16
#pragma unroll
        for (int it = 0; it < 4; it++) {
            int ch = tid + it * 256;
            int r = ch >> 4, g = ch & 15;
            CP_ASYNC16(base + r * 256 + SW4(g, r) * 16, src + (size_t)r * 4096 + g * 16);
        }
    };
    // Q: 128x128 fp16
#pragma unroll
    for (int it = 0; it < 8; it++) {
        int ch = tid + it * 256;
        int r = ch >> 4, g = ch & 15;
        CP_ASYNC16(sb + AQ + r * 256 + SW4(g, r) * 16, qg + (size_t)r * 4096 + g * 16);
    }
    load64(kg, sb + AK);
    load64(vg, sb + AV);
    CP_COMMIT();
    CP_WAIT0();
    __syncthreads();

    // preload Q fragments for all 8 k16-steps (stays in regs whole kernel)
    uint32_t aq[8][4];
#pragma unroll
    for (int ks = 0; ks < 8; ks++) {
        int r = R + a_ro;
        ldsm_x4(aq[ks][0], aq[ks][1], aq[ks][2], aq[ks][3],
                sb + AQ + r * 256 + SW4(2 * ks + a_kh, r) * 16);
    }

    float o[16][4];
    float m0 = -INFINITY, m1 = -INFINITY, l0 = 0.f, l1 = 0.f;
#pragma unroll
    for (int nf = 0; nf < 16; nf++)
#pragma unroll
        for (int e = 0; e < 4; e++) o[nf][e] = 0.f;

    const int nb = T_LEN / 64;
    for (int j = 0; j < nb; j++) {
        const int b = j & 1;
        if (j + 1 < nb) {
            load64(kg + (size_t)(j + 1) * 64 * 4096, sb + AK + (1 - b) * 16384);
            load64(vg + (size_t)(j + 1) * 64 * 4096, sb + AV + (1 - b) * 16384);
            CP_COMMIT();
        }
        const uint32_t sK = sb + AK + b * 16384;
        const uint32_t sV = sb + AV + b * 16384;

        // ---- S = Q K^T : warp 16q x 64keys, 8 k16-steps
        float s[8][4];
#pragma unroll
        for (int nf = 0; nf < 8; nf++)
#pragma unroll
            for (int e = 0; e < 4; e++) s[nf][e] = 0.f;

#pragma unroll
        for (int ks = 0; ks < 8; ks++) {
            uint32_t bfr[8][2];
#pragma unroll
            for (int pj = 0; pj < 4; pj++) {
                int r = pj * 16 + b_ro;
                uint32_t r0, r1, r2, r3;
                ldsm_x4(r0, r1, r2, r3, sK + r * 256 + SW4(2 * ks + b_kh, r) * 16);
                bfr[2 * pj][0] = r0;     bfr[2 * pj][1] = r1;
                bfr[2 * pj + 1][0] = r2; bfr[2 * pj + 1][1] = r3;
            }
#pragma unroll
            for (int nf = 0; nf < 8; nf++)
                mma_f16(s[nf], aq[ks], bfr[nf]);
        }

#pragma unroll
        for (int nf = 0; nf < 8; nf++)
#pragma unroll
            for (int e = 0; e < 4; e++) s[nf][e] *= sc;

        if (!allones) {
#pragma unroll
            for (int nf = 0; nf < 8; nf++)
#pragma unroll
                for (int e = 0; e < 4; e++) {
                    int r = R + (lane >> 2) + (e >> 1) * 8;
                    int c = nf * 8 + (lane & 3) * 2 + (e & 1);
                    if (mask[(size_t)(j * 64 + c) * S_LEN + q0 + r] == 0)
                        s[nf][e] = -INFINITY;
                }
        }

        // ---- in-warp softmax (rows r0 = R+(lane>>2), r1 = +8)
        float mx0 = s[0][0], mx1 = s[0][2];
#pragma unroll
        for (int nf = 0; nf < 8; nf++) {
            mx0 = fmaxf(mx0, fmaxf(s[nf][0], s[nf][1]));
            mx1 = fmaxf(mx1, fmaxf(s[nf][2], s[nf][3]));
        }
        mx0 = fmaxf(mx0, __shfl_xor_sync(0xffffffffu, mx0, 1));
        mx0 = fmaxf(mx0, __shfl_xor_sync(0xffffffffu, mx0, 2));
        mx1 = fmaxf(mx1, __shfl_xor_sync(0xffffffffu, mx1, 1));
        mx1 = fmaxf(mx1, __shfl_xor_sync(0xffffffffu, mx1, 2));

        float mn0 = fmaxf(m0, mx0), mn1 = fmaxf(m1, mx1);
        float al0 = (m0 == mn0) ? 1.f : __expf(m0 - mn0);
        float al1 = (m1 == mn1) ? 1.f : __expf(m1 - mn1);
        m0 = mn0; m1 = mn1;

        // exp + P pack (register A-fragments for PV) + partial sums
        uint32_t ap[4][4];
        float ps0 = 0.f, ps1 = 0.f;
#pragma unroll
        for (int nf = 0; nf < 8; nf++) {
            float e0 = __expf(s[nf][0] - m0);
            float e1 = __expf(s[nf][1] - m0);
            float e2 = __expf(s[nf][2] - m1);
            float e3 = __expf(s[nf][3] - m1);
            ps0 += e0 + e1; ps1 += e2 + e3;
            int ks = nf >> 1, hi = nf & 1;
            ap[ks][hi * 2]     = packh2(e0, e1);
            ap[ks][hi * 2 + 1] = packh2(e2, e3);
        }
        ps0 += __shfl_xor_sync(0xffffffffu, ps0, 1);
        ps0 += __shfl_xor_sync(0xffffffffu, ps0, 2);
        ps1 += __shfl_xor_sync(0xffffffffu, ps1, 1);
        ps1 += __shfl_xor_sync(0xffffffffu, ps1, 2);
        l0 = l0 * al0 + ps0;
        l1 = l1 * al1 + ps1;

#pragma unroll
        for (int nf = 0; nf < 16; nf++) {
            o[nf][0] *= al0; o[nf][1] *= al0;
            o[nf][2] *= al1; o[nf][3] *= al1;
        }

        // ---- O += P V : warp 16q x 128d, 4 k16-steps; V via ldmatrix.trans
#pragma unroll
        for (int ks = 0; ks < 4; ks++) {
            uint32_t bv[16][2];
#pragma unroll
            for (int pv = 0; pv < 8; pv++) {
                int r = ks * 16 + (lane & 15);
                int g = pv * 2 + ((lane >> 4) & 1);
                uint32_t r0, r1, r2, r3;
                ldsm_x4_t(r0, r1, r2, r3, sV + r * 256 + SW4(g, r) * 16);
                bv[2 * pv][0] = r0;     bv[2 * pv][1] = r1;
                bv[2 * pv + 1][0] = r2; bv[2 * pv + 1][1] = r3;
            }
#pragma unroll
            for (int nf = 0; nf < 16; nf++)
                mma_f16(o[nf], ap[ks], bv[nf]);
        }

        if (j + 1 < nb) CP_WAIT0();
        __syncthreads();   // all warps done reading buf b before it's refilled
    }

    __half* cb = g_ctx16 + (size_t)(bn * S_LEN + q0) * E_DIM + h * D_HEAD;
    const int R0 = R + (lane >> 2);
    const float i0 = 1.f / l0, i1 = 1.f / l1;
#pragma unroll
    for (int nf = 0; nf < 16; nf++) {
        int c = nf * 8 + (lane & 3) * 2;
        *(__half2*)&cb[(size_t)R0 * E_DIM + c] =
            __floats2half2_rn(o[nf][0] * i0, o[nf][1] * i0);
        *(__half2*)&cb[(size_t)(R0 + 8) * E_DIM + c] =
            __floats2half2_rn(o[nf][2] * i1, o[nf][3] * i1);
    }
}

// ---------------- launch -----------------------------------------------------
extern "C" void kernel_launch(void* const* d_in, const int* in_sizes, int n_in,
                              void* d_out, int out_size)
{
    const float* query = (const float*)d_in[0];
    const float* key   = (const float*)d_in[1];
    const float* value = (const float*)d_in[2];
    const int*   mask  = (const int*)  d_in[3];
    const float* Wq    = (const float*)d_in[4];
    const float* bq    = (const float*)d_in[5];
    const float* Wk    = (const float*)d_in[6];
    const float* bk    = (const float*)d_in[7];
    const float* Wv    = (const float*)d_in[8];
    const float* bv    = (const float*)d_in[9];
    const float* Wp    = (const float*)d_in[10];
    const float* bp    = (const float*)d_in[11];
    float* out = (float*)d_out;

    __half *qs, *ks, *vs, *cs, *ra, *rw;
    cudaGetSymbolAddress((void**)&qs, g_q16);
    cudaGetSymbolAddress((void**)&ks, g_k16);
    cudaGetSymbolAddress((void**)&vs, g_v16);
    cudaGetSymbolAddress((void**)&cs, g_ctx16);
    cudaGetSymbolAddress((void**)&ra, g_ra16);
    cudaGetSymbolAddress((void**)&rw, g_rw16);

    cudaFuncSetAttribute(gemm_f16_kernel,
                         cudaFuncAttributeMaxDynamicSharedMemorySize, GEMM_SMEM);
    cudaFuncSetAttribute(attn_f16_kernel,
                         cudaFuncAttributeMaxDynamicSharedMemorySize, ATT_SMEM);

    const int nA4 = M_TOK * 512;
    const int nW4 = E_DIM * 512;
    const size_t ASZ = (size_t)M_TOK * E_DIM;   // halves per activation buf
    const size_t WSZ = (size_t)E_DIM * E_DIM;
    dim3 ggrid(E_DIM / 256, M_TOK / 128);       // (8, 64)

    // all converts up front (independent)
    cvt_f16_kernel<<<nA4 / 256, 256>>>(query, ra,            nA4);
    cvt_f16_kernel<<<nA4 / 256, 256>>>(key,   ra + ASZ,      nA4);
    cvt_f16_kernel<<<nA4 / 256, 256>>>(value, ra + 2 * ASZ,  nA4);
    cvt_f16_kernel<<<nW4 / 256, 256>>>(Wq,    rw,            nW4);
    cvt_f16_kernel<<<nW4 / 256, 256>>>(Wk,    rw + WSZ,      nW4);
    cvt_f16_kernel<<<nW4 / 256, 256>>>(Wv,    rw + 2 * WSZ,  nW4);
    cvt_f16_kernel<<<nW4 / 256, 256>>>(Wp,    rw + 3 * WSZ,  nW4);
    mask_init_kernel<<<1, 1>>>();
    mask_check_kernel<<<1024, 256>>>(mask, T_LEN * S_LEN);

    gemm_f16_kernel<<<ggrid, 256, GEMM_SMEM>>>(ra,           rw,           bq, qs, nullptr);
    gemm_f16_kernel<<<ggrid, 256, GEMM_SMEM>>>(ra + ASZ,     rw + WSZ,     bk, ks, nullptr);
    gemm_f16_kernel<<<ggrid, 256, GEMM_SMEM>>>(ra + 2 * ASZ, rw + 2 * WSZ, bv, vs, nullptr);

    attn_f16_kernel<<<dim3(S_LEN / 128, N_BATCH * H_HEADS), 256, ATT_SMEM>>>(mask);

    gemm_f16_kernel<<<ggrid, 256, GEMM_SMEM>>>(cs, rw + 3 * WSZ, bp, nullptr, out);
}

// round 11
// speedup vs baseline: 10.6212x; 1.0011x over previous
#include <cuda_runtime.h>
#include <cuda_fp16.h>
#include <math.h>
#include <cstdint>

#define E_DIM   2048
#define H_HEADS 16
#define D_HEAD  128
#define N_BATCH 4
#define S_LEN   2048
#define T_LEN   2048
#define M_TOK   (N_BATCH * S_LEN)

// ---------------- scratch ----------------------------------------------------
__device__ __half g_q16[16777216];
__device__ __half g_k16[16777216];
__device__ __half g_v16[16777216];
__device__ __half g_ctx16[16777216];
__device__ __half g_ra16[50331648];   // 3 activation buffers
__device__ __half g_rw16[16777216];   // 4 weight buffers
__device__ int    g_mask_allones;

extern __shared__ char dynsmem[];

// ======================= helpers =============================================
__device__ __forceinline__ uint32_t smem_u32(const void* p) {
    uint32_t a;
    asm("{ .reg .u64 t; cvta.to.shared.u64 t, %1; cvt.u32.u64 %0, t; }"
        : "=r"(a) : "l"(p));
    return a;
}
__device__ __forceinline__ uint32_t packh2(float a, float b) {
    __half2 h = __floats2half2_rn(a, b);
    return *reinterpret_cast<uint32_t*>(&h);
}
__device__ __forceinline__ float ex2(float x) {
    float y;
    asm("ex2.approx.f32 %0, %1;" : "=f"(y) : "f"(x));
    return y;
}
#define CP_ASYNC16(dst, src) asm volatile("cp.async.cg.shared.global [%0], [%1], 16;" :: "r"(dst), "l"(src))
#define CP_COMMIT()          asm volatile("cp.async.commit_group;" ::: "memory")
#define CP_WAIT0()           asm volatile("cp.async.wait_group 0;" ::: "memory")
#define CP_WAIT1()           asm volatile("cp.async.wait_group 1;" ::: "memory")

__device__ __forceinline__ void ldsm_x4(uint32_t& r0, uint32_t& r1,
                                        uint32_t& r2, uint32_t& r3, uint32_t a) {
    asm volatile("ldmatrix.sync.aligned.m8n8.x4.shared.b16 {%0,%1,%2,%3}, [%4];"
                 : "=r"(r0), "=r"(r1), "=r"(r2), "=r"(r3) : "r"(a));
}
__device__ __forceinline__ void ldsm_x4_t(uint32_t& r0, uint32_t& r1,
                                          uint32_t& r2, uint32_t& r3, uint32_t a) {
    asm volatile("ldmatrix.sync.aligned.m8n8.x4.trans.shared.b16 {%0,%1,%2,%3}, [%4];"
                 : "=r"(r0), "=r"(r1), "=r"(r2), "=r"(r3) : "r"(a));
}
__device__ __forceinline__ void mma_f16(float* d, const uint32_t* a, const uint32_t* b) {
    asm volatile(
        "mma.sync.aligned.m16n8k16.row.col.f32.f16.f16.f32 "
        "{%0,%1,%2,%3}, {%4,%5,%6,%7}, {%8,%9}, {%0,%1,%2,%3};"
        : "+f"(d[0]), "+f"(d[1]), "+f"(d[2]), "+f"(d[3])
        : "r"(a[0]), "r"(a[1]), "r"(a[2]), "r"(a[3]), "r"(b[0]), "r"(b[1]));
}
#define SW4(g, row) (((g) & 24) | (((g) & 7) ^ ((row) & 7)))

// ======================= convert fp32 -> fp16(RN) ============================
__global__ __launch_bounds__(256) void cvt_f16_kernel(
    const float* __restrict__ src, __half* __restrict__ dst, int n4)
{
    int idx = blockIdx.x * blockDim.x + threadIdx.x;
    if (idx >= n4) return;
    float4 v = ((const float4*)src)[idx];
    ((__half2*)dst)[idx * 2]     = __floats2half2_rn(v.x, v.y);
    ((__half2*)dst)[idx * 2 + 1] = __floats2half2_rn(v.z, v.w);
}

// ======================= fp16 GEMM: C = (A@B^T + bias) * oscale ==============
#define GNT 32
#define GA_B (128 * 128)
#define GB_B (256 * 128)
#define GSTG_B (GA_B + GB_B)
#define GEMM_SMEM (3 * GSTG_B)       // 147456

__global__ __launch_bounds__(256, 1) void gemm_f16_kernel(
    const __half* __restrict__ A, const __half* __restrict__ B,
    const float* __restrict__ bias, __half* __restrict__ C16,
    float* __restrict__ C32, float oscale)
{
    const uint32_t sb = smem_u32(dynsmem);
    const int tid  = threadIdx.x;
    const int lane = tid & 31;
    const int wid  = tid >> 5;
    const int wm   = wid & 1;
    const int wn   = wid >> 1;
    const int row0 = blockIdx.y * 128;
    const int col0 = blockIdx.x * 256;

    const char* Ab = (const char*)(A + (size_t)row0 * E_DIM);
    const char* Bb = (const char*)(B + (size_t)col0 * E_DIM);

    float acc[4][8][4];
#pragma unroll
    for (int mf = 0; mf < 4; mf++)
#pragma unroll
        for (int nf = 0; nf < 8; nf++)
#pragma unroll
            for (int e = 0; e < 4; e++) acc[mf][nf][e] = 0.f;

    auto load_stage = [&](int kt, int stg) {
        const uint32_t sA = sb + stg * GSTG_B;
        const uint32_t sB = sA + GA_B;
        const size_t koff = (size_t)kt * 128;
#pragma unroll
        for (int it = 0; it < 4; it++) {
            int ch = tid + it * 256;
            int r = ch >> 3, g = ch & 7;
            CP_ASYNC16(sA + r * 128 + SW4(g, r) * 16,
                       Ab + (size_t)r * 4096 + koff + g * 16);
        }
#pragma unroll
        for (int it = 0; it < 8; it++) {
            int ch = tid + it * 256;
            int r = ch >> 3, g = ch & 7;
            CP_ASYNC16(sB + r * 128 + SW4(g, r) * 16,
                       Bb + (size_t)r * 4096 + koff + g * 16);
        }
    };

    load_stage(0, 0); CP_COMMIT();
    load_stage(1, 1); CP_COMMIT();

    const int a_ro = (lane & 7) + ((lane >> 3) & 1) * 8;
    const int a_kh = (lane >> 4) & 1;
    const int b_ro = (lane & 7) + ((lane >> 4) & 1) * 8;
    const int b_kh = (lane >> 3) & 1;

    for (int i = 0; i < GNT; i++) {
        CP_WAIT1();
        __syncthreads();
        const int j = i + 2;
        if (j < GNT) load_stage(j, j % 3);
        CP_COMMIT();

        const uint32_t sA = sb + (i % 3) * GSTG_B;
        const uint32_t sB = sA + GA_B;
#pragma unroll
        for (int s = 0; s < 4; s++) {
            uint32_t a[4][4], b[8][2];
#pragma unroll
            for (int mf = 0; mf < 4; mf++) {
                int r = wm * 64 + mf * 16 + a_ro;
                ldsm_x4(a[mf][0], a[mf][1], a[mf][2], a[mf][3],
                        sA + r * 128 + SW4(2 * s + a_kh, r) * 16);
            }
#pragma unroll
            for (int pj = 0; pj < 4; pj++) {
                int r = wn * 64 + pj * 16 + b_ro;
                uint32_t r0, r1, r2, r3;
                ldsm_x4(r0, r1, r2, r3, sB + r * 128 + SW4(2 * s + b_kh, r) * 16);
                b[2 * pj][0] = r0;     b[2 * pj][1] = r1;
                b[2 * pj + 1][0] = r2; b[2 * pj + 1][1] = r3;
            }
#pragma unroll
            for (int mf = 0; mf < 4; mf++)
#pragma unroll
                for (int nf = 0; nf < 8; nf++)
                    mma_f16(acc[mf][nf], a[mf], b[nf]);
        }
    }

#pragma unroll
    for (int mf = 0; mf < 4; mf++) {
        const int rg = row0 + wm * 64 + mf * 16 + (lane >> 2);
#pragma unroll
        for (int nf = 0; nf < 8; nf++) {
            const int col = col0 + wn * 64 + nf * 8 + (lane & 3) * 2;
            const float b0 = bias[col], b1 = bias[col + 1];
            float v00 = (acc[mf][nf][0] + b0) * oscale;
            float v01 = (acc[mf][nf][1] + b1) * oscale;
            float v10 = (acc[mf][nf][2] + b0) * oscale;
            float v11 = (acc[mf][nf][3] + b1) * oscale;
            if (C16) {
                *(__half2*)&C16[(size_t)rg * E_DIM + col]       = __floats2half2_rn(v00, v01);
                *(__half2*)&C16[(size_t)(rg + 8) * E_DIM + col] = __floats2half2_rn(v10, v11);
            } else {
                *(float2*)&C32[(size_t)rg * E_DIM + col]       = make_float2(v00, v01);
                *(float2*)&C32[(size_t)(rg + 8) * E_DIM + col] = make_float2(v10, v11);
            }
        }
    }
}

// ---------------- mask reduction --------------------------------------------
__global__ void mask_init_kernel() { g_mask_allones = 1; }
__global__ void mask_check_kernel(const int* __restrict__ mask, int n)
{
    int idx = blockIdx.x * blockDim.x + threadIdx.x;
    int stride = gridDim.x * blockDim.x;
    int bad = 0;
    for (int i = idx; i < n; i += stride) bad |= (mask[i] == 0);
    if (bad) atomicAnd(&g_mask_allones, 0);
}

// ======================= FA2 fp16 flash attention (BM=64, 2 CTA/SM) ==========
// 64 q (4 warps x 16 rows), BN=64 keys/iter, d=128. Q pre-scaled by log2e/sqrt(d)
// in projection epilogue -> softmax uses ex2 directly.
// smem: Q 16384 | K 2x16384 | V 2x16384 = 81920 B  (2 CTAs/SM)
#define AQ  0
#define AK  16384
#define AV  49152
#define ATT_SMEM 81920

__global__ __launch_bounds__(128, 2) void attn_f16_kernel(const int* __restrict__ mask)
{
    const uint32_t sb = smem_u32(dynsmem);
    const int tid  = threadIdx.x;
    const int lane = tid & 31;
    const int wid  = tid >> 5;
    const int R    = wid * 16;
    const int q0   = blockIdx.x * 64;
    const int nh   = blockIdx.y;
    const int bn   = nh / H_HEADS;
    const int h    = nh % H_HEADS;
    const bool allones = (g_mask_allones != 0);

    const char* qg = (const char*)(g_q16 + (size_t)(bn * S_LEN + q0) * E_DIM + h * D_HEAD);
    const char* kg = (const char*)(g_k16 + (size_t)(bn * T_LEN) * E_DIM + h * D_HEAD);
    const char* vg = (const char*)(g_v16 + (size_t)(bn * T_LEN) * E_DIM + h * D_HEAD);

    const int a_ro = (lane & 7) + ((lane >> 3) & 1) * 8;
    const int a_kh = (lane >> 4) & 1;
    const int b_ro = (lane & 7) + ((lane >> 4) & 1) * 8;
    const int b_kh = (lane >> 3) & 1;

    auto load64 = [&](const char* src, uint32_t base) {   // 64x128 fp16, 1024 chunks
#pragma unroll
        for (int it = 0; it < 8; it++) {
            int ch = tid + it * 128;
            int r = ch >> 4, g = ch & 15;
            CP_ASYNC16(base + r * 256 + SW4(g, r) * 16, src + (size_t)r * 4096 + g * 16);
        }
    };
    load64(qg, sb + AQ);
    load64(kg, sb + AK);
    load64(vg, sb + AV);
    CP_COMMIT();
    CP_WAIT0();
    __syncthreads();

    // preload Q fragments (pre-scaled by log2e/sqrt(d) at projection time)
    uint32_t aq[8][4];
#pragma unroll
    for (int ks = 0; ks < 8; ks++) {
        int r = R + a_ro;
        ldsm_x4(aq[ks][0], aq[ks][1], aq[ks][2], aq[ks][3],
                sb + AQ + r * 256 + SW4(2 * ks + a_kh, r) * 16);
    }

    float o[16][4];
    float m0 = -INFINITY, m1 = -INFINITY, l0 = 0.f, l1 = 0.f;
#pragma unroll
    for (int nf = 0; nf < 16; nf++)
#pragma unroll
        for (int e = 0; e < 4; e++) o[nf][e] = 0.f;

    const int nb = T_LEN / 64;
    for (int j = 0; j < nb; j++) {
        const int b = j & 1;
        if (j + 1 < nb) {
            load64(kg + (size_t)(j + 1) * 64 * 4096, sb + AK + (1 - b) * 16384);
            load64(vg + (size_t)(j + 1) * 64 * 4096, sb + AV + (1 - b) * 16384);
            CP_COMMIT();
        }
        const uint32_t sK = sb + AK + b * 16384;
        const uint32_t sV = sb + AV + b * 16384;

        // ---- S = Q K^T (warp: 16q x 64keys), 8 k16-steps; s already in log2 units
        float s[8][4];
#pragma unroll
        for (int nf = 0; nf < 8; nf++)
#pragma unroll
            for (int e = 0; e < 4; e++) s[nf][e] = 0.f;

#pragma unroll
        for (int ks = 0; ks < 8; ks++) {
            uint32_t bfr[8][2];
#pragma unroll
            for (int pj = 0; pj < 4; pj++) {
                int r = pj * 16 + b_ro;
                uint32_t r0, r1, r2, r3;
                ldsm_x4(r0, r1, r2, r3, sK + r * 256 + SW4(2 * ks + b_kh, r) * 16);
                bfr[2 * pj][0] = r0;     bfr[2 * pj][1] = r1;
                bfr[2 * pj + 1][0] = r2; bfr[2 * pj + 1][1] = r3;
            }
#pragma unroll
            for (int nf = 0; nf < 8; nf++)
                mma_f16(s[nf], aq[ks], bfr[nf]);
        }

        if (!allones) {
#pragma unroll
            for (int nf = 0; nf < 8; nf++)
#pragma unroll
                for (int e = 0; e < 4; e++) {
                    int r = R + (lane >> 2) + (e >> 1) * 8;
                    int c = nf * 8 + (lane & 3) * 2 + (e & 1);
                    if (mask[(size_t)(j * 64 + c) * S_LEN + q0 + r] == 0)
                        s[nf][e] = -INFINITY;
                }
        }

        // ---- in-warp softmax (base-2 domain)
        float mx0 = s[0][0], mx1 = s[0][2];
#pragma unroll
        for (int nf = 0; nf < 8; nf++) {
            mx0 = fmaxf(mx0, fmaxf(s[nf][0], s[nf][1]));
            mx1 = fmaxf(mx1, fmaxf(s[nf][2], s[nf][3]));
        }
        mx0 = fmaxf(mx0, __shfl_xor_sync(0xffffffffu, mx0, 1));
        mx0 = fmaxf(mx0, __shfl_xor_sync(0xffffffffu, mx0, 2));
        mx1 = fmaxf(mx1, __shfl_xor_sync(0xffffffffu, mx1, 1));
        mx1 = fmaxf(mx1, __shfl_xor_sync(0xffffffffu, mx1, 2));

        float mn0 = fmaxf(m0, mx0), mn1 = fmaxf(m1, mx1);
        float al0 = (m0 == mn0) ? 1.f : ex2(m0 - mn0);
        float al1 = (m1 == mn1) ? 1.f : ex2(m1 - mn1);
        m0 = mn0; m1 = mn1;

        uint32_t ap[4][4];
        float ps0 = 0.f, ps1 = 0.f;
#pragma unroll
        for (int nf = 0; nf < 8; nf++) {
            float e0 = ex2(s[nf][0] - m0);
            float e1 = ex2(s[nf][1] - m0);
            float e2 = ex2(s[nf][2] - m1);
            float e3 = ex2(s[nf][3] - m1);
            ps0 += e0 + e1; ps1 += e2 + e3;
            int ks = nf >> 1, hi = nf & 1;
            ap[ks][hi * 2]     = packh2(e0, e1);
            ap[ks][hi * 2 + 1] = packh2(e2, e3);
        }
        ps0 += __shfl_xor_sync(0xffffffffu, ps0, 1);
        ps0 += __shfl_xor_sync(0xffffffffu, ps0, 2);
        ps1 += __shfl_xor_sync(0xffffffffu, ps1, 1);
        ps1 += __shfl_xor_sync(0xffffffffu, ps1, 2);
        l0 = l0 * al0 + ps0;
        l1 = l1 * al1 + ps1;

        if (al0 != 1.f || al1 != 1.f) {
#pragma unroll
            for (int nf = 0; nf < 16; nf++) {
                o[nf][0] *= al0; o[nf][1] *= al0;
                o[nf][2] *= al1; o[nf][3] *= al1;
            }
        }

        // ---- O += P V (warp: 16q x 128d), 4 k16-steps; V via ldmatrix.trans
#pragma unroll
        for (int ks = 0; ks < 4; ks++) {
            uint32_t bv[16][2];
#pragma unroll
            for (int pv = 0; pv < 8; pv++) {
                int r = ks * 16 + (lane & 15);
                int g = pv * 2 + ((lane >> 4) & 1);
                uint32_t r0, r1, r2, r3;
                ldsm_x4_t(r0, r1, r2, r3, sV + r * 256 + SW4(g, r) * 16);
                bv[2 * pv][0] = r0;     bv[2 * pv][1] = r1;
                bv[2 * pv + 1][0] = r2; bv[2 * pv + 1][1] = r3;
            }
#pragma unroll
            for (int nf = 0; nf < 16; nf++)
                mma_f16(o[nf], ap[ks], bv[nf]);
        }

        if (j + 1 < nb) CP_WAIT0();
        __syncthreads();
    }

    __half* cb = g_ctx16 + (size_t)(bn * S_LEN + q0) * E_DIM + h * D_HEAD;
    const int R0 = R + (lane >> 2);
    const float i0 = 1.f / l0, i1 = 1.f / l1;
#pragma unroll
    for (int nf = 0; nf < 16; nf++) {
        int c = nf * 8 + (lane & 3) * 2;
        *(__half2*)&cb[(size_t)R0 * E_DIM + c] =
            __floats2half2_rn(o[nf][0] * i0, o[nf][1] * i0);
        *(__half2*)&cb[(size_t)(R0 + 8) * E_DIM + c] =
            __floats2half2_rn(o[nf][2] * i1, o[nf][3] * i1);
    }
}

// ---------------- launch -----------------------------------------------------
extern "C" void kernel_launch(void* const* d_in, const int* in_sizes, int n_in,
                              void* d_out, int out_size)
{
    const float* query = (const float*)d_in[0];
    const float* key   = (const float*)d_in[1];
    const float* value = (const float*)d_in[2];
    const int*   mask  = (const int*)  d_in[3];
    const float* Wq    = (const float*)d_in[4];
    const float* bq    = (const float*)d_in[5];
    const float* Wk    = (const float*)d_in[6];
    const float* bk    = (const float*)d_in[7];
    const float* Wv    = (const float*)d_in[8];
    const float* bv    = (const float*)d_in[9];
    const float* Wp    = (const float*)d_in[10];
    const float* bp    = (const float*)d_in[11];
    float* out = (float*)d_out;

    __half *qs, *ks, *vs, *cs, *ra, *rw;
    cudaGetSymbolAddress((void**)&qs, g_q16);
    cudaGetSymbolAddress((void**)&ks, g_k16);
    cudaGetSymbolAddress((void**)&vs, g_v16);
    cudaGetSymbolAddress((void**)&cs, g_ctx16);
    cudaGetSymbolAddress((void**)&ra, g_ra16);
    cudaGetSymbolAddress((void**)&rw, g_rw16);

    cudaFuncSetAttribute(gemm_f16_kernel,
                         cudaFuncAttributeMaxDynamicSharedMemorySize, GEMM_SMEM);
    cudaFuncSetAttribute(attn_f16_kernel,
                         cudaFuncAttributeMaxDynamicSharedMemorySize, ATT_SMEM);

    const int nA4 = M_TOK * 512;
    const int nW4 = E_DIM * 512;
    const size_t ASZ = (size_t)M_TOK * E_DIM;
    const size_t WSZ = (size_t)E_DIM * E_DIM;
    dim3 ggrid(E_DIM / 256, M_TOK / 128);   // (8, 64)

    // log2(e) / sqrt(d): folded into Q projection -> attention uses ex2
    const float qscale = 1.4426950408889634f / sqrtf((float)D_HEAD);

    cvt_f16_kernel<<<nA4 / 256, 256>>>(query, ra,            nA4);
    cvt_f16_kernel<<<nA4 / 256, 256>>>(key,   ra + ASZ,      nA4);
    cvt_f16_kernel<<<nA4 / 256, 256>>>(value, ra + 2 * ASZ,  nA4);
    cvt_f16_kernel<<<nW4 / 256, 256>>>(Wq,    rw,            nW4);
    cvt_f16_kernel<<<nW4 / 256, 256>>>(Wk,    rw + WSZ,      nW4);
    cvt_f16_kernel<<<nW4 / 256, 256>>>(Wv,    rw + 2 * WSZ,  nW4);
    cvt_f16_kernel<<<nW4 / 256, 256>>>(Wp,    rw + 3 * WSZ,  nW4);
    mask_init_kernel<<<1, 1>>>();
    mask_check_kernel<<<1024, 256>>>(mask, T_LEN * S_LEN);

    gemm_f16_kernel<<<ggrid, 256, GEMM_SMEM>>>(ra,           rw,           bq, qs, nullptr, qscale);
    gemm_f16_kernel<<<ggrid, 256, GEMM_SMEM>>>(ra + ASZ,     rw + WSZ,     bk, ks, nullptr, 1.f);
    gemm_f16_kernel<<<ggrid, 256, GEMM_SMEM>>>(ra + 2 * ASZ, rw + 2 * WSZ, bv, vs, nullptr, 1.f);

    attn_f16_kernel<<<dim3(S_LEN / 64, N_BATCH * H_HEADS), 128, ATT_SMEM>>>(mask);

    gemm_f16_kernel<<<ggrid, 256, GEMM_SMEM>>>(cs, rw + 3 * WSZ, bp, nullptr, out, 1.f);
}

// round 12
// speedup vs baseline: 10.8543x; 1.0220x over previous
#include <cuda_runtime.h>
#include <cuda_fp16.h>
#include <math.h>
#include <cstdint>

#define E_DIM   2048
#define H_HEADS 16
#define D_HEAD  128
#define N_BATCH 4
#define S_LEN   2048
#define T_LEN   2048
#define M_TOK   (N_BATCH * S_LEN)

// ---------------- scratch ----------------------------------------------------
__device__ __half g_q16[16777216];
__device__ __half g_k16[16777216];
__device__ __half g_v16[16777216];
__device__ __half g_ctx16[16777216];
__device__ __half g_ra16[50331648];
__device__ __half g_rw16[16777216];
__device__ int    g_mask_allones;

extern __shared__ char dynsmem[];

// ======================= helpers =============================================
__device__ __forceinline__ uint32_t smem_u32(const void* p) {
    uint32_t a;
    asm("{ .reg .u64 t; cvta.to.shared.u64 t, %1; cvt.u32.u64 %0, t; }"
        : "=r"(a) : "l"(p));
    return a;
}
__device__ __forceinline__ uint32_t packh2(float a, float b) {
    __half2 h = __floats2half2_rn(a, b);
    return *reinterpret_cast<uint32_t*>(&h);
}
__device__ __forceinline__ float ex2(float x) {
    float y;
    asm("ex2.approx.f32 %0, %1;" : "=f"(y) : "f"(x));
    return y;
}
#define CP_ASYNC16(dst, src) asm volatile("cp.async.cg.shared.global [%0], [%1], 16;" :: "r"(dst), "l"(src))
#define CP_COMMIT()          asm volatile("cp.async.commit_group;" ::: "memory")
#define CP_WAIT0()           asm volatile("cp.async.wait_group 0;" ::: "memory")
#define CP_WAIT1()           asm volatile("cp.async.wait_group 1;" ::: "memory")

__device__ __forceinline__ void ldsm_x4(uint32_t& r0, uint32_t& r1,
                                        uint32_t& r2, uint32_t& r3, uint32_t a) {
    asm volatile("ldmatrix.sync.aligned.m8n8.x4.shared.b16 {%0,%1,%2,%3}, [%4];"
                 : "=r"(r0), "=r"(r1), "=r"(r2), "=r"(r3) : "r"(a));
}
__device__ __forceinline__ void ldsm_x4_t(uint32_t& r0, uint32_t& r1,
                                          uint32_t& r2, uint32_t& r3, uint32_t a) {
    asm volatile("ldmatrix.sync.aligned.m8n8.x4.trans.shared.b16 {%0,%1,%2,%3}, [%4];"
                 : "=r"(r0), "=r"(r1), "=r"(r2), "=r"(r3) : "r"(a));
}
__device__ __forceinline__ void mma_f16(float* d, const uint32_t* a, const uint32_t* b) {
    asm volatile(
        "mma.sync.aligned.m16n8k16.row.col.f32.f16.f16.f32 "
        "{%0,%1,%2,%3}, {%4,%5,%6,%7}, {%8,%9}, {%0,%1,%2,%3};"
        : "+f"(d[0]), "+f"(d[1]), "+f"(d[2]), "+f"(d[3])
        : "r"(a[0]), "r"(a[1]), "r"(a[2]), "r"(a[3]), "r"(b[0]), "r"(b[1]));
}
#define SW4(g, row) (((g) & 24) | (((g) & 7) ^ ((row) & 7)))

// ======================= convert fp32 -> fp16(RN) ============================
__global__ __launch_bounds__(256) void cvt_f16_kernel(
    const float* __restrict__ src, __half* __restrict__ dst, int n4)
{
    int idx = blockIdx.x * blockDim.x + threadIdx.x;
    if (idx >= n4) return;
    float4 v = ((const float4*)src)[idx];
    ((__half2*)dst)[idx * 2]     = __floats2half2_rn(v.x, v.y);
    ((__half2*)dst)[idx * 2 + 1] = __floats2half2_rn(v.z, v.w);
}

// ======================= fp16 GEMM: C = (A@B^T + bias) * oscale ==============
#define GNT 32
#define GA_B (128 * 128)
#define GB_B (256 * 128)
#define GSTG_B (GA_B + GB_B)
#define GEMM_SMEM (3 * GSTG_B)       // 147456

__global__ __launch_bounds__(256, 1) void gemm_f16_kernel(
    const __half* __restrict__ A, const __half* __restrict__ B,
    const float* __restrict__ bias, __half* __restrict__ C16,
    float* __restrict__ C32, float oscale)
{
    const uint32_t sb = smem_u32(dynsmem);
    const int tid  = threadIdx.x;
    const int lane = tid & 31;
    const int wid  = tid >> 5;
    const int wm   = wid & 1;
    const int wn   = wid >> 1;
    const int row0 = blockIdx.y * 128;
    const int col0 = blockIdx.x * 256;

    const char* Ab = (const char*)(A + (size_t)row0 * E_DIM);
    const char* Bb = (const char*)(B + (size_t)col0 * E_DIM);

    float acc[4][8][4];
#pragma unroll
    for (int mf = 0; mf < 4; mf++)
#pragma unroll
        for (int nf = 0; nf < 8; nf++)
#pragma unroll
            for (int e = 0; e < 4; e++) acc[mf][nf][e] = 0.f;

    auto load_stage = [&](int kt, int stg) {
        const uint32_t sA = sb + stg * GSTG_B;
        const uint32_t sB = sA + GA_B;
        const size_t koff = (size_t)kt * 128;
#pragma unroll
        for (int it = 0; it < 4; it++) {
            int ch = tid + it * 256;
            int r = ch >> 3, g = ch & 7;
            CP_ASYNC16(sA + r * 128 + SW4(g, r) * 16,
                       Ab + (size_t)r * 4096 + koff + g * 16);
        }
#pragma unroll
        for (int it = 0; it < 8; it++) {
            int ch = tid + it * 256;
            int r = ch >> 3, g = ch & 7;
            CP_ASYNC16(sB + r * 128 + SW4(g, r) * 16,
                       Bb + (size_t)r * 4096 + koff + g * 16);
        }
    };

    load_stage(0, 0); CP_COMMIT();
    load_stage(1, 1); CP_COMMIT();

    const int a_ro = (lane & 7) + ((lane >> 3) & 1) * 8;
    const int a_kh = (lane >> 4) & 1;
    const int b_ro = (lane & 7) + ((lane >> 4) & 1) * 8;
    const int b_kh = (lane >> 3) & 1;

    for (int i = 0; i < GNT; i++) {
        CP_WAIT1();
        __syncthreads();
        const int j = i + 2;
        if (j < GNT) load_stage(j, j % 3);
        CP_COMMIT();

        const uint32_t sA = sb + (i % 3) * GSTG_B;
        const uint32_t sB = sA + GA_B;
#pragma unroll
        for (int s = 0; s < 4; s++) {
            uint32_t a[4][4], b[8][2];
#pragma unroll
            for (int mf = 0; mf < 4; mf++) {
                int r = wm * 64 + mf * 16 + a_ro;
                ldsm_x4(a[mf][0], a[mf][1], a[mf][2], a[mf][3],
                        sA + r * 128 + SW4(2 * s + a_kh, r) * 16);
            }
#pragma unroll
            for (int pj = 0; pj < 4; pj++) {
                int r = wn * 64 + pj * 16 + b_ro;
                uint32_t r0, r1, r2, r3;
                ldsm_x4(r0, r1, r2, r3, sB + r * 128 + SW4(2 * s + b_kh, r) * 16);
                b[2 * pj][0] = r0;     b[2 * pj][1] = r1;
                b[2 * pj + 1][0] = r2; b[2 * pj + 1][1] = r3;
            }
#pragma unroll
            for (int mf = 0; mf < 4; mf++)
#pragma unroll
                for (int nf = 0; nf < 8; nf++)
                    mma_f16(acc[mf][nf], a[mf], b[nf]);
        }
    }

#pragma unroll
    for (int mf = 0; mf < 4; mf++) {
        const int rg = row0 + wm * 64 + mf * 16 + (lane >> 2);
#pragma unroll
        for (int nf = 0; nf < 8; nf++) {
            const int col = col0 + wn * 64 + nf * 8 + (lane & 3) * 2;
            const float b0 = bias[col], b1 = bias[col + 1];
            float v00 = (acc[mf][nf][0] + b0) * oscale;
            float v01 = (acc[mf][nf][1] + b1) * oscale;
            float v10 = (acc[mf][nf][2] + b0) * oscale;
            float v11 = (acc[mf][nf][3] + b1) * oscale;
            if (C16) {
                *(__half2*)&C16[(size_t)rg * E_DIM + col]       = __floats2half2_rn(v00, v01);
                *(__half2*)&C16[(size_t)(rg + 8) * E_DIM + col] = __floats2half2_rn(v10, v11);
            } else {
                *(float2*)&C32[(size_t)rg * E_DIM + col]       = make_float2(v00, v01);
                *(float2*)&C32[(size_t)(rg + 8) * E_DIM + col] = make_float2(v10, v11);
            }
        }
    }
}

// ---------------- mask reduction --------------------------------------------
__global__ void mask_init_kernel() { g_mask_allones = 1; }
__global__ void mask_check_kernel(const int* __restrict__ mask, int n)
{
    int idx = blockIdx.x * blockDim.x + threadIdx.x;
    int stride = gridDim.x * blockDim.x;
    int bad = 0;
    for (int i = idx; i < n; i += stride) bad |= (mask[i] == 0);
    if (bad) atomicAnd(&g_mask_allones, 0);
}

// ======================= FA2 fp16 flash attention ============================
// BM=128 q, 4 warps x 32 q-rows, BN=64 keys/iter, d=128, 2 CTA/SM.
// Warps own 32 rows each -> K/V ldsm redundancy 4x over a 128q tile
// (1.6x less smem read per q than 16-row warps). Q frags reloaded per iter.
// smem: Q 32768 | K 2x16384 | V 2x16384 = 98304 B
#define AQ  0
#define AK  32768
#define AV  65536
#define ATT_SMEM 98304

__global__ __launch_bounds__(128, 2) void attn_f16_kernel(const int* __restrict__ mask)
{
    const uint32_t sb = smem_u32(dynsmem);
    const int tid  = threadIdx.x;
    const int lane = tid & 31;
    const int wid  = tid >> 5;
    const int R    = wid * 32;           // warp's 32-row base
    const int q0   = blockIdx.x * 128;
    const int nh   = blockIdx.y;
    const int bn   = nh / H_HEADS;
    const int h    = nh % H_HEADS;
    const bool allones = (g_mask_allones != 0);

    const char* qg = (const char*)(g_q16 + (size_t)(bn * S_LEN + q0) * E_DIM + h * D_HEAD);
    const char* kg = (const char*)(g_k16 + (size_t)(bn * T_LEN) * E_DIM + h * D_HEAD);
    const char* vg = (const char*)(g_v16 + (size_t)(bn * T_LEN) * E_DIM + h * D_HEAD);

    const int a_ro = (lane & 7) + ((lane >> 3) & 1) * 8;
    const int a_kh = (lane >> 4) & 1;
    const int b_ro = (lane & 7) + ((lane >> 4) & 1) * 8;
    const int b_kh = (lane >> 3) & 1;

    auto load64 = [&](const char* src, uint32_t base) {   // 64x128 fp16, 1024 chunks
#pragma unroll
        for (int it = 0; it < 8; it++) {
            int ch = tid + it * 128;
            int r = ch >> 4, g = ch & 15;
            CP_ASYNC16(base + r * 256 + SW4(g, r) * 16, src + (size_t)r * 4096 + g * 16);
        }
    };
    // Q: 128x128 fp16, 2048 chunks
#pragma unroll
    for (int it = 0; it < 16; it++) {
        int ch = tid + it * 128;
        int r = ch >> 4, g = ch & 15;
        CP_ASYNC16(sb + AQ + r * 256 + SW4(g, r) * 16, qg + (size_t)r * 4096 + g * 16);
    }
    load64(kg, sb + AK);
    load64(vg, sb + AV);
    CP_COMMIT();
    CP_WAIT0();
    __syncthreads();

    float o[2][16][4];                   // 32q x 128d
    float m[2][2], lsum[2][2];
#pragma unroll
    for (int mf = 0; mf < 2; mf++) {
#pragma unroll
        for (int r = 0; r < 2; r++) { m[mf][r] = -INFINITY; lsum[mf][r] = 0.f; }
#pragma unroll
        for (int nf = 0; nf < 16; nf++)
#pragma unroll
            for (int e = 0; e < 4; e++) o[mf][nf][e] = 0.f;
    }

    const int nb = T_LEN / 64;
    for (int j = 0; j < nb; j++) {
        const int b = j & 1;
        if (j + 1 < nb) {
            load64(kg + (size_t)(j + 1) * 64 * 4096, sb + AK + (1 - b) * 16384);
            load64(vg + (size_t)(j + 1) * 64 * 4096, sb + AV + (1 - b) * 16384);
            CP_COMMIT();
        }
        const uint32_t sK = sb + AK + b * 16384;
        const uint32_t sV = sb + AV + b * 16384;

        // ---- S = Q K^T : warp 32q x 64keys, 8 k16-steps (Q frags from smem)
        float s[2][8][4];
#pragma unroll
        for (int mf = 0; mf < 2; mf++)
#pragma unroll
            for (int nf = 0; nf < 8; nf++)
#pragma unroll
                for (int e = 0; e < 4; e++) s[mf][nf][e] = 0.f;

#pragma unroll
        for (int ks = 0; ks < 8; ks++) {
            uint32_t aqf[2][4], bfr[8][2];
#pragma unroll
            for (int mf = 0; mf < 2; mf++) {
                int r = R + mf * 16 + a_ro;
                ldsm_x4(aqf[mf][0], aqf[mf][1], aqf[mf][2], aqf[mf][3],
                        sb + AQ + r * 256 + SW4(2 * ks + a_kh, r) * 16);
            }
#pragma unroll
            for (int pj = 0; pj < 4; pj++) {
                int r = pj * 16 + b_ro;
                uint32_t r0, r1, r2, r3;
                ldsm_x4(r0, r1, r2, r3, sK + r * 256 + SW4(2 * ks + b_kh, r) * 16);
                bfr[2 * pj][0] = r0;     bfr[2 * pj][1] = r1;
                bfr[2 * pj + 1][0] = r2; bfr[2 * pj + 1][1] = r3;
            }
#pragma unroll
            for (int mf = 0; mf < 2; mf++)
#pragma unroll
                for (int nf = 0; nf < 8; nf++)
                    mma_f16(s[mf][nf], aqf[mf], bfr[nf]);
        }

        if (!allones) {
#pragma unroll
            for (int mf = 0; mf < 2; mf++)
#pragma unroll
                for (int nf = 0; nf < 8; nf++)
#pragma unroll
                    for (int e = 0; e < 4; e++) {
                        int r = R + mf * 16 + (lane >> 2) + (e >> 1) * 8;
                        int c = nf * 8 + (lane & 3) * 2 + (e & 1);
                        if (mask[(size_t)(j * 64 + c) * S_LEN + q0 + r] == 0)
                            s[mf][nf][e] = -INFINITY;
                    }
        }

        // ---- in-warp softmax (base-2; Q pre-scaled by log2e/sqrt(d))
        uint32_t ap[2][4][4];
        float al[2][2];
#pragma unroll
        for (int mf = 0; mf < 2; mf++) {
            float mx0 = s[mf][0][0], mx1 = s[mf][0][2];
#pragma unroll
            for (int nf = 0; nf < 8; nf++) {
                mx0 = fmaxf(mx0, fmaxf(s[mf][nf][0], s[mf][nf][1]));
                mx1 = fmaxf(mx1, fmaxf(s[mf][nf][2], s[mf][nf][3]));
            }
            mx0 = fmaxf(mx0, __shfl_xor_sync(0xffffffffu, mx0, 1));
            mx0 = fmaxf(mx0, __shfl_xor_sync(0xffffffffu, mx0, 2));
            mx1 = fmaxf(mx1, __shfl_xor_sync(0xffffffffu, mx1, 1));
            mx1 = fmaxf(mx1, __shfl_xor_sync(0xffffffffu, mx1, 2));

            float mn0 = fmaxf(m[mf][0], mx0), mn1 = fmaxf(m[mf][1], mx1);
            al[mf][0] = (m[mf][0] == mn0) ? 1.f : ex2(m[mf][0] - mn0);
            al[mf][1] = (m[mf][1] == mn1) ? 1.f : ex2(m[mf][1] - mn1);
            m[mf][0] = mn0; m[mf][1] = mn1;

            float ps0 = 0.f, ps1 = 0.f;
#pragma unroll
            for (int nf = 0; nf < 8; nf++) {
                float e0 = ex2(s[mf][nf][0] - mn0);
                float e1 = ex2(s[mf][nf][1] - mn0);
                float e2 = ex2(s[mf][nf][2] - mn1);
                float e3 = ex2(s[mf][nf][3] - mn1);
                ps0 += e0 + e1; ps1 += e2 + e3;
                int ks = nf >> 1, hi = nf & 1;
                ap[mf][ks][hi * 2]     = packh2(e0, e1);
                ap[mf][ks][hi * 2 + 1] = packh2(e2, e3);
            }
            ps0 += __shfl_xor_sync(0xffffffffu, ps0, 1);
            ps0 += __shfl_xor_sync(0xffffffffu, ps0, 2);
            ps1 += __shfl_xor_sync(0xffffffffu, ps1, 1);
            ps1 += __shfl_xor_sync(0xffffffffu, ps1, 2);
            lsum[mf][0] = lsum[mf][0] * al[mf][0] + ps0;
            lsum[mf][1] = lsum[mf][1] * al[mf][1] + ps1;

            if (al[mf][0] != 1.f || al[mf][1] != 1.f) {
#pragma unroll
                for (int nf = 0; nf < 16; nf++) {
                    o[mf][nf][0] *= al[mf][0]; o[mf][nf][1] *= al[mf][0];
                    o[mf][nf][2] *= al[mf][1]; o[mf][nf][3] *= al[mf][1];
                }
            }
        }

        // ---- O += P V : warp 32q x 128d, 4 k16-steps; V via ldmatrix.trans
#pragma unroll
        for (int ks = 0; ks < 4; ks++) {
            uint32_t bv[16][2];
#pragma unroll
            for (int pv = 0; pv < 8; pv++) {
                int r = ks * 16 + (lane & 15);
                int g = pv * 2 + ((lane >> 4) & 1);
                uint32_t r0, r1, r2, r3;
                ldsm_x4_t(r0, r1, r2, r3, sV + r * 256 + SW4(g, r) * 16);
                bv[2 * pv][0] = r0;     bv[2 * pv][1] = r1;
                bv[2 * pv + 1][0] = r2; bv[2 * pv + 1][1] = r3;
            }
#pragma unroll
            for (int mf = 0; mf < 2; mf++)
#pragma unroll
                for (int nf = 0; nf < 16; nf++)
                    mma_f16(o[mf][nf], ap[mf][ks], bv[nf]);
        }

        if (j + 1 < nb) CP_WAIT0();
        __syncthreads();
    }

    __half* cb = g_ctx16 + (size_t)(bn * S_LEN + q0) * E_DIM + h * D_HEAD;
#pragma unroll
    for (int mf = 0; mf < 2; mf++) {
        const int R0 = R + mf * 16 + (lane >> 2);
        const float i0 = 1.f / lsum[mf][0], i1 = 1.f / lsum[mf][1];
#pragma unroll
        for (int nf = 0; nf < 16; nf++) {
            int c = nf * 8 + (lane & 3) * 2;
            *(__half2*)&cb[(size_t)R0 * E_DIM + c] =
                __floats2half2_rn(o[mf][nf][0] * i0, o[mf][nf][1] * i0);
            *(__half2*)&cb[(size_t)(R0 + 8) * E_DIM + c] =
                __floats2half2_rn(o[mf][nf][2] * i1, o[mf][nf][3] * i1);
        }
    }
}

// ---------------- launch -----------------------------------------------------
extern "C" void kernel_launch(void* const* d_in, const int* in_sizes, int n_in,
                              void* d_out, int out_size)
{
    const float* query = (const float*)d_in[0];
    const float* key   = (const float*)d_in[1];
    const float* value = (const float*)d_in[2];
    const int*   mask  = (const int*)  d_in[3];
    const float* Wq    = (const float*)d_in[4];
    const float* bq    = (const float*)d_in[5];
    const float* Wk    = (const float*)d_in[6];
    const float* bk    = (const float*)d_in[7];
    const float* Wv    = (const float*)d_in[8];
    const float* bv    = (const float*)d_in[9];
    const float* Wp    = (const float*)d_in[10];
    const float* bp    = (const float*)d_in[11];
    float* out = (float*)d_out;

    __half *qs, *ks, *vs, *cs, *ra, *rw;
    cudaGetSymbolAddress((void**)&qs, g_q16);
    cudaGetSymbolAddress((void**)&ks, g_k16);
    cudaGetSymbolAddress((void**)&vs, g_v16);
    cudaGetSymbolAddress((void**)&cs, g_ctx16);
    cudaGetSymbolAddress((void**)&ra, g_ra16);
    cudaGetSymbolAddress((void**)&rw, g_rw16);

    cudaFuncSetAttribute(gemm_f16_kernel,
                         cudaFuncAttributeMaxDynamicSharedMemorySize, GEMM_SMEM);
    cudaFuncSetAttribute(attn_f16_kernel,
                         cudaFuncAttributeMaxDynamicSharedMemorySize, ATT_SMEM);

    const int nA4 = M_TOK * 512;
    const int nW4 = E_DIM * 512;
    const size_t ASZ = (size_t)M_TOK * E_DIM;
    const size_t WSZ = (size_t)E_DIM * E_DIM;
    dim3 ggrid(E_DIM / 256, M_TOK / 128);   // (8, 64)

    const float qscale = 1.4426950408889634f / sqrtf((float)D_HEAD);

    cvt_f16_kernel<<<nA4 / 256, 256>>>(query, ra,            nA4);
    cvt_f16_kernel<<<nA4 / 256, 256>>>(key,   ra + ASZ,      nA4);
    cvt_f16_kernel<<<nA4 / 256, 256>>>(value, ra + 2 * ASZ,  nA4);
    cvt_f16_kernel<<<nW4 / 256, 256>>>(Wq,    rw,            nW4);
    cvt_f16_kernel<<<nW4 / 256, 256>>>(Wk,    rw + WSZ,      nW4);
    cvt_f16_kernel<<<nW4 / 256, 256>>>(Wv,    rw + 2 * WSZ,  nW4);
    cvt_f16_kernel<<<nW4 / 256, 256>>>(Wp,    rw + 3 * WSZ,  nW4);
    mask_init_kernel<<<1, 1>>>();
    mask_check_kernel<<<1024, 256>>>(mask, T_LEN * S_LEN);

    gemm_f16_kernel<<<ggrid, 256, GEMM_SMEM>>>(ra,           rw,           bq, qs, nullptr, qscale);
    gemm_f16_kernel<<<ggrid, 256, GEMM_SMEM>>>(ra + ASZ,     rw + WSZ,     bk, ks, nullptr, 1.f);
    gemm_f16_kernel<<<ggrid, 256, GEMM_SMEM>>>(ra + 2 * ASZ, rw + 2 * WSZ, bv, vs, nullptr, 1.f);

    attn_f16_kernel<<<dim3(S_LEN / 128, N_BATCH * H_HEADS), 128, ATT_SMEM>>>(mask);

    gemm_f16_kernel<<<ggrid, 256, GEMM_SMEM>>>(cs, rw + 3 * WSZ, bp, nullptr, out, 1.f);
}

// round 14
// speedup vs baseline: 11.3838x; 1.0488x over previous
#include <cuda_runtime.h>
#include <cuda_fp16.h>
#include <math.h>
#include <cstdint>

#define E_DIM   2048
#define H_HEADS 16
#define D_HEAD  128
#define N_BATCH 4
#define S_LEN   2048
#define T_LEN   2048
#define M_TOK   (N_BATCH * S_LEN)

// ---------------- scratch ----------------------------------------------------
__device__ __half g_q16[16777216];
__device__ __half g_k16[16777216];
__device__ __half g_v16[16777216];
__device__ __half g_ctx16[16777216];
__device__ __half g_ra16[50331648];   // q|k|v activation fp16
__device__ __half g_rw16[16777216];   // Wq|Wk|Wv|Wp fp16 (contiguous)
__device__ int    g_mask_allones;

extern __shared__ char dynsmem[];

// ======================= helpers =============================================
__device__ __forceinline__ uint32_t smem_u32(const void* p) {
    uint32_t a;
    asm("{ .reg .u64 t; cvta.to.shared.u64 t, %1; cvt.u32.u64 %0, t; }"
        : "=r"(a) : "l"(p));
    return a;
}
__device__ __forceinline__ uint32_t packh2(float a, float b) {
    __half2 h = __floats2half2_rn(a, b);
    return *reinterpret_cast<uint32_t*>(&h);
}
__device__ __forceinline__ float ex2(float x) {
    float y;
    asm("ex2.approx.f32 %0, %1;" : "=f"(y) : "f"(x));
    return y;
}
#define CP_ASYNC16(dst, src) asm volatile("cp.async.cg.shared.global [%0], [%1], 16;" :: "r"(dst), "l"(src))
#define CP_COMMIT()          asm volatile("cp.async.commit_group;" ::: "memory")
#define CP_WAIT0()           asm volatile("cp.async.wait_group 0;" ::: "memory")
#define CP_WAIT1()           asm volatile("cp.async.wait_group 1;" ::: "memory")

__device__ __forceinline__ void ldsm_x4(uint32_t& r0, uint32_t& r1,
                                        uint32_t& r2, uint32_t& r3, uint32_t a) {
    asm volatile("ldmatrix.sync.aligned.m8n8.x4.shared.b16 {%0,%1,%2,%3}, [%4];"
                 : "=r"(r0), "=r"(r1), "=r"(r2), "=r"(r3) : "r"(a));
}
__device__ __forceinline__ void ldsm_x4_t(uint32_t& r0, uint32_t& r1,
                                          uint32_t& r2, uint32_t& r3, uint32_t a) {
    asm volatile("ldmatrix.sync.aligned.m8n8.x4.trans.shared.b16 {%0,%1,%2,%3}, [%4];"
                 : "=r"(r0), "=r"(r1), "=r"(r2), "=r"(r3) : "r"(a));
}
__device__ __forceinline__ void mma_f16(float* d, const uint32_t* a, const uint32_t* b) {
    asm volatile(
        "mma.sync.aligned.m16n8k16.row.col.f32.f16.f16.f32 "
        "{%0,%1,%2,%3}, {%4,%5,%6,%7}, {%8,%9}, {%0,%1,%2,%3};"
        : "+f"(d[0]), "+f"(d[1]), "+f"(d[2]), "+f"(d[3])
        : "r"(a[0]), "r"(a[1]), "r"(a[2]), "r"(a[3]), "r"(b[0]), "r"(b[1]));
}
#define SW4(g, row) (((g) & 24) | (((g) & 7) ^ ((row) & 7)))

// ======================= fused convert: 7 tensors in one launch ==============
__global__ __launch_bounds__(256) void cvt_all_kernel(
    const float* __restrict__ q,  const float* __restrict__ k,
    const float* __restrict__ v,  const float* __restrict__ wq,
    const float* __restrict__ wk, const float* __restrict__ wv,
    const float* __restrict__ wp,
    __half* __restrict__ ra, __half* __restrict__ rw,
    int nA4, int nW4)
{
    if (blockIdx.x == 0 && blockIdx.y == 0 && threadIdx.x == 0)
        g_mask_allones = 1;

    const int y = blockIdx.y;
    const int n4 = (y < 3) ? nA4 : nW4;
    int idx = blockIdx.x * blockDim.x + threadIdx.x;
    if (idx >= n4) return;

    const float* src;
    __half* dst;
    if (y == 0)      { src = q;  dst = ra; }
    else if (y == 1) { src = k;  dst = ra + (size_t)nA4 * 4; }
    else if (y == 2) { src = v;  dst = ra + (size_t)nA4 * 8; }
    else if (y == 3) { src = wq; dst = rw; }
    else if (y == 4) { src = wk; dst = rw + (size_t)nW4 * 4; }
    else if (y == 5) { src = wv; dst = rw + (size_t)nW4 * 8; }
    else             { src = wp; dst = rw + (size_t)nW4 * 12; }

    float4 vv = ((const float4*)src)[idx];
    ((__half2*)dst)[idx * 2]     = __floats2half2_rn(vv.x, vv.y);
    ((__half2*)dst)[idx * 2 + 1] = __floats2half2_rn(vv.z, vv.w);
}

__global__ void mask_check_kernel(const int* __restrict__ mask, int n)
{
    int idx = blockIdx.x * blockDim.x + threadIdx.x;
    int stride = gridDim.x * blockDim.x;
    int bad = 0;
    for (int i = idx; i < n; i += stride) bad |= (mask[i] == 0);
    if (bad) atomicAnd(&g_mask_allones, 0);
}

// ======================= fp16 GEMM core (tile 128x256, BK=64, 3 stages) ======
#define GNT 32
#define GA_B (128 * 128)
#define GB_B (256 * 128)
#define GSTG_B (GA_B + GB_B)
#define GEMM_SMEM (3 * GSTG_B)       // 147456

template <typename EPI>
__device__ __forceinline__ void gemm_core(
    const __half* A, const __half* B, int row0, int col0, EPI epi)
{
    const uint32_t sb = smem_u32(dynsmem);
    const int tid  = threadIdx.x;
    const int lane = tid & 31;
    const int wid  = tid >> 5;
    const int wm   = wid & 1;
    const int wn   = wid >> 1;

    const char* Ab = (const char*)(A + (size_t)row0 * E_DIM);
    const char* Bb = (const char*)(B + (size_t)col0 * E_DIM);

    float acc[4][8][4];
#pragma unroll
    for (int mf = 0; mf < 4; mf++)
#pragma unroll
        for (int nf = 0; nf < 8; nf++)
#pragma unroll
            for (int e = 0; e < 4; e++) acc[mf][nf][e] = 0.f;

    auto load_stage = [&](int kt, int stg) {
        const uint32_t sA = sb + stg * GSTG_B;
        const uint32_t sB = sA + GA_B;
        const size_t koff = (size_t)kt * 128;
#pragma unroll
        for (int it = 0; it < 4; it++) {
            int ch = tid + it * 256;
            int r = ch >> 3, g = ch & 7;
            CP_ASYNC16(sA + r * 128 + SW4(g, r) * 16,
                       Ab + (size_t)r * 4096 + koff + g * 16);
        }
#pragma unroll
        for (int it = 0; it < 8; it++) {
            int ch = tid + it * 256;
            int r = ch >> 3, g = ch & 7;
            CP_ASYNC16(sB + r * 128 + SW4(g, r) * 16,
                       Bb + (size_t)r * 4096 + koff + g * 16);
        }
    };

    load_stage(0, 0); CP_COMMIT();
    load_stage(1, 1); CP_COMMIT();

    const int a_ro = (lane & 7) + ((lane >> 3) & 1) * 8;
    const int a_kh = (lane >> 4) & 1;
    const int b_ro = (lane & 7) + ((lane >> 4) & 1) * 8;
    const int b_kh = (lane >> 3) & 1;

    for (int i = 0; i < GNT; i++) {
        CP_WAIT1();
        __syncthreads();
        const int j = i + 2;
        if (j < GNT) load_stage(j, j % 3);
        CP_COMMIT();

        const uint32_t sA = sb + (i % 3) * GSTG_B;
        const uint32_t sB = sA + GA_B;
#pragma unroll
        for (int s = 0; s < 4; s++) {
            uint32_t a[4][4], b[8][2];
#pragma unroll
            for (int mf = 0; mf < 4; mf++) {
                int r = wm * 64 + mf * 16 + a_ro;
                ldsm_x4(a[mf][0], a[mf][1], a[mf][2], a[mf][3],
                        sA + r * 128 + SW4(2 * s + a_kh, r) * 16);
            }
#pragma unroll
            for (int pj = 0; pj < 4; pj++) {
                int r = wn * 64 + pj * 16 + b_ro;
                uint32_t r0, r1, r2, r3;
                ldsm_x4(r0, r1, r2, r3, sB + r * 128 + SW4(2 * s + b_kh, r) * 16);
                b[2 * pj][0] = r0;     b[2 * pj][1] = r1;
                b[2 * pj + 1][0] = r2; b[2 * pj + 1][1] = r3;
            }
#pragma unroll
            for (int mf = 0; mf < 4; mf++)
#pragma unroll
                for (int nf = 0; nf < 8; nf++)
                    mma_f16(acc[mf][nf], a[mf], b[nf]);
        }
    }

#pragma unroll
    for (int mf = 0; mf < 4; mf++) {
        const int rg = row0 + wm * 64 + mf * 16 + (lane >> 2);
#pragma unroll
        for (int nf = 0; nf < 8; nf++) {
            const int col = col0 + wn * 64 + nf * 8 + (lane & 3) * 2;
            epi(rg, col, acc[mf][nf]);
        }
    }
}

// fused QKV projection: N = 6144 (Wq|Wk|Wv); BOTH A and W selected per block.
// q = query@Wq, k = key@Wk, v = value@Wv  (distinct activations!)
__global__ __launch_bounds__(256, 1) void gemm_qkv_kernel(
    const __half* __restrict__ Aall, const __half* __restrict__ W,
    const float* __restrict__ bq, const float* __restrict__ bk,
    const float* __restrict__ bv, float qscale)
{
    const int col0 = blockIdx.x * 256;
    const int sel  = col0 >> 11;                 // 0=Q 1=K 2=V (2048 % 256 == 0)
    const float* bias = (sel == 0) ? bq : (sel == 1) ? bk : bv;
    __half* Cb = (sel == 0) ? g_q16 : (sel == 1) ? g_k16 : g_v16;
    const float osc = (sel == 0) ? qscale : 1.f;
    const __half* A = Aall + (size_t)sel * M_TOK * E_DIM;   // <-- the R13 bug fix

    gemm_core(A, W, blockIdx.y * 128, col0,
        [&](int rg, int col, const float* acc) {
            const int oc = col & 2047;
            const float b0 = bias[oc], b1 = bias[oc + 1];
            *(__half2*)&Cb[(size_t)rg * E_DIM + oc] =
                __floats2half2_rn((acc[0] + b0) * osc, (acc[1] + b1) * osc);
            *(__half2*)&Cb[(size_t)(rg + 8) * E_DIM + oc] =
                __floats2half2_rn((acc[2] + b0) * osc, (acc[3] + b1) * osc);
        });
}

// out projection: fp32 output
__global__ __launch_bounds__(256, 1) void gemm_out_kernel(
    const __half* __restrict__ A, const __half* __restrict__ W,
    const float* __restrict__ bias, float* __restrict__ C)
{
    gemm_core(A, W, blockIdx.y * 128, blockIdx.x * 256,
        [&](int rg, int col, const float* acc) {
            const float b0 = bias[col], b1 = bias[col + 1];
            *(float2*)&C[(size_t)rg * E_DIM + col] =
                make_float2(acc[0] + b0, acc[1] + b1);
            *(float2*)&C[(size_t)(rg + 8) * E_DIM + col] =
                make_float2(acc[2] + b0, acc[3] + b1);
        });
}

// ======================= FA2 fp16 flash attention (unchanged R12) ============
#define AQ  0
#define AK  32768
#define AV  65536
#define ATT_SMEM 98304

__global__ __launch_bounds__(128, 2) void attn_f16_kernel(const int* __restrict__ mask)
{
    const uint32_t sb = smem_u32(dynsmem);
    const int tid  = threadIdx.x;
    const int lane = tid & 31;
    const int wid  = tid >> 5;
    const int R    = wid * 32;
    const int q0   = blockIdx.x * 128;
    const int nh   = blockIdx.y;
    const int bn   = nh / H_HEADS;
    const int h    = nh % H_HEADS;
    const bool allones = (g_mask_allones != 0);

    const char* qg = (const char*)(g_q16 + (size_t)(bn * S_LEN + q0) * E_DIM + h * D_HEAD);
    const char* kg = (const char*)(g_k16 + (size_t)(bn * T_LEN) * E_DIM + h * D_HEAD);
    const char* vg = (const char*)(g_v16 + (size_t)(bn * T_LEN) * E_DIM + h * D_HEAD);

    const int a_ro = (lane & 7) + ((lane >> 3) & 1) * 8;
    const int a_kh = (lane >> 4) & 1;
    const int b_ro = (lane & 7) + ((lane >> 4) & 1) * 8;
    const int b_kh = (lane >> 3) & 1;

    auto load64 = [&](const char* src, uint32_t base) {
#pragma unroll
        for (int it = 0; it < 8; it++) {
            int ch = tid + it * 128;
            int r = ch >> 4, g = ch & 15;
            CP_ASYNC16(base + r * 256 + SW4(g, r) * 16, src + (size_t)r * 4096 + g * 16);
        }
    };
#pragma unroll
    for (int it = 0; it < 16; it++) {
        int ch = tid + it * 128;
        int r = ch >> 4, g = ch & 15;
        CP_ASYNC16(sb + AQ + r * 256 + SW4(g, r) * 16, qg + (size_t)r * 4096 + g * 16);
    }
    load64(kg, sb + AK);
    load64(vg, sb + AV);
    CP_COMMIT();
    CP_WAIT0();
    __syncthreads();

    float o[2][16][4];
    float m[2][2], lsum[2][2];
#pragma unroll
    for (int mf = 0; mf < 2; mf++) {
#pragma unroll
        for (int r = 0; r < 2; r++) { m[mf][r] = -INFINITY; lsum[mf][r] = 0.f; }
#pragma unroll
        for (int nf = 0; nf < 16; nf++)
#pragma unroll
            for (int e = 0; e < 4; e++) o[mf][nf][e] = 0.f;
    }

    const int nb = T_LEN / 64;
    for (int j = 0; j < nb; j++) {
        const int b = j & 1;
        if (j + 1 < nb) {
            load64(kg + (size_t)(j + 1) * 64 * 4096, sb + AK + (1 - b) * 16384);
            load64(vg + (size_t)(j + 1) * 64 * 4096, sb + AV + (1 - b) * 16384);
            CP_COMMIT();
        }
        const uint32_t sK = sb + AK + b * 16384;
        const uint32_t sV = sb + AV + b * 16384;

        float s[2][8][4];
#pragma unroll
        for (int mf = 0; mf < 2; mf++)
#pragma unroll
            for (int nf = 0; nf < 8; nf++)
#pragma unroll
                for (int e = 0; e < 4; e++) s[mf][nf][e] = 0.f;

#pragma unroll
        for (int ks = 0; ks < 8; ks++) {
            uint32_t aqf[2][4], bfr[8][2];
#pragma unroll
            for (int mf = 0; mf < 2; mf++) {
                int r = R + mf * 16 + a_ro;
                ldsm_x4(aqf[mf][0], aqf[mf][1], aqf[mf][2], aqf[mf][3],
                        sb + AQ + r * 256 + SW4(2 * ks + a_kh, r) * 16);
            }
#pragma unroll
            for (int pj = 0; pj < 4; pj++) {
                int r = pj * 16 + b_ro;
                uint32_t r0, r1, r2, r3;
                ldsm_x4(r0, r1, r2, r3, sK + r * 256 + SW4(2 * ks + b_kh, r) * 16);
                bfr[2 * pj][0] = r0;     bfr[2 * pj][1] = r1;
                bfr[2 * pj + 1][0] = r2; bfr[2 * pj + 1][1] = r3;
            }
#pragma unroll
            for (int mf = 0; mf < 2; mf++)
#pragma unroll
                for (int nf = 0; nf < 8; nf++)
                    mma_f16(s[mf][nf], aqf[mf], bfr[nf]);
        }

        if (!allones) {
#pragma unroll
            for (int mf = 0; mf < 2; mf++)
#pragma unroll
                for (int nf = 0; nf < 8; nf++)
#pragma unroll
                    for (int e = 0; e < 4; e++) {
                        int r = R + mf * 16 + (lane >> 2) + (e >> 1) * 8;
                        int c = nf * 8 + (lane & 3) * 2 + (e & 1);
                        if (mask[(size_t)(j * 64 + c) * S_LEN + q0 + r] == 0)
                            s[mf][nf][e] = -INFINITY;
                    }
        }

        uint32_t ap[2][4][4];
        float al[2][2];
#pragma unroll
        for (int mf = 0; mf < 2; mf++) {
            float mx0 = s[mf][0][0], mx1 = s[mf][0][2];
#pragma unroll
            for (int nf = 0; nf < 8; nf++) {
                mx0 = fmaxf(mx0, fmaxf(s[mf][nf][0], s[mf][nf][1]));
                mx1 = fmaxf(mx1, fmaxf(s[mf][nf][2], s[mf][nf][3]));
            }
            mx0 = fmaxf(mx0, __shfl_xor_sync(0xffffffffu, mx0, 1));
            mx0 = fmaxf(mx0, __shfl_xor_sync(0xffffffffu, mx0, 2));
            mx1 = fmaxf(mx1, __shfl_xor_sync(0xffffffffu, mx1, 1));
            mx1 = fmaxf(mx1, __shfl_xor_sync(0xffffffffu, mx1, 2));

            float mn0 = fmaxf(m[mf][0], mx0), mn1 = fmaxf(m[mf][1], mx1);
            al[mf][0] = (m[mf][0] == mn0) ? 1.f : ex2(m[mf][0] - mn0);
            al[mf][1] = (m[mf][1] == mn1) ? 1.f : ex2(m[mf][1] - mn1);
            m[mf][0] = mn0; m[mf][1] = mn1;

            float ps0 = 0.f, ps1 = 0.f;
#pragma unroll
            for (int nf = 0; nf < 8; nf++) {
                float e0 = ex2(s[mf][nf][0] - mn0);
                float e1 = ex2(s[mf][nf][1] - mn0);
                float e2 = ex2(s[mf][nf][2] - mn1);
                float e3 = ex2(s[mf][nf][3] - mn1);
                ps0 += e0 + e1; ps1 += e2 + e3;
                int ks = nf >> 1, hi = nf & 1;
                ap[mf][ks][hi * 2]     = packh2(e0, e1);
                ap[mf][ks][hi * 2 + 1] = packh2(e2, e3);
            }
            ps0 += __shfl_xor_sync(0xffffffffu, ps0, 1);
            ps0 += __shfl_xor_sync(0xffffffffu, ps0, 2);
            ps1 += __shfl_xor_sync(0xffffffffu, ps1, 1);
            ps1 += __shfl_xor_sync(0xffffffffu, ps1, 2);
            lsum[mf][0] = lsum[mf][0] * al[mf][0] + ps0;
            lsum[mf][1] = lsum[mf][1] * al[mf][1] + ps1;

            if (al[mf][0] != 1.f || al[mf][1] != 1.f) {
#pragma unroll
                for (int nf = 0; nf < 16; nf++) {
                    o[mf][nf][0] *= al[mf][0]; o[mf][nf][1] *= al[mf][0];
                    o[mf][nf][2] *= al[mf][1]; o[mf][nf][3] *= al[mf][1];
                }
            }
        }

#pragma unroll
        for (int ks = 0; ks < 4; ks++) {
            uint32_t bv[16][2];
#pragma unroll
            for (int pv = 0; pv < 8; pv++) {
                int r = ks * 16 + (lane & 15);
                int g = pv * 2 + ((lane >> 4) & 1);
                uint32_t r0, r1, r2, r3;
                ldsm_x4_t(r0, r1, r2, r3, sV + r * 256 + SW4(g, r) * 16);
                bv[2 * pv][0] = r0;     bv[2 * pv][1] = r1;
                bv[2 * pv + 1][0] = r2; bv[2 * pv + 1][1] = r3;
            }
#pragma unroll
            for (int mf = 0; mf < 2; mf++)
#pragma unroll
                for (int nf = 0; nf < 16; nf++)
                    mma_f16(o[mf][nf], ap[mf][ks], bv[nf]);
        }

        if (j + 1 < nb) CP_WAIT0();
        __syncthreads();
    }

    __half* cb = g_ctx16 + (size_t)(bn * S_LEN + q0) * E_DIM + h * D_HEAD;
#pragma unroll
    for (int mf = 0; mf < 2; mf++) {
        const int R0 = R + mf * 16 + (lane >> 2);
        const float i0 = 1.f / lsum[mf][0], i1 = 1.f / lsum[mf][1];
#pragma unroll
        for (int nf = 0; nf < 16; nf++) {
            int c = nf * 8 + (lane & 3) * 2;
            *(__half2*)&cb[(size_t)R0 * E_DIM + c] =
                __floats2half2_rn(o[mf][nf][0] * i0, o[mf][nf][1] * i0);
            *(__half2*)&cb[(size_t)(R0 + 8) * E_DIM + c] =
                __floats2half2_rn(o[mf][nf][2] * i1, o[mf][nf][3] * i1);
        }
    }
}

// ---------------- launch -----------------------------------------------------
extern "C" void kernel_launch(void* const* d_in, const int* in_sizes, int n_in,
                              void* d_out, int out_size)
{
    const float* query = (const float*)d_in[0];
    const float* key   = (const float*)d_in[1];
    const float* value = (const float*)d_in[2];
    const int*   mask  = (const int*)  d_in[3];
    const float* Wq    = (const float*)d_in[4];
    const float* bq    = (const float*)d_in[5];
    const float* Wk    = (const float*)d_in[6];
    const float* bk    = (const float*)d_in[7];
    const float* Wv    = (const float*)d_in[8];
    const float* bv    = (const float*)d_in[9];
    const float* Wp    = (const float*)d_in[10];
    const float* bp    = (const float*)d_in[11];
    float* out = (float*)d_out;

    __half *cs, *ra, *rw;
    cudaGetSymbolAddress((void**)&cs, g_ctx16);
    cudaGetSymbolAddress((void**)&ra, g_ra16);
    cudaGetSymbolAddress((void**)&rw, g_rw16);

    cudaFuncSetAttribute(gemm_qkv_kernel,
                         cudaFuncAttributeMaxDynamicSharedMemorySize, GEMM_SMEM);
    cudaFuncSetAttribute(gemm_out_kernel,
                         cudaFuncAttributeMaxDynamicSharedMemorySize, GEMM_SMEM);
    cudaFuncSetAttribute(attn_f16_kernel,
                         cudaFuncAttributeMaxDynamicSharedMemorySize, ATT_SMEM);

    const int nA4 = M_TOK * 512;
    const int nW4 = E_DIM * 512;
    const float qscale = 1.4426950408889634f / sqrtf((float)D_HEAD);

    // [1] all converts (+ mask-flag re-arm)
    cvt_all_kernel<<<dim3(nA4 / 256, 7), 256>>>(query, key, value,
                                                Wq, Wk, Wv, Wp, ra, rw, nA4, nW4);
    // [2] mask scan
    mask_check_kernel<<<1024, 256>>>(mask, T_LEN * S_LEN);
    // [3] fused QKV projection (N = 6144, per-block A+W select)
    gemm_qkv_kernel<<<dim3(6144 / 256, M_TOK / 128), 256, GEMM_SMEM>>>(
        ra, rw, bq, bk, bv, qscale);
    // [4] attention  <- ncu node 4
    attn_f16_kernel<<<dim3(S_LEN / 128, N_BATCH * H_HEADS), 128, ATT_SMEM>>>(mask);
    // [5] output projection
    gemm_out_kernel<<<dim3(E_DIM / 256, M_TOK / 128), 256, GEMM_SMEM>>>(
        cs, rw + 3 * (size_t)E_DIM * E_DIM, bp, out);
}

// round 17
// speedup vs baseline: 11.9403x; 1.0489x over previous
#include <cuda_runtime.h>
#include <cuda_fp16.h>
#include <math.h>
#include <cstdint>

#define E_DIM   2048
#define H_HEADS 16
#define D_HEAD  128
#define N_BATCH 4
#define S_LEN   2048
#define T_LEN   2048
#define M_TOK   (N_BATCH * S_LEN)

// ---------------- scratch ----------------------------------------------------
__device__ __half g_q16[16777216];
__device__ __half g_k16[16777216];
__device__ __half g_v16[16777216];
__device__ __half g_ctx16[16777216];
__device__ __half g_ra16[50331648];   // q|k|v activation fp16
__device__ __half g_rw16[16777216];   // Wq|Wk|Wv|Wp fp16 (contiguous)
__device__ int    g_mask_allones;

extern __shared__ char dynsmem[];

// ======================= helpers =============================================
__device__ __forceinline__ uint32_t smem_u32(const void* p) {
    uint32_t a;
    asm("{ .reg .u64 t; cvta.to.shared.u64 t, %1; cvt.u32.u64 %0, t; }"
        : "=r"(a) : "l"(p));
    return a;
}
__device__ __forceinline__ uint32_t packh2(float a, float b) {
    __half2 h = __floats2half2_rn(a, b);
    return *reinterpret_cast<uint32_t*>(&h);
}
__device__ __forceinline__ float ex2(float x) {
    float y;
    asm("ex2.approx.f32 %0, %1;" : "=f"(y) : "f"(x));
    return y;
}
#define CP_ASYNC16(dst, src) asm volatile("cp.async.cg.shared.global [%0], [%1], 16;" :: "r"(dst), "l"(src))
#define CP_COMMIT()          asm volatile("cp.async.commit_group;" ::: "memory")
#define CP_WAIT0()           asm volatile("cp.async.wait_group 0;" ::: "memory")
#define CP_WAIT1()           asm volatile("cp.async.wait_group 1;" ::: "memory")

__device__ __forceinline__ void ldsm_x4(uint32_t& r0, uint32_t& r1,
                                        uint32_t& r2, uint32_t& r3, uint32_t a) {
    asm volatile("ldmatrix.sync.aligned.m8n8.x4.shared.b16 {%0,%1,%2,%3}, [%4];"
                 : "=r"(r0), "=r"(r1), "=r"(r2), "=r"(r3) : "r"(a));
}
__device__ __forceinline__ void ldsm_x4_t(uint32_t& r0, uint32_t& r1,
                                          uint32_t& r2, uint32_t& r3, uint32_t a) {
    asm volatile("ldmatrix.sync.aligned.m8n8.x4.trans.shared.b16 {%0,%1,%2,%3}, [%4];"
                 : "=r"(r0), "=r"(r1), "=r"(r2), "=r"(r3) : "r"(a));
}
__device__ __forceinline__ void mma_f16(float* d, const uint32_t* a, const uint32_t* b) {
    asm volatile(
        "mma.sync.aligned.m16n8k16.row.col.f32.f16.f16.f32 "
        "{%0,%1,%2,%3}, {%4,%5,%6,%7}, {%8,%9}, {%0,%1,%2,%3};"
        : "+f"(d[0]), "+f"(d[1]), "+f"(d[2]), "+f"(d[3])
        : "r"(a[0]), "r"(a[1]), "r"(a[2]), "r"(a[3]), "r"(b[0]), "r"(b[1]));
}
#define SW4(g, row) (((g) & 24) | (((g) & 7) ^ ((row) & 7)))

// ======================= fused convert: 7 tensors in one launch ==============
__global__ __launch_bounds__(256) void cvt_all_kernel(
    const float* __restrict__ q,  const float* __restrict__ k,
    const float* __restrict__ v,  const float* __restrict__ wq,
    const float* __restrict__ wk, const float* __restrict__ wv,
    const float* __restrict__ wp,
    __half* __restrict__ ra, __half* __restrict__ rw,
    int nA4, int nW4)
{
    if (blockIdx.x == 0 && blockIdx.y == 0 && threadIdx.x == 0)
        g_mask_allones = 1;

    const int y = blockIdx.y;
    const int n4 = (y < 3) ? nA4 : nW4;
    int idx = blockIdx.x * blockDim.x + threadIdx.x;
    if (idx >= n4) return;

    const float* src;
    __half* dst;
    if (y == 0)      { src = q;  dst = ra; }
    else if (y == 1) { src = k;  dst = ra + (size_t)nA4 * 4; }
    else if (y == 2) { src = v;  dst = ra + (size_t)nA4 * 8; }
    else if (y == 3) { src = wq; dst = rw; }
    else if (y == 4) { src = wk; dst = rw + (size_t)nW4 * 4; }
    else if (y == 5) { src = wv; dst = rw + (size_t)nW4 * 8; }
    else             { src = wp; dst = rw + (size_t)nW4 * 12; }

    float4 vv = ((const float4*)src)[idx];
    ((__half2*)dst)[idx * 2]     = __floats2half2_rn(vv.x, vv.y);
    ((__half2*)dst)[idx * 2 + 1] = __floats2half2_rn(vv.z, vv.w);
}

__global__ void mask_check_kernel(const int* __restrict__ mask, int n)
{
    int idx = blockIdx.x * blockDim.x + threadIdx.x;
    int stride = gridDim.x * blockDim.x;
    int bad = 0;
    for (int i = idx; i < n; i += stride) bad |= (mask[i] == 0);
    if (bad) atomicAnd(&g_mask_allones, 0);
}

// ======================= fp16 GEMM core ======================================
// CTA tile 128x128, 4 warps (2m x 2n, warp 64x64), BK=64, 3 stages.
// smem 96 KB and <=255 regs -> 2 CTAs/SM (no minBlocks qualifier needed).
#define GNT 32
#define GA_B (128 * 128)
#define GB_B (128 * 128)
#define GSTG_B (GA_B + GB_B)
#define GEMM_SMEM (3 * GSTG_B)       // 98304 -> 2 CTA/SM

template <typename EPI>
__device__ __forceinline__ void gemm_core(
    const __half* A, const __half* B, int row0, int col0, EPI epi)
{
    const uint32_t sb = smem_u32(dynsmem);
    const int tid  = threadIdx.x;
    const int lane = tid & 31;
    const int wid  = tid >> 5;       // 0..3
    const int wm   = wid & 1;
    const int wn   = wid >> 1;

    const char* Ab = (const char*)(A + (size_t)row0 * E_DIM);
    const char* Bb = (const char*)(B + (size_t)col0 * E_DIM);

    float acc[4][8][4];
#pragma unroll
    for (int mf = 0; mf < 4; mf++)
#pragma unroll
        for (int nf = 0; nf < 8; nf++)
#pragma unroll
            for (int e = 0; e < 4; e++) acc[mf][nf][e] = 0.f;

    auto load_stage = [&](int kt, int stg) {
        const uint32_t sA = sb + stg * GSTG_B;
        const uint32_t sB = sA + GA_B;
        const size_t koff = (size_t)kt * 128;
#pragma unroll
        for (int it = 0; it < 8; it++) {
            int ch = tid + it * 128;
            int r = ch >> 3, g = ch & 7;
            CP_ASYNC16(sA + r * 128 + SW4(g, r) * 16,
                       Ab + (size_t)r * 4096 + koff + g * 16);
        }
#pragma unroll
        for (int it = 0; it < 8; it++) {
            int ch = tid + it * 128;
            int r = ch >> 3, g = ch & 7;
            CP_ASYNC16(sB + r * 128 + SW4(g, r) * 16,
                       Bb + (size_t)r * 4096 + koff + g * 16);
        }
    };

    load_stage(0, 0); CP_COMMIT();
    load_stage(1, 1); CP_COMMIT();

    const int a_ro = (lane & 7) + ((lane >> 3) & 1) * 8;
    const int a_kh = (lane >> 4) & 1;
    const int b_ro = (lane & 7) + ((lane >> 4) & 1) * 8;
    const int b_kh = (lane >> 3) & 1;

    for (int i = 0; i < GNT; i++) {
        CP_WAIT1();
        __syncthreads();
        const int j = i + 2;
        if (j < GNT) load_stage(j, j % 3);
        CP_COMMIT();

        const uint32_t sA = sb + (i % 3) * GSTG_B;
        const uint32_t sB = sA + GA_B;
#pragma unroll
        for (int s = 0; s < 4; s++) {
            uint32_t a[4][4], b[8][2];
#pragma unroll
            for (int mf = 0; mf < 4; mf++) {
                int r = wm * 64 + mf * 16 + a_ro;
                ldsm_x4(a[mf][0], a[mf][1], a[mf][2], a[mf][3],
                        sA + r * 128 + SW4(2 * s + a_kh, r) * 16);
            }
#pragma unroll
            for (int pj = 0; pj < 4; pj++) {
                int r = wn * 64 + pj * 16 + b_ro;
                uint32_t r0, r1, r2, r3;
                ldsm_x4(r0, r1, r2, r3, sB + r * 128 + SW4(2 * s + b_kh, r) * 16);
                b[2 * pj][0] = r0;     b[2 * pj][1] = r1;
                b[2 * pj + 1][0] = r2; b[2 * pj + 1][1] = r3;
            }
#pragma unroll
            for (int mf = 0; mf < 4; mf++)
#pragma unroll
                for (int nf = 0; nf < 8; nf++)
                    mma_f16(acc[mf][nf], a[mf], b[nf]);
        }
    }

#pragma unroll
    for (int mf = 0; mf < 4; mf++) {
        const int rg = row0 + wm * 64 + mf * 16 + (lane >> 2);
#pragma unroll
        for (int nf = 0; nf < 8; nf++) {
            const int col = col0 + wn * 64 + nf * 8 + (lane & 3) * 2;
            epi(rg, col, acc[mf][nf]);
        }
    }
}

// fused QKV projection: N = 6144 (Wq|Wk|Wv); A and W selected per block.
__global__ __launch_bounds__(128) void gemm_qkv_kernel(
    const __half* __restrict__ Aall, const __half* __restrict__ W,
    const float* __restrict__ bq, const float* __restrict__ bk,
    const float* __restrict__ bv, float qscale)
{
    const int col0 = blockIdx.x * 128;
    const int sel  = col0 >> 11;                 // 0=Q 1=K 2=V
    const float* bias = (sel == 0) ? bq : (sel == 1) ? bk : bv;
    __half* Cb = (sel == 0) ? g_q16 : (sel == 1) ? g_k16 : g_v16;
    const float osc = (sel == 0) ? qscale : 1.f;
    const __half* A = Aall + (size_t)sel * M_TOK * E_DIM;

    gemm_core(A, W, blockIdx.y * 128, col0,
        [&](int rg, int col, const float* acc) {
            const int oc = col & 2047;
            const float b0 = bias[oc], b1 = bias[oc + 1];
            *(__half2*)&Cb[(size_t)rg * E_DIM + oc] =
                __floats2half2_rn((acc[0] + b0) * osc, (acc[1] + b1) * osc);
            *(__half2*)&Cb[(size_t)(rg + 8) * E_DIM + oc] =
                __floats2half2_rn((acc[2] + b0) * osc, (acc[3] + b1) * osc);
        });
}

// out projection: fp32 output
__global__ __launch_bounds__(128) void gemm_out_kernel(
    const __half* __restrict__ A, const __half* __restrict__ W,
    const float* __restrict__ bias, float* __restrict__ C)
{
    gemm_core(A, W, blockIdx.y * 128, blockIdx.x * 128,
        [&](int rg, int col, const float* acc) {
            const float b0 = bias[col], b1 = bias[col + 1];
            *(float2*)&C[(size_t)rg * E_DIM + col] =
                make_float2(acc[0] + b0, acc[1] + b1);
            *(float2*)&C[(size_t)(rg + 8) * E_DIM + col] =
                make_float2(acc[2] + b0, acc[3] + b1);
        });
}

// ======================= FA2 fp16 flash attention (unchanged) ================
#define AQ  0
#define AK  32768
#define AV  65536
#define ATT_SMEM 98304

__global__ __launch_bounds__(128, 2) void attn_f16_kernel(const int* __restrict__ mask)
{
    const uint32_t sb = smem_u32(dynsmem);
    const int tid  = threadIdx.x;
    const int lane = tid & 31;
    const int wid  = tid >> 5;
    const int R    = wid * 32;
    const int q0   = blockIdx.x * 128;
    const int nh   = blockIdx.y;
    const int bn   = nh / H_HEADS;
    const int h    = nh % H_HEADS;
    const bool allones = (g_mask_allones != 0);

    const char* qg = (const char*)(g_q16 + (size_t)(bn * S_LEN + q0) * E_DIM + h * D_HEAD);
    const char* kg = (const char*)(g_k16 + (size_t)(bn * T_LEN) * E_DIM + h * D_HEAD);
    const char* vg = (const char*)(g_v16 + (size_t)(bn * T_LEN) * E_DIM + h * D_HEAD);

    const int a_ro = (lane & 7) + ((lane >> 3) & 1) * 8;
    const int a_kh = (lane >> 4) & 1;
    const int b_ro = (lane & 7) + ((lane >> 4) & 1) * 8;
    const int b_kh = (lane >> 3) & 1;

    auto load64 = [&](const char* src, uint32_t base) {
#pragma unroll
        for (int it = 0; it < 8; it++) {
            int ch = tid + it * 128;
            int r = ch >> 4, g = ch & 15;
            CP_ASYNC16(base + r * 256 + SW4(g, r) * 16, src + (size_t)r * 4096 + g * 16);
        }
    };
#pragma unroll
    for (int it = 0; it < 16; it++) {
        int ch = tid + it * 128;
        int r = ch >> 4, g = ch & 15;
        CP_ASYNC16(sb + AQ + r * 256 + SW4(g, r) * 16, qg + (size_t)r * 4096 + g * 16);
    }
    load64(kg, sb + AK);
    load64(vg, sb + AV);
    CP_COMMIT();
    CP_WAIT0();
    __syncthreads();

    float o[2][16][4];
    float m[2][2], lsum[2][2];
#pragma unroll
    for (int mf = 0; mf < 2; mf++) {
#pragma unroll
        for (int r = 0; r < 2; r++) { m[mf][r] = -INFINITY; lsum[mf][r] = 0.f; }
#pragma unroll
        for (int nf = 0; nf < 16; nf++)
#pragma unroll
            for (int e = 0; e < 4; e++) o[mf][nf][e] = 0.f;
    }

    const int nb = T_LEN / 64;
    for (int j = 0; j < nb; j++) {
        const int b = j & 1;
        if (j + 1 < nb) {
            load64(kg + (size_t)(j + 1) * 64 * 4096, sb + AK + (1 - b) * 16384);
            load64(vg + (size_t)(j + 1) * 64 * 4096, sb + AV + (1 - b) * 16384);
            CP_COMMIT();
        }
        const uint32_t sK = sb + AK + b * 16384;
        const uint32_t sV = sb + AV + b * 16384;

        float s[2][8][4];
#pragma unroll
        for (int mf = 0; mf < 2; mf++)
#pragma unroll
            for (int nf = 0; nf < 8; nf++)
#pragma unroll
                for (int e = 0; e < 4; e++) s[mf][nf][e] = 0.f;

#pragma unroll
        for (int ks = 0; ks < 8; ks++) {
            uint32_t aqf[2][4], bfr[8][2];
#pragma unroll
            for (int mf = 0; mf < 2; mf++) {
                int r = R + mf * 16 + a_ro;
                ldsm_x4(aqf[mf][0], aqf[mf][1], aqf[mf][2], aqf[mf][3],
                        sb + AQ + r * 256 + SW4(2 * ks + a_kh, r) * 16);
            }
#pragma unroll
            for (int pj = 0; pj < 4; pj++) {
                int r = pj * 16 + b_ro;
                uint32_t r0, r1, r2, r3;
                ldsm_x4(r0, r1, r2, r3, sK + r * 256 + SW4(2 * ks + b_kh, r) * 16);
                bfr[2 * pj][0] = r0;     bfr[2 * pj][1] = r1;
                bfr[2 * pj + 1][0] = r2; bfr[2 * pj + 1][1] = r3;
            }
#pragma unroll
            for (int mf = 0; mf < 2; mf++)
#pragma unroll
                for (int nf = 0; nf < 8; nf++)
                    mma_f16(s[mf][nf], aqf[mf], bfr[nf]);
        }

        if (!allones) {
#pragma unroll
            for (int mf = 0; mf < 2; mf++)
#pragma unroll
                for (int nf = 0; nf < 8; nf++)
#pragma unroll
                    for (int e = 0; e < 4; e++) {
                        int r = R + mf * 16 + (lane >> 2) + (e >> 1) * 8;
                        int c = nf * 8 + (lane & 3) * 2 + (e & 1);
                        if (mask[(size_t)(j * 64 + c) * S_LEN + q0 + r] == 0)
                            s[mf][nf][e] = -INFINITY;
                    }
        }

        uint32_t ap[2][4][4];
        float al[2][2];
#pragma unroll
        for (int mf = 0; mf < 2; mf++) {
            float mx0 = s[mf][0][0], mx1 = s[mf][0][2];
#pragma unroll
            for (int nf = 0; nf < 8; nf++) {
                mx0 = fmaxf(mx0, fmaxf(s[mf][nf][0], s[mf][nf][1]));
                mx1 = fmaxf(mx1, fmaxf(s[mf][nf][2], s[mf][nf][3]));
            }
            mx0 = fmaxf(mx0, __shfl_xor_sync(0xffffffffu, mx0, 1));
            mx0 = fmaxf(mx0, __shfl_xor_sync(0xffffffffu, mx0, 2));
            mx1 = fmaxf(mx1, __shfl_xor_sync(0xffffffffu, mx1, 1));
            mx1 = fmaxf(mx1, __shfl_xor_sync(0xffffffffu, mx1, 2));

            float mn0 = fmaxf(m[mf][0], mx0), mn1 = fmaxf(m[mf][1], mx1);
            al[mf][0] = (m[mf][0] == mn0) ? 1.f : ex2(m[mf][0] - mn0);
            al[mf][1] = (m[mf][1] == mn1) ? 1.f : ex2(m[mf][1] - mn1);
            m[mf][0] = mn0; m[mf][1] = mn1;

            float ps0 = 0.f, ps1 = 0.f;
#pragma unroll
            for (int nf = 0; nf < 8; nf++) {
                float e0 = ex2(s[mf][nf][0] - mn0);
                float e1 = ex2(s[mf][nf][1] - mn0);
                float e2 = ex2(s[mf][nf][2] - mn1);
                float e3 = ex2(s[mf][nf][3] - mn1);
                ps0 += e0 + e1; ps1 += e2 + e3;
                int ks = nf >> 1, hi = nf & 1;
                ap[mf][ks][hi * 2]     = packh2(e0, e1);
                ap[mf][ks][hi * 2 + 1] = packh2(e2, e3);
            }
            ps0 += __shfl_xor_sync(0xffffffffu, ps0, 1);
            ps0 += __shfl_xor_sync(0xffffffffu, ps0, 2);
            ps1 += __shfl_xor_sync(0xffffffffu, ps1, 1);
            ps1 += __shfl_xor_sync(0xffffffffu, ps1, 2);
            lsum[mf][0] = lsum[mf][0] * al[mf][0] + ps0;
            lsum[mf][1] = lsum[mf][1] * al[mf][1] + ps1;

            if (al[mf][0] != 1.f || al[mf][1] != 1.f) {
#pragma unroll
                for (int nf = 0; nf < 16; nf++) {
                    o[mf][nf][0] *= al[mf][0]; o[mf][nf][1] *= al[mf][0];
                    o[mf][nf][2] *= al[mf][1]; o[mf][nf][3] *= al[mf][1];
                }
            }
        }

#pragma unroll
        for (int ks = 0; ks < 4; ks++) {
            uint32_t bv[16][2];
#pragma unroll
            for (int pv = 0; pv < 8; pv++) {
                int r = ks * 16 + (lane & 15);
                int g = pv * 2 + ((lane >> 4) & 1);
                uint32_t r0, r1, r2, r3;
                ldsm_x4_t(r0, r1, r2, r3, sV + r * 256 + SW4(g, r) * 16);
                bv[2 * pv][0] = r0;     bv[2 * pv][1] = r1;
                bv[2 * pv + 1][0] = r2; bv[2 * pv + 1][1] = r3;
            }
#pragma unroll
            for (int mf = 0; mf < 2; mf++)
#pragma unroll
                for (int nf = 0; nf < 16; nf++)
                    mma_f16(o[mf][nf], ap[mf][ks], bv[nf]);
        }

        if (j + 1 < nb) CP_WAIT0();
        __syncthreads();
    }

    __half* cb = g_ctx16 + (size_t)(bn * S_LEN + q0) * E_DIM + h * D_HEAD;
#pragma unroll
    for (int mf = 0; mf < 2; mf++) {
        const int R0 = R + mf * 16 + (lane >> 2);
        const float i0 = 1.f / lsum[mf][0], i1 = 1.f / lsum[mf][1];
#pragma unroll
        for (int nf = 0; nf < 16; nf++) {
            int c = nf * 8 + (lane & 3) * 2;
            *(__half2*)&cb[(size_t)R0 * E_DIM + c] =
                __floats2half2_rn(o[mf][nf][0] * i0, o[mf][nf][1] * i0);
            *(__half2*)&cb[(size_t)(R0 + 8) * E_DIM + c] =
                __floats2half2_rn(o[mf][nf][2] * i1, o[mf][nf][3] * i1);
        }
    }
}

// ---------------- launch -----------------------------------------------------
extern "C" void kernel_launch(void* const* d_in, const int* in_sizes, int n_in,
                              void* d_out, int out_size)
{
    const float* query = (const float*)d_in[0];
    const float* key   = (const float*)d_in[1];
    const float* value = (const float*)d_in[2];
    const int*   mask  = (const int*)  d_in[3];
    const float* Wq    = (const float*)d_in[4];
    const float* bq    = (const float*)d_in[5];
    const float* Wk    = (const float*)d_in[6];
    const float* bk    = (const float*)d_in[7];
    const float* Wv    = (const float*)d_in[8];
    const float* bv    = (const float*)d_in[9];
    const float* Wp    = (const float*)d_in[10];
    const float* bp    = (const float*)d_in[11];
    float* out = (float*)d_out;

    __half *cs, *ra, *rw;
    cudaGetSymbolAddress((void**)&cs, g_ctx16);
    cudaGetSymbolAddress((void**)&ra, g_ra16);
    cudaGetSymbolAddress((void**)&rw, g_rw16);

    cudaFuncSetAttribute(gemm_qkv_kernel,
                         cudaFuncAttributeMaxDynamicSharedMemorySize, GEMM_SMEM);
    cudaFuncSetAttribute(gemm_out_kernel,
                         cudaFuncAttributeMaxDynamicSharedMemorySize, GEMM_SMEM);
    cudaFuncSetAttribute(attn_f16_kernel,
                         cudaFuncAttributeMaxDynamicSharedMemorySize, ATT_SMEM);

    const int nA4 = M_TOK * 512;
    const int nW4 = E_DIM * 512;
    const float qscale = 1.4426950408889634f / sqrtf((float)D_HEAD);

    cvt_all_kernel<<<dim3(nA4 / 256, 7), 256>>>(query, key, value,
                                                Wq, Wk, Wv, Wp, ra, rw, nA4, nW4);
    mask_check_kernel<<<1024, 256>>>(mask, T_LEN * S_LEN);
    gemm_qkv_kernel<<<dim3(6144 / 128, M_TOK / 128), 128, GEMM_SMEM>>>(
        ra, rw, bq, bk, bv, qscale);
    attn_f16_kernel<<<dim3(S_LEN / 128, N_BATCH * H_HEADS), 128, ATT_SMEM>>>(mask);
    gemm_out_kernel<<<dim3(E_DIM / 128, M_TOK / 128), 128, GEMM_SMEM>>>(
        cs, rw + 3 * (size_t)E_DIM * E_DIM, bp, out);
}